// round 2
// baseline (speedup 1.0000x reference)
#include <cuda_runtime.h>
#include <math.h>

#define CV_   256
#define CQK_  320
#define DP_   64
#define NPIX_ 4096

#define OFF_QUERY  0u
#define OFF_KEYT   (OFF_QUERY + 2621440u)
#define OFF_QF     (OFF_KEYT  + 2621440u)
#define OFF_KF     (OFF_QF    + 2621440u)
#define OFF_QP     (OFF_KF    + 2621440u)
#define OFF_KP     (OFF_QP    + 524288u)
#define OFF_VT     (OFF_KP    + 524288u)
#define OFF_V2T    (OFF_VT    + 2097152u)
#define OFF_VH     (OFF_V2T   + 2097152u)
#define OFF_STATS  (OFF_VH    + 2097152u)
#define OFF_CONF   (OFF_STATS + 32768u)
#define OFF_OUT    (OFF_CONF  + 8192u)
#define OFF_ACTV   (OFF_OUT   + 2097152u)
#define OFF_GAMMA  (OFF_ACTV  + 1048576u)
#define OFF_BETA   (OFF_GAMMA + 2097152u)
#define OFF_Y      (OFF_BETA  + 2097152u)
#define OFF_T1     (OFF_Y     + 2097152u)
#define OFF_INNM   (OFF_T1    + 2097152u)
#define OFF_MASK   (OFF_INNM  + 1024u)
#define SCRATCH_FLOATS (OFF_MASK + 8388608u)

__device__ float g_scratch[SCRATCH_FLOATS];

// normalize src over channels, concat pos -> dst[b][n][320]
__global__ void k_normcat(const float* __restrict__ src, const float* __restrict__ pos,
                          float* __restrict__ dst) {
    int b = blockIdx.x >> 6, n0 = (blockIdx.x & 63) << 6, tid = threadIdx.x;
    __shared__ float red[4][64], rnorm[64];
    int nn = tid & 63, cp = tid >> 6;
    const float* sp = src + (size_t)b * CV_ * NPIX_ + n0 + nn;
    float acc = 0.f;
    for (int c = cp; c < CV_; c += 4) { float x = sp[(size_t)c * NPIX_]; acc += x * x; }
    red[cp][nn] = acc;
    __syncthreads();
    if (tid < 64) {
        float s = red[0][tid] + red[1][tid] + red[2][tid] + red[3][tid];
        rnorm[tid] = 1.f / (sqrtf(s) + 2.220446049250313e-16f);
    }
    __syncthreads();
    for (int i = 0; i < 80; i++) {
        int idx = i * 256 + tid, n = idx / CQK_, c = idx - n * CQK_;
        float v = (c < CV_) ? src[(size_t)(b * CV_ + c) * NPIX_ + n0 + n] * rnorm[n]
                            : pos[(size_t)(c - CV_) * NPIX_ + n0 + n];
        dst[((size_t)b * NPIX_ + n0 + n) * CQK_ + c] = v;
    }
}

__global__ void k_transpose(const float* __restrict__ src, float* __restrict__ dst) {
    __shared__ float t[32][33];
    int c0 = blockIdx.x * 32, n0 = blockIdx.y * 32, b = blockIdx.z;
    int tx = threadIdx.x, ty = threadIdx.y;
    const float* s = src + (size_t)b * CV_ * NPIX_;
    float* d = dst + (size_t)b * NPIX_ * CV_;
    for (int j = 0; j < 32; j += 8) t[ty + j][tx] = s[(size_t)(c0 + ty + j) * NPIX_ + n0 + tx];
    __syncthreads();
    for (int j = 0; j < 32; j += 8) d[(size_t)(n0 + ty + j) * CV_ + c0 + tx] = t[tx][ty + j];
}

// C[p][o] = sum_k A[p][k]*W[o][k] + bias[o]
__global__ void k_gemm(const float* __restrict__ A, const float* __restrict__ W,
                       const float* __restrict__ bias, float* __restrict__ C, int K, int O) {
    __shared__ float As[16][64], Ws[16][64];
    int p0 = blockIdx.y << 6, o0 = blockIdx.x << 6, tid = threadIdx.x;
    int tx4 = (tid & 15) * 4, ty4 = (tid >> 4) * 4;
    float acc[4][4] = {};
    for (int k0 = 0; k0 < K; k0 += 16) {
        #pragma unroll
        for (int i = 0; i < 4; i++) {
            int idx = i * 256 + tid, pp = idx >> 4, kk = idx & 15;
            As[kk][pp] = A[(size_t)(p0 + pp) * K + k0 + kk];
            Ws[kk][pp] = W[(size_t)(o0 + pp) * K + k0 + kk];
        }
        __syncthreads();
        #pragma unroll
        for (int kk = 0; kk < 16; kk++) {
            float4 a = *(const float4*)&As[kk][ty4];
            float4 w = *(const float4*)&Ws[kk][tx4];
            float av[4] = {a.x,a.y,a.z,a.w}, wv[4] = {w.x,w.y,w.z,w.w};
            #pragma unroll
            for (int ii = 0; ii < 4; ii++)
                #pragma unroll
                for (int jj = 0; jj < 4; jj++) acc[ii][jj] += av[ii] * wv[jj];
        }
        __syncthreads();
    }
    for (int ii = 0; ii < 4; ii++) {
        float4 r;
        r.x = acc[ii][0] + bias[o0+tx4+0]; r.y = acc[ii][1] + bias[o0+tx4+1];
        r.z = acc[ii][2] + bias[o0+tx4+2]; r.w = acc[ii][3] + bias[o0+tx4+3];
        *(float4*)&C[(size_t)(p0 + ty4 + ii) * O + o0 + tx4] = r;
    }
}

// cor = Qf·Kf^T/sqrt(320); mask = (Qp·Kp^T > 0)
__global__ void k_cor(const float* __restrict__ Qf, const float* __restrict__ Kf,
                      const float* __restrict__ Qp, const float* __restrict__ Kp,
                      float* __restrict__ cor, unsigned char* __restrict__ mask) {
    __shared__ float As[16][64], Bs[16][64];
    int b = blockIdx.z, n0 = blockIdx.y << 6, m0 = blockIdx.x << 6, tid = threadIdx.x;
    int tx4 = (tid & 15) * 4, ty4 = (tid >> 4) * 4;
    float acc[4][4] = {}, acc2[4][4] = {};
    const float* Aq = Qf + (size_t)b * NPIX_ * CQK_;
    const float* Bk = Kf + (size_t)b * NPIX_ * CQK_;
    for (int k0 = 0; k0 < CQK_; k0 += 16) {
        #pragma unroll
        for (int i = 0; i < 4; i++) {
            int idx = i * 256 + tid, pp = idx >> 4, kk = idx & 15;
            As[kk][pp] = Aq[(size_t)(n0 + pp) * CQK_ + k0 + kk];
            Bs[kk][pp] = Bk[(size_t)(m0 + pp) * CQK_ + k0 + kk];
        }
        __syncthreads();
        #pragma unroll
        for (int kk = 0; kk < 16; kk++) {
            float4 a = *(const float4*)&As[kk][ty4];
            float4 w = *(const float4*)&Bs[kk][tx4];
            float av[4] = {a.x,a.y,a.z,a.w}, wv[4] = {w.x,w.y,w.z,w.w};
            #pragma unroll
            for (int ii = 0; ii < 4; ii++)
                #pragma unroll
                for (int jj = 0; jj < 4; jj++) acc[ii][jj] += av[ii] * wv[jj];
        }
        __syncthreads();
    }
    const float* Ap = Qp + (size_t)b * NPIX_ * DP_;
    const float* Bp = Kp + (size_t)b * NPIX_ * DP_;
    for (int k0 = 0; k0 < DP_; k0 += 16) {
        #pragma unroll
        for (int i = 0; i < 4; i++) {
            int idx = i * 256 + tid, pp = idx >> 4, kk = idx & 15;
            As[kk][pp] = Ap[(size_t)(n0 + pp) * DP_ + k0 + kk];
            Bs[kk][pp] = Bp[(size_t)(m0 + pp) * DP_ + k0 + kk];
        }
        __syncthreads();
        #pragma unroll
        for (int kk = 0; kk < 16; kk++) {
            float4 a = *(const float4*)&As[kk][ty4];
            float4 w = *(const float4*)&Bs[kk][tx4];
            float av[4] = {a.x,a.y,a.z,a.w}, wv[4] = {w.x,w.y,w.z,w.w};
            #pragma unroll
            for (int ii = 0; ii < 4; ii++)
                #pragma unroll
                for (int jj = 0; jj < 4; jj++) acc2[ii][jj] += av[ii] * wv[jj];
        }
        __syncthreads();
    }
    const float scale = 0.05590169943749474f;
    for (int ii = 0; ii < 4; ii++) {
        int n = n0 + ty4 + ii;
        float4 cv = {acc[ii][0]*scale, acc[ii][1]*scale, acc[ii][2]*scale, acc[ii][3]*scale};
        *(float4*)&cor[((size_t)b * NPIX_ + n) * NPIX_ + m0 + tx4] = cv;
        uchar4 mv = {(unsigned char)(acc2[ii][0] > 0.f), (unsigned char)(acc2[ii][1] > 0.f),
                     (unsigned char)(acc2[ii][2] > 0.f), (unsigned char)(acc2[ii][3] > 0.f)};
        *(uchar4*)&mask[((size_t)b * NPIX_ + n) * NPIX_ + m0 + tx4] = mv;
    }
}

__global__ void k_rowstats(const float* __restrict__ cor, const unsigned char* __restrict__ mask,
                           float* __restrict__ stats, float* __restrict__ conf) {
    int row = blockIdx.x, tid = threadIdx.x;
    const float* r = cor + (size_t)row * NPIX_;
    const unsigned char* mk = mask + (size_t)row * NPIX_;
    __shared__ float sa[256], sb[256], sc[256];
    float mx1 = -3.0e38f, mx2 = -3.0e38f;
    for (int m = tid; m < NPIX_; m += 256) {
        float x = r[m];
        mx1 = fmaxf(mx1, x);
        mx2 = fmaxf(mx2, mk[m] ? -10000.f : x);
    }
    sa[tid] = mx1; sb[tid] = mx2;
    __syncthreads();
    for (int s = 128; s > 0; s >>= 1) {
        if (tid < s) { sa[tid] = fmaxf(sa[tid], sa[tid+s]); sb[tid] = fmaxf(sb[tid], sb[tid+s]); }
        __syncthreads();
    }
    mx1 = sa[0]; mx2 = sb[0];
    __syncthreads();
    float s1 = 0.f, sm = 0.f, s2 = 0.f;
    for (int m = tid; m < NPIX_; m += 256) {
        float x = r[m], mv = mk[m] ? 1.f : 0.f;
        float e1 = __expf(x - mx1);
        s1 += e1; sm += mv * e1;
        s2 += __expf((mv > 0.f ? -10000.f : x) - mx2);
    }
    sa[tid] = s1; sb[tid] = sm; sc[tid] = s2;
    __syncthreads();
    for (int s = 128; s > 0; s >>= 1) {
        if (tid < s) { sa[tid] += sa[tid+s]; sb[tid] += sb[tid+s]; sc[tid] += sc[tid+s]; }
        __syncthreads();
    }
    if (tid == 0) {
        stats[row*4+0] = mx1; stats[row*4+1] = 1.f / sa[0];
        stats[row*4+2] = mx2; stats[row*4+3] = 1.f / sc[0];
        conf[row] = sb[0] / sa[0];
    }
}

// out = (softmax*mask)·Vh, out2 = softmax(inv-mask)·V2 ; both written [b][c][n]
__global__ void k_pc(const float* __restrict__ cor, const unsigned char* __restrict__ mask,
                     const float* __restrict__ stats, const float* __restrict__ Vh,
                     const float* __restrict__ V2t, float* __restrict__ outat,
                     float* __restrict__ out2) {
    extern __shared__ float smem[];
    float* ct  = smem;          // 64*65
    float* msf = smem + 4160;   // 64*65
    float* w1t = smem + 8320;   // 64*68
    float* w2t = smem + 12672;  // 64*68
    float* V1s = smem + 17024;  // 64*64
    float* V2s = smem + 21120;  // 64*64
    float* st  = smem + 25216;  // 256
    int b = blockIdx.z, n0 = blockIdx.y << 6, c0 = blockIdx.x << 6, tid = threadIdx.x;
    int tx4 = (tid & 15) * 4, ty4 = (tid >> 4) * 4;
    st[tid] = stats[((size_t)b * NPIX_ + n0) * 4 + tid];
    const float* corb = cor + ((size_t)b * NPIX_ + n0) * NPIX_;
    const unsigned char* mb = mask + ((size_t)b * NPIX_ + n0) * NPIX_;
    const float* Vb  = Vh  + (size_t)b * NPIX_ * CV_ + c0;
    const float* V2b = V2t + (size_t)b * NPIX_ * CV_ + c0;
    float acc1[4][4] = {}, acc2[4][4] = {};
    __syncthreads();
    for (int m0 = 0; m0 < NPIX_; m0 += 64) {
        #pragma unroll
        for (int i = 0; i < 16; i++) {
            int idx = i * 256 + tid, a = idx >> 6, c = idx & 63;
            ct [a*65+c] = corb[(size_t)a * NPIX_ + m0 + c];
            msf[a*65+c] = (float)mb[(size_t)a * NPIX_ + m0 + c];
            V1s[a*64+c] = Vb [(size_t)(m0 + a) * CV_ + c];
            V2s[a*64+c] = V2b[(size_t)(m0 + a) * CV_ + c];
        }
        __syncthreads();
        #pragma unroll
        for (int i = 0; i < 16; i++) {
            int idx = i * 256 + tid, mm = idx >> 6, nn = idx & 63;
            float x = ct[nn*65+mm], mv = msf[nn*65+mm];
            w1t[mm*68+nn] = __expf(x - st[nn*4+0]) * st[nn*4+1] * mv;
            float l2 = (mv > 0.f) ? -10000.f : x;
            w2t[mm*68+nn] = __expf(l2 - st[nn*4+2]) * st[nn*4+3];
        }
        __syncthreads();
        #pragma unroll 2
        for (int mm = 0; mm < 64; mm++) {
            float4 a1 = *(const float4*)(w1t + mm*68 + ty4);
            float4 a2 = *(const float4*)(w2t + mm*68 + ty4);
            float4 b1 = *(const float4*)(V1s + mm*64 + tx4);
            float4 b2 = *(const float4*)(V2s + mm*64 + tx4);
            float A1[4]={a1.x,a1.y,a1.z,a1.w}, A2[4]={a2.x,a2.y,a2.z,a2.w};
            float B1[4]={b1.x,b1.y,b1.z,b1.w}, B2[4]={b2.x,b2.y,b2.z,b2.w};
            #pragma unroll
            for (int ii = 0; ii < 4; ii++)
                #pragma unroll
                for (int jj = 0; jj < 4; jj++) {
                    acc1[ii][jj] += A1[ii] * B1[jj];
                    acc2[ii][jj] += A2[ii] * B2[jj];
                }
        }
        __syncthreads();
    }
    #pragma unroll
    for (int ii = 0; ii < 4; ii++)
        for (int jj = 0; jj < 4; jj++) ct[(tx4+jj)*65 + ty4+ii] = acc1[ii][jj];
    __syncthreads();
    for (int i = 0; i < 16; i++) {
        int idx = i * 256 + tid, cc = idx >> 6, nn = idx & 63;
        outat[((size_t)b * CV_ + c0 + cc) * NPIX_ + n0 + nn] = ct[cc*65+nn];
    }
    __syncthreads();
    #pragma unroll
    for (int ii = 0; ii < 4; ii++)
        for (int jj = 0; jj < 4; jj++) ct[(tx4+jj)*65 + ty4+ii] = acc2[ii][jj];
    __syncthreads();
    for (int i = 0; i < 16; i++) {
        int idx = i * 256 + tid, cc = idx >> 6, nn = idx & 63;
        out2[((size_t)b * CV_ + c0 + cc) * NPIX_ + n0 + nn] = ct[cc*65+nn];
    }
}

// 3x3 conv SAME, NCHW. flags: 1=relu, 2=add res
__global__ void k_conv3(const float* __restrict__ in, const float* __restrict__ wgt,
                        const float* __restrict__ bias, float* __restrict__ out,
                        int Cin, int Cout, int flags, const float* __restrict__ res) {
    __shared__ float ins[1600];  // 16ic*10*10
    __shared__ float ws[9216];   // 16ic*9*64oc
    int b = blockIdx.z, t = blockIdx.y, oc0 = blockIdx.x << 6;
    int y0 = (t >> 3) << 3, x0 = (t & 7) << 3, tid = threadIdx.x;
    int tx = tid & 15, ty = tid >> 4;
    int pyb = tx >> 1, pxb = (tx & 1) << 2;
    float acc[4][4] = {};
    for (int ic0 = 0; ic0 < Cin; ic0 += 16) {
        for (int i = tid; i < 1600; i += 256) {
            int icl = i / 100, rem = i - icl * 100, hy = rem / 10, hx = rem - hy * 10;
            int gy = y0 + hy - 1, gx = x0 + hx - 1, ic = ic0 + icl;
            float v = 0.f;
            if (ic < Cin && (unsigned)gy < 64u && (unsigned)gx < 64u)
                v = in[(((size_t)b * Cin + ic) * 64 + gy) * 64 + gx];
            ins[i] = v;
        }
        for (int i = tid; i < 9216; i += 256) {
            int oc = i & 63, kk = i >> 6, icl = kk / 9, tap = kk - icl * 9, ic = ic0 + icl;
            ws[i] = (ic < Cin) ? wgt[(((size_t)(oc0 + oc)) * Cin + ic) * 9 + tap] : 0.f;
        }
        __syncthreads();
        int icm = (Cin - ic0 < 16) ? (Cin - ic0) : 16;
        for (int icl = 0; icl < icm; icl++) {
            #pragma unroll
            for (int tap = 0; tap < 9; tap++) {
                int ky = tap / 3, kx = tap - ky * 3;
                float4 wv = *(const float4*)&ws[(icl * 9 + tap) * 64 + ty * 4];
                float W[4] = {wv.x, wv.y, wv.z, wv.w};
                const float* ip = &ins[icl * 100 + (pyb + ky) * 10 + pxb + kx];
                float X[4] = {ip[0], ip[1], ip[2], ip[3]};
                #pragma unroll
                for (int oi = 0; oi < 4; oi++)
                    #pragma unroll
                    for (int pj = 0; pj < 4; pj++) acc[oi][pj] += W[oi] * X[pj];
            }
        }
        __syncthreads();
    }
    for (int oi = 0; oi < 4; oi++) {
        int oc = oc0 + ty * 4 + oi;
        float bv = bias[oc];
        size_t ob = (((size_t)b * Cout + oc) * 64 + y0 + pyb) * 64 + x0 + pxb;
        #pragma unroll
        for (int pj = 0; pj < 4; pj++) {
            float vv = acc[oi][pj] + bv;
            if (flags & 1) vv = fmaxf(vv, 0.f);
            if (flags & 2) vv += res[ob + pj];
            out[ob + pj] = vv;
        }
    }
}

__global__ void k_instnorm(const float* __restrict__ x, float* __restrict__ st) {
    int row = blockIdx.x, tid = threadIdx.x;
    const float* p = x + (size_t)row * NPIX_;
    float s = 0.f, ss = 0.f;
    for (int i = tid; i < NPIX_; i += 256) { float v = p[i]; s += v; ss += v * v; }
    __shared__ float r1[256], r2[256];
    r1[tid] = s; r2[tid] = ss;
    __syncthreads();
    for (int k = 128; k > 0; k >>= 1) {
        if (tid < k) { r1[tid] += r1[tid+k]; r2[tid] += r2[tid+k]; }
        __syncthreads();
    }
    if (tid == 0) {
        float m = r1[0] * (1.f / NPIX_);
        float v = r2[0] * (1.f / NPIX_) - m * m;
        st[row*2] = m; st[row*2+1] = rsqrtf(v + 1e-5f);
    }
}

__global__ void k_spade_pono(const float* __restrict__ q, const float* __restrict__ gam,
                             const float* __restrict__ bet, const float* __restrict__ outat,
                             const float* __restrict__ conf, const float* __restrict__ innm,
                             float* __restrict__ y) {
    int b = blockIdx.x >> 6, n0 = (blockIdx.x & 63) << 6, tid = threadIdx.x;
    int nn = tid & 63, cp = tid >> 6;
    __shared__ float ps[4][64], pss[4][64], pm[64], pr[64];
    float cf = conf[(size_t)b * NPIX_ + n0 + nn];
    float s = 0.f, ss = 0.f;
    for (int base = 0; base < CV_; base += 4) {
        int cc = base + cp;
        size_t o = ((size_t)b * CV_ + cc) * NPIX_ + n0 + nn;
        float m = innm[(b*CV_+cc)*2], rs = innm[(b*CV_+cc)*2+1];
        float qv = q[o];
        float sp = (qv - m) * rs * (1.f + gam[o]) + bet[o];
        float tv = outat[o] + (1.f - cf) * sp + qv;
        s += tv; ss += tv * tv;
    }
    ps[cp][nn] = s; pss[cp][nn] = ss;
    __syncthreads();
    if (tid < 64) {
        float S = ps[0][tid]+ps[1][tid]+ps[2][tid]+ps[3][tid];
        float SS = pss[0][tid]+pss[1][tid]+pss[2][tid]+pss[3][tid];
        float m = S * (1.f/256.f), v = SS * (1.f/256.f) - m * m;
        pm[tid] = m; pr[tid] = rsqrtf(v + 1e-5f);
    }
    __syncthreads();
    float mmu = pm[nn], rr = pr[nn];
    for (int base = 0; base < CV_; base += 4) {
        int cc = base + cp;
        size_t o = ((size_t)b * CV_ + cc) * NPIX_ + n0 + nn;
        float m = innm[(b*CV_+cc)*2], rs = innm[(b*CV_+cc)*2+1];
        float qv = q[o];
        float sp = (qv - m) * rs * (1.f + gam[o]) + bet[o];
        float tv = outat[o] + (1.f - cf) * sp + qv;
        y[o] = (tv - mmu) * rr;
    }
}

extern "C" void kernel_launch(void* const* d_in, const int* in_sizes, int n_in,
                              void* d_out, int out_size) {
    const float *q = (const float*)d_in[0], *k = (const float*)d_in[1],
                *v = (const float*)d_in[2], *pos = (const float*)d_in[3],
                *seg = (const float*)d_in[4], *v2 = (const float*)d_in[5],
                *f_w = (const float*)d_in[6], *f_b = (const float*)d_in[7],
                *g_w = (const float*)d_in[8], *g_b = (const float*)d_in[9],
                *h_w = (const float*)d_in[10], *h_b = (const float*)d_in[11],
                *fp_w = (const float*)d_in[12], *fp_b = (const float*)d_in[13],
                *gp_w = (const float*)d_in[14], *gp_b = (const float*)d_in[15],
                *sp_s_w = (const float*)d_in[16], *sp_s_b = (const float*)d_in[17],
                *sp_g_w = (const float*)d_in[18], *sp_g_b = (const float*)d_in[19],
                *sp_b_w = (const float*)d_in[20], *sp_b_b = (const float*)d_in[21],
                *r1_w = (const float*)d_in[22], *r1_b = (const float*)d_in[23],
                *r2_w = (const float*)d_in[24], *r2_b = (const float*)d_in[25];
    float* S;
    cudaGetSymbolAddress((void**)&S, g_scratch);
    float* out_res  = (float*)d_out;
    float* out_out2 = out_res + 2097152;
    float* out_cor  = out_res + 4194304;
    unsigned char* mask = (unsigned char*)(S + OFF_MASK);

    k_normcat<<<128, 256>>>(q, pos, S + OFF_QUERY);
    k_normcat<<<128, 256>>>(k, pos, S + OFF_KEYT);
    k_transpose<<<dim3(8,128,2), dim3(32,8)>>>(v,  S + OFF_VT);
    k_transpose<<<dim3(8,128,2), dim3(32,8)>>>(v2, S + OFF_V2T);
    k_gemm<<<dim3(5,128), 256>>>(S + OFF_QUERY, f_w,  f_b,  S + OFF_QF, CQK_, CQK_);
    k_gemm<<<dim3(5,128), 256>>>(S + OFF_KEYT,  g_w,  g_b,  S + OFF_KF, CQK_, CQK_);
    k_gemm<<<dim3(1,128), 256>>>(S + OFF_QUERY, fp_w, fp_b, S + OFF_QP, CQK_, DP_);
    k_gemm<<<dim3(1,128), 256>>>(S + OFF_KEYT,  gp_w, gp_b, S + OFF_KP, CQK_, DP_);
    k_gemm<<<dim3(4,128), 256>>>(S + OFF_VT,    h_w,  h_b,  S + OFF_VH, CV_,  CV_);
    k_cor<<<dim3(64,64,2), 256>>>(S + OFF_QF, S + OFF_KF, S + OFF_QP, S + OFF_KP,
                                  out_cor, mask);
    k_rowstats<<<8192, 256>>>(out_cor, mask, S + OFF_STATS, S + OFF_CONF);
    cudaFuncSetAttribute(k_pc, cudaFuncAttributeMaxDynamicSharedMemorySize, 101888);
    k_pc<<<dim3(4,64,2), 256, 101888>>>(out_cor, mask, S + OFF_STATS, S + OFF_VH,
                                        S + OFF_V2T, S + OFF_OUT, out_out2);
    k_conv3<<<dim3(2,64,2), 256>>>(seg, sp_s_w, sp_s_b, S + OFF_ACTV, 3, 128, 1, nullptr);
    k_conv3<<<dim3(4,64,2), 256>>>(S + OFF_ACTV, sp_g_w, sp_g_b, S + OFF_GAMMA, 128, 256, 0, nullptr);
    k_conv3<<<dim3(4,64,2), 256>>>(S + OFF_ACTV, sp_b_w, sp_b_b, S + OFF_BETA,  128, 256, 0, nullptr);
    k_instnorm<<<512, 256>>>(q, S + OFF_INNM);
    k_spade_pono<<<128, 256>>>(q, S + OFF_GAMMA, S + OFF_BETA, S + OFF_OUT,
                               S + OFF_CONF, S + OFF_INNM, S + OFF_Y);
    k_conv3<<<dim3(4,64,2), 256>>>(S + OFF_Y,  r1_w, r1_b, S + OFF_T1, 256, 256, 1, nullptr);
    k_conv3<<<dim3(4,64,2), 256>>>(S + OFF_T1, r2_w, r2_b, out_res,    256, 256, 2, S + OFF_Y);
}

// round 3
// speedup vs baseline: 1.9284x; 1.9284x over previous
#include <cuda_runtime.h>
#include <math.h>

#define CV_   256
#define CQK_  320
#define DP_   64
#define NPIX_ 4096

#define OFF_QUERY  0u
#define OFF_KEYT   (OFF_QUERY + 2621440u)
#define OFF_QF     (OFF_KEYT  + 2621440u)
#define OFF_KF     (OFF_QF    + 2621440u)
#define OFF_QP     (OFF_KF    + 2621440u)
#define OFF_KP     (OFF_QP    + 524288u)
#define OFF_VT     (OFF_KP    + 524288u)
#define OFF_V2T    (OFF_VT    + 2097152u)
#define OFF_VH     (OFF_V2T   + 2097152u)
#define OFF_STATS  (OFF_VH    + 2097152u)
#define OFF_CONF   (OFF_STATS + 32768u)
#define OFF_OUT    (OFF_CONF  + 8192u)
#define OFF_ACTV   (OFF_OUT   + 2097152u)
#define OFF_GAMMA  (OFF_ACTV  + 1048576u)
#define OFF_BETA   (OFF_GAMMA + 2097152u)
#define OFF_Y      (OFF_BETA  + 2097152u)
#define OFF_T1     (OFF_Y     + 2097152u)
#define OFF_INNM   (OFF_T1    + 2097152u)
#define OFF_MASK   (OFF_INNM  + 1024u)
#define SCRATCH_FLOATS (OFF_MASK + 8388608u)

__device__ float g_scratch[SCRATCH_FLOATS];

typedef unsigned long long ull;
__device__ __forceinline__ ull pk2(float lo, float hi) {
    ull r; asm("mov.b64 %0,{%1,%2};" : "=l"(r) : "f"(lo), "f"(hi)); return r;
}
__device__ __forceinline__ void fma2(ull& d, ull a, ull b) {
    asm("fma.rn.f32x2 %0,%1,%2,%0;" : "+l"(d) : "l"(a), "l"(b));
}
__device__ __forceinline__ float2 up2(ull v) {
    float2 f; asm("mov.b64 {%0,%1},%2;" : "=f"(f.x), "=f"(f.y) : "l"(v)); return f;
}

// normalize src over channels, concat pos -> dst[b][n][320]
__global__ void k_normcat(const float* __restrict__ src, const float* __restrict__ pos,
                          float* __restrict__ dst) {
    int b = blockIdx.x >> 6, n0 = (blockIdx.x & 63) << 6, tid = threadIdx.x;
    __shared__ float red[4][64], rnorm[64];
    int nn = tid & 63, cp = tid >> 6;
    const float* sp = src + (size_t)b * CV_ * NPIX_ + n0 + nn;
    float acc = 0.f;
    for (int c = cp; c < CV_; c += 4) { float x = sp[(size_t)c * NPIX_]; acc += x * x; }
    red[cp][nn] = acc;
    __syncthreads();
    if (tid < 64) {
        float s = red[0][tid] + red[1][tid] + red[2][tid] + red[3][tid];
        rnorm[tid] = 1.f / (sqrtf(s) + 2.220446049250313e-16f);
    }
    __syncthreads();
    for (int i = 0; i < 80; i++) {
        int idx = i * 256 + tid, n = idx / CQK_, c = idx - n * CQK_;
        float v = (c < CV_) ? src[(size_t)(b * CV_ + c) * NPIX_ + n0 + n] * rnorm[n]
                            : pos[(size_t)(c - CV_) * NPIX_ + n0 + n];
        dst[((size_t)b * NPIX_ + n0 + n) * CQK_ + c] = v;
    }
}

__global__ void k_transpose(const float* __restrict__ src, float* __restrict__ dst) {
    __shared__ float t[32][33];
    int c0 = blockIdx.x * 32, n0 = blockIdx.y * 32, b = blockIdx.z;
    int tx = threadIdx.x, ty = threadIdx.y;
    const float* s = src + (size_t)b * CV_ * NPIX_;
    float* d = dst + (size_t)b * NPIX_ * CV_;
    for (int j = 0; j < 32; j += 8) t[ty + j][tx] = s[(size_t)(c0 + ty + j) * NPIX_ + n0 + tx];
    __syncthreads();
    for (int j = 0; j < 32; j += 8) d[(size_t)(n0 + ty + j) * CV_ + c0 + tx] = t[tx][ty + j];
}

// C[p][o] = sum_k A[p][k]*W[o][k] + bias[o]  (64x64 tiles, f32x2)
__global__ void k_gemm(const float* __restrict__ A, const float* __restrict__ W,
                       const float* __restrict__ bias, float* __restrict__ C, int K, int O) {
    __shared__ float As[16][64], Ws[16][64];
    int p0 = blockIdx.y << 6, o0 = blockIdx.x << 6, tid = threadIdx.x;
    int tx4 = (tid & 15) * 4, ty4 = (tid >> 4) * 4;
    ull acc[4][2];
    #pragma unroll
    for (int i = 0; i < 4; i++) { acc[i][0] = 0ull; acc[i][1] = 0ull; }
    for (int k0 = 0; k0 < K; k0 += 16) {
        #pragma unroll
        for (int i = 0; i < 4; i++) {
            int idx = i * 256 + tid, pp = idx >> 4, kk = idx & 15;
            As[kk][pp] = A[(size_t)(p0 + pp) * K + k0 + kk];
            Ws[kk][pp] = W[(size_t)(o0 + pp) * K + k0 + kk];
        }
        __syncthreads();
        #pragma unroll
        for (int kk = 0; kk < 16; kk++) {
            float4 a = *(const float4*)&As[kk][ty4];
            ull b0 = *(const ull*)&Ws[kk][tx4];
            ull b1 = *(const ull*)&Ws[kk][tx4 + 2];
            float av[4] = {a.x, a.y, a.z, a.w};
            #pragma unroll
            for (int ii = 0; ii < 4; ii++) {
                ull pa = pk2(av[ii], av[ii]);
                fma2(acc[ii][0], pa, b0);
                fma2(acc[ii][1], pa, b1);
            }
        }
        __syncthreads();
    }
    for (int ii = 0; ii < 4; ii++) {
        float2 q0 = up2(acc[ii][0]), q1 = up2(acc[ii][1]);
        float4 r;
        r.x = q0.x + bias[o0+tx4+0]; r.y = q0.y + bias[o0+tx4+1];
        r.z = q1.x + bias[o0+tx4+2]; r.w = q1.y + bias[o0+tx4+3];
        *(float4*)&C[(size_t)(p0 + ty4 + ii) * O + o0 + tx4] = r;
    }
}

// cor = Qf·Kf^T / sqrt(320)   (128x128 tiles, 8x8 microtiles, f32x2)
__global__ void k_cor2(const float* __restrict__ Qf, const float* __restrict__ Kf,
                       float* __restrict__ cor) {
    __shared__ float As[8][132], Bs[8][132];
    int b = blockIdx.z, n0 = blockIdx.y << 7, m0 = blockIdx.x << 7;
    int tid = threadIdx.x, tx = tid & 15, ty = tid >> 4;
    int r = tid >> 1, kq = (tid & 1) << 2;
    const float* A  = Qf + (size_t)(b * NPIX_ + n0) * CQK_;
    const float* Bk = Kf + (size_t)(b * NPIX_ + m0) * CQK_;
    ull acc[8][4];
    #pragma unroll
    for (int i = 0; i < 8; i++)
        #pragma unroll
        for (int j = 0; j < 4; j++) acc[i][j] = 0ull;
    for (int k0 = 0; k0 < CQK_; k0 += 8) {
        float4 av = *(const float4*)&A [(size_t)r * CQK_ + k0 + kq];
        float4 bv = *(const float4*)&Bk[(size_t)r * CQK_ + k0 + kq];
        As[kq+0][r] = av.x; As[kq+1][r] = av.y; As[kq+2][r] = av.z; As[kq+3][r] = av.w;
        Bs[kq+0][r] = bv.x; Bs[kq+1][r] = bv.y; Bs[kq+2][r] = bv.z; Bs[kq+3][r] = bv.w;
        __syncthreads();
        #pragma unroll
        for (int kk = 0; kk < 8; kk++) {
            float4 a0 = *(const float4*)&As[kk][ty << 3];
            float4 a1 = *(const float4*)&As[kk][(ty << 3) + 4];
            ull bb[4];
            #pragma unroll
            for (int j = 0; j < 4; j++) bb[j] = *(const ull*)&Bs[kk][(tx << 3) + 2*j];
            float aa[8] = {a0.x,a0.y,a0.z,a0.w,a1.x,a1.y,a1.z,a1.w};
            #pragma unroll
            for (int i = 0; i < 8; i++) {
                ull pa = pk2(aa[i], aa[i]);
                #pragma unroll
                for (int j = 0; j < 4; j++) fma2(acc[i][j], pa, bb[j]);
            }
        }
        __syncthreads();
    }
    const float s = 0.05590169943749474f;
    #pragma unroll
    for (int i = 0; i < 8; i++) {
        int n = n0 + (ty << 3) + i;
        float2 p0 = up2(acc[i][0]), p1 = up2(acc[i][1]), p2 = up2(acc[i][2]), p3 = up2(acc[i][3]);
        float4 w0 = {p0.x*s, p0.y*s, p1.x*s, p1.y*s};
        float4 w1 = {p2.x*s, p2.y*s, p3.x*s, p3.y*s};
        float* dst = &cor[((size_t)b * NPIX_ + n) * NPIX_ + m0 + (tx << 3)];
        *(float4*)dst = w0; *(float4*)(dst + 4) = w1;
    }
}

// mask = (Qp·Kp^T > 0)   (128x128 tiles, bytes out)
__global__ void k_mask(const float* __restrict__ Qp, const float* __restrict__ Kp,
                       unsigned char* __restrict__ mask) {
    __shared__ float As[8][132], Bs[8][132];
    int b = blockIdx.z, n0 = blockIdx.y << 7, m0 = blockIdx.x << 7;
    int tid = threadIdx.x, tx = tid & 15, ty = tid >> 4;
    int r = tid >> 1, kq = (tid & 1) << 2;
    const float* A  = Qp + (size_t)(b * NPIX_ + n0) * DP_;
    const float* Bk = Kp + (size_t)(b * NPIX_ + m0) * DP_;
    ull acc[8][4];
    #pragma unroll
    for (int i = 0; i < 8; i++)
        #pragma unroll
        for (int j = 0; j < 4; j++) acc[i][j] = 0ull;
    for (int k0 = 0; k0 < DP_; k0 += 8) {
        float4 av = *(const float4*)&A [(size_t)r * DP_ + k0 + kq];
        float4 bv = *(const float4*)&Bk[(size_t)r * DP_ + k0 + kq];
        As[kq+0][r] = av.x; As[kq+1][r] = av.y; As[kq+2][r] = av.z; As[kq+3][r] = av.w;
        Bs[kq+0][r] = bv.x; Bs[kq+1][r] = bv.y; Bs[kq+2][r] = bv.z; Bs[kq+3][r] = bv.w;
        __syncthreads();
        #pragma unroll
        for (int kk = 0; kk < 8; kk++) {
            float4 a0 = *(const float4*)&As[kk][ty << 3];
            float4 a1 = *(const float4*)&As[kk][(ty << 3) + 4];
            ull bb[4];
            #pragma unroll
            for (int j = 0; j < 4; j++) bb[j] = *(const ull*)&Bs[kk][(tx << 3) + 2*j];
            float aa[8] = {a0.x,a0.y,a0.z,a0.w,a1.x,a1.y,a1.z,a1.w};
            #pragma unroll
            for (int i = 0; i < 8; i++) {
                ull pa = pk2(aa[i], aa[i]);
                #pragma unroll
                for (int j = 0; j < 4; j++) fma2(acc[i][j], pa, bb[j]);
            }
        }
        __syncthreads();
    }
    #pragma unroll
    for (int i = 0; i < 8; i++) {
        int n = n0 + (ty << 3) + i;
        float2 p0 = up2(acc[i][0]), p1 = up2(acc[i][1]), p2 = up2(acc[i][2]), p3 = up2(acc[i][3]);
        unsigned lo = (p0.x>0.f?1u:0u) | ((p0.y>0.f?1u:0u)<<8) | ((p1.x>0.f?1u:0u)<<16) | ((p1.y>0.f?1u:0u)<<24);
        unsigned hi = (p2.x>0.f?1u:0u) | ((p2.y>0.f?1u:0u)<<8) | ((p3.x>0.f?1u:0u)<<16) | ((p3.y>0.f?1u:0u)<<24);
        unsigned char* dst = &mask[((size_t)b * NPIX_ + n) * NPIX_ + m0 + (tx << 3)];
        *(unsigned*)dst = lo; *(unsigned*)(dst + 4) = hi;
    }
}

__global__ void k_rowstats(const float* __restrict__ cor, const unsigned char* __restrict__ mask,
                           float* __restrict__ stats, float* __restrict__ conf) {
    int row = blockIdx.x, tid = threadIdx.x;
    const float* r = cor + (size_t)row * NPIX_;
    const unsigned char* mk = mask + (size_t)row * NPIX_;
    __shared__ float sa[256], sb[256], sc[256];
    float mx1 = -3.0e38f, mx2 = -3.0e38f;
    for (int m = tid; m < NPIX_; m += 256) {
        float x = r[m];
        mx1 = fmaxf(mx1, x);
        mx2 = fmaxf(mx2, mk[m] ? -10000.f : x);
    }
    sa[tid] = mx1; sb[tid] = mx2;
    __syncthreads();
    for (int s = 128; s > 0; s >>= 1) {
        if (tid < s) { sa[tid] = fmaxf(sa[tid], sa[tid+s]); sb[tid] = fmaxf(sb[tid], sb[tid+s]); }
        __syncthreads();
    }
    mx1 = sa[0]; mx2 = sb[0];
    __syncthreads();
    float s1 = 0.f, sm = 0.f, s2 = 0.f;
    for (int m = tid; m < NPIX_; m += 256) {
        float x = r[m], mv = mk[m] ? 1.f : 0.f;
        float e1 = __expf(x - mx1);
        s1 += e1; sm += mv * e1;
        s2 += __expf((mv > 0.f ? -10000.f : x) - mx2);
    }
    sa[tid] = s1; sb[tid] = sm; sc[tid] = s2;
    __syncthreads();
    for (int s = 128; s > 0; s >>= 1) {
        if (tid < s) { sa[tid] += sa[tid+s]; sb[tid] += sb[tid+s]; sc[tid] += sc[tid+s]; }
        __syncthreads();
    }
    if (tid == 0) {
        stats[row*4+0] = mx1; stats[row*4+1] = 1.f / sa[0];
        stats[row*4+2] = mx2; stats[row*4+3] = 1.f / sc[0];
        conf[row] = sb[0] / sa[0];
    }
}

// out[n][c] = sum_m w(cor,mask)[n][m] * V[m][c]; g=0: masked softmax x Vh -> outat[b][c][n]
// g=1: inverse-masked softmax x V2 -> out2[b][c][n]
__global__ void k_av(const float* __restrict__ cor, const unsigned char* __restrict__ mask,
                     const float* __restrict__ stats, const float* __restrict__ Vh,
                     const float* __restrict__ V2t, float* __restrict__ outat,
                     float* __restrict__ out2) {
    __shared__ float As[8][132], Bs[8][132];
    __shared__ float smx[128], sinv[128];
    int b = blockIdx.z;
    int g = blockIdx.x >> 1, ct = blockIdx.x & 1;
    int n0 = blockIdx.y << 7, c0 = ct << 7;
    int tid = threadIdx.x, tx = tid & 15, ty = tid >> 4;
    int ar = tid >> 1, amq = (tid & 1) << 2;
    int br = tid >> 5, bcq = (tid & 31) << 2;
    if (tid < 128) {
        smx[tid]  = stats[((size_t)b * NPIX_ + n0 + tid) * 4 + g * 2 + 0];
        sinv[tid] = stats[((size_t)b * NPIX_ + n0 + tid) * 4 + g * 2 + 1];
    }
    const float* V = (g ? V2t : Vh) + (size_t)b * NPIX_ * CV_ + c0;
    const float* C = cor + ((size_t)b * NPIX_ + n0) * NPIX_;
    const unsigned char* M = mask + ((size_t)b * NPIX_ + n0) * NPIX_;
    ull acc[8][4];
    #pragma unroll
    for (int i = 0; i < 8; i++)
        #pragma unroll
        for (int j = 0; j < 4; j++) acc[i][j] = 0ull;
    __syncthreads();
    for (int k0 = 0; k0 < NPIX_; k0 += 8) {
        float4 cv = *(const float4*)&C[(size_t)ar * NPIX_ + k0 + amq];
        uchar4 mv = *(const uchar4*)&M[(size_t)ar * NPIX_ + k0 + amq];
        float mx = smx[ar], iv = sinv[ar];
        float x[4] = {cv.x, cv.y, cv.z, cv.w};
        unsigned char mm[4] = {mv.x, mv.y, mv.z, mv.w};
        #pragma unroll
        for (int t = 0; t < 4; t++) {
            float w;
            if (g == 0) w = mm[t] ? __expf(x[t] - mx) * iv : 0.f;
            else        w = __expf((mm[t] ? -10000.f : x[t]) - mx) * iv;
            As[amq + t][ar] = w;
        }
        float4 vv = *(const float4*)&V[(size_t)(k0 + br) * CV_ + bcq];
        *(float4*)&Bs[br][bcq] = vv;
        __syncthreads();
        #pragma unroll
        for (int kk = 0; kk < 8; kk++) {
            float4 a0 = *(const float4*)&As[kk][ty << 3];
            float4 a1 = *(const float4*)&As[kk][(ty << 3) + 4];
            ull bb[4];
            #pragma unroll
            for (int j = 0; j < 4; j++) bb[j] = *(const ull*)&Bs[kk][(tx << 3) + 2*j];
            float aa[8] = {a0.x,a0.y,a0.z,a0.w,a1.x,a1.y,a1.z,a1.w};
            #pragma unroll
            for (int i = 0; i < 8; i++) {
                ull pa = pk2(aa[i], aa[i]);
                #pragma unroll
                for (int j = 0; j < 4; j++) fma2(acc[i][j], pa, bb[j]);
            }
        }
        __syncthreads();
    }
    float* O = g ? out2 : outat;
    float rr[8][8];
    #pragma unroll
    for (int i = 0; i < 8; i++)
        #pragma unroll
        for (int jp = 0; jp < 4; jp++) {
            float2 p = up2(acc[i][jp]);
            rr[i][2*jp] = p.x; rr[i][2*jp+1] = p.y;
        }
    #pragma unroll
    for (int j = 0; j < 8; j++) {
        int c = c0 + (tx << 3) + j;
        float4 w0 = {rr[0][j], rr[1][j], rr[2][j], rr[3][j]};
        float4 w1 = {rr[4][j], rr[5][j], rr[6][j], rr[7][j]};
        float* dst = &O[((size_t)b * CV_ + c) * NPIX_ + n0 + (ty << 3)];
        *(float4*)dst = w0; *(float4*)(dst + 4) = w1;
    }
}

// 3x3 conv SAME, NCHW, f32x2 inner. flags: 1=relu, 2=add res
__global__ void k_conv3(const float* __restrict__ in, const float* __restrict__ wgt,
                        const float* __restrict__ bias, float* __restrict__ out,
                        int Cin, int Cout, int flags, const float* __restrict__ res) {
    __shared__ float ins[1600];
    __shared__ float ws[9216];
    int b = blockIdx.z, t = blockIdx.y, oc0 = blockIdx.x << 6;
    int y0 = (t >> 3) << 3, x0 = (t & 7) << 3, tid = threadIdx.x;
    int tx = tid & 15, ty = tid >> 4;
    int pyb = tx >> 1, pxb = (tx & 1) << 2;
    ull acc[4][2];
    #pragma unroll
    for (int i = 0; i < 4; i++) { acc[i][0] = 0ull; acc[i][1] = 0ull; }
    for (int ic0 = 0; ic0 < Cin; ic0 += 16) {
        for (int i = tid; i < 1600; i += 256) {
            int icl = i / 100, rem = i - icl * 100, hy = rem / 10, hx = rem - hy * 10;
            int gy = y0 + hy - 1, gx = x0 + hx - 1, ic = ic0 + icl;
            float v = 0.f;
            if (ic < Cin && (unsigned)gy < 64u && (unsigned)gx < 64u)
                v = in[(((size_t)b * Cin + ic) * 64 + gy) * 64 + gx];
            ins[i] = v;
        }
        for (int i = tid; i < 9216; i += 256) {
            int oc = i & 63, kk = i >> 6, icl = kk / 9, tap = kk - icl * 9, ic = ic0 + icl;
            ws[i] = (ic < Cin) ? wgt[(((size_t)(oc0 + oc)) * Cin + ic) * 9 + tap] : 0.f;
        }
        __syncthreads();
        int icm = (Cin - ic0 < 16) ? (Cin - ic0) : 16;
        for (int icl = 0; icl < icm; icl++) {
            #pragma unroll
            for (int tap = 0; tap < 9; tap++) {
                int ky = tap / 3, kx = tap - ky * 3;
                float4 wv = *(const float4*)&ws[(icl * 9 + tap) * 64 + ty * 4];
                const float* ip = &ins[icl * 100 + (pyb + ky) * 10 + pxb + kx];
                ull x01 = pk2(ip[0], ip[1]);
                ull x23 = pk2(ip[2], ip[3]);
                ull pw0 = pk2(wv.x, wv.x), pw1 = pk2(wv.y, wv.y);
                ull pw2 = pk2(wv.z, wv.z), pw3 = pk2(wv.w, wv.w);
                fma2(acc[0][0], pw0, x01); fma2(acc[0][1], pw0, x23);
                fma2(acc[1][0], pw1, x01); fma2(acc[1][1], pw1, x23);
                fma2(acc[2][0], pw2, x01); fma2(acc[2][1], pw2, x23);
                fma2(acc[3][0], pw3, x01); fma2(acc[3][1], pw3, x23);
            }
        }
        __syncthreads();
    }
    for (int oi = 0; oi < 4; oi++) {
        int oc = oc0 + ty * 4 + oi;
        float bv = bias[oc];
        size_t ob = (((size_t)b * Cout + oc) * 64 + y0 + pyb) * 64 + x0 + pxb;
        float2 q0 = up2(acc[oi][0]), q1 = up2(acc[oi][1]);
        float vals[4] = {q0.x, q0.y, q1.x, q1.y};
        #pragma unroll
        for (int pj = 0; pj < 4; pj++) {
            float vv = vals[pj] + bv;
            if (flags & 1) vv = fmaxf(vv, 0.f);
            if (flags & 2) vv += res[ob + pj];
            out[ob + pj] = vv;
        }
    }
}

__global__ void k_instnorm(const float* __restrict__ x, float* __restrict__ st) {
    int row = blockIdx.x, tid = threadIdx.x;
    const float* p = x + (size_t)row * NPIX_;
    float s = 0.f, ss = 0.f;
    for (int i = tid; i < NPIX_; i += 256) { float v = p[i]; s += v; ss += v * v; }
    __shared__ float r1[256], r2[256];
    r1[tid] = s; r2[tid] = ss;
    __syncthreads();
    for (int k = 128; k > 0; k >>= 1) {
        if (tid < k) { r1[tid] += r1[tid+k]; r2[tid] += r2[tid+k]; }
        __syncthreads();
    }
    if (tid == 0) {
        float m = r1[0] * (1.f / NPIX_);
        float v = r2[0] * (1.f / NPIX_) - m * m;
        st[row*2] = m; st[row*2+1] = rsqrtf(v + 1e-5f);
    }
}

__global__ void k_spade_pono(const float* __restrict__ q, const float* __restrict__ gam,
                             const float* __restrict__ bet, const float* __restrict__ outat,
                             const float* __restrict__ conf, const float* __restrict__ innm,
                             float* __restrict__ y) {
    int b = blockIdx.x >> 6, n0 = (blockIdx.x & 63) << 6, tid = threadIdx.x;
    int nn = tid & 63, cp = tid >> 6;
    __shared__ float ps[4][64], pss[4][64], pm[64], pr[64];
    float cf = conf[(size_t)b * NPIX_ + n0 + nn];
    float s = 0.f, ss = 0.f;
    for (int base = 0; base < CV_; base += 4) {
        int cc = base + cp;
        size_t o = ((size_t)b * CV_ + cc) * NPIX_ + n0 + nn;
        float m = innm[(b*CV_+cc)*2], rs = innm[(b*CV_+cc)*2+1];
        float qv = q[o];
        float sp = (qv - m) * rs * (1.f + gam[o]) + bet[o];
        float tv = outat[o] + (1.f - cf) * sp + qv;
        s += tv; ss += tv * tv;
    }
    ps[cp][nn] = s; pss[cp][nn] = ss;
    __syncthreads();
    if (tid < 64) {
        float S = ps[0][tid]+ps[1][tid]+ps[2][tid]+ps[3][tid];
        float SS = pss[0][tid]+pss[1][tid]+pss[2][tid]+pss[3][tid];
        float m = S * (1.f/256.f), v = SS * (1.f/256.f) - m * m;
        pm[tid] = m; pr[tid] = rsqrtf(v + 1e-5f);
    }
    __syncthreads();
    float mmu = pm[nn], rr = pr[nn];
    for (int base = 0; base < CV_; base += 4) {
        int cc = base + cp;
        size_t o = ((size_t)b * CV_ + cc) * NPIX_ + n0 + nn;
        float m = innm[(b*CV_+cc)*2], rs = innm[(b*CV_+cc)*2+1];
        float qv = q[o];
        float sp = (qv - m) * rs * (1.f + gam[o]) + bet[o];
        float tv = outat[o] + (1.f - cf) * sp + qv;
        y[o] = (tv - mmu) * rr;
    }
}

extern "C" void kernel_launch(void* const* d_in, const int* in_sizes, int n_in,
                              void* d_out, int out_size) {
    const float *q = (const float*)d_in[0], *k = (const float*)d_in[1],
                *v = (const float*)d_in[2], *pos = (const float*)d_in[3],
                *seg = (const float*)d_in[4], *v2 = (const float*)d_in[5],
                *f_w = (const float*)d_in[6], *f_b = (const float*)d_in[7],
                *g_w = (const float*)d_in[8], *g_b = (const float*)d_in[9],
                *h_w = (const float*)d_in[10], *h_b = (const float*)d_in[11],
                *fp_w = (const float*)d_in[12], *fp_b = (const float*)d_in[13],
                *gp_w = (const float*)d_in[14], *gp_b = (const float*)d_in[15],
                *sp_s_w = (const float*)d_in[16], *sp_s_b = (const float*)d_in[17],
                *sp_g_w = (const float*)d_in[18], *sp_g_b = (const float*)d_in[19],
                *sp_b_w = (const float*)d_in[20], *sp_b_b = (const float*)d_in[21],
                *r1_w = (const float*)d_in[22], *r1_b = (const float*)d_in[23],
                *r2_w = (const float*)d_in[24], *r2_b = (const float*)d_in[25];
    float* S;
    cudaGetSymbolAddress((void**)&S, g_scratch);
    float* out_res  = (float*)d_out;
    float* out_out2 = out_res + 2097152;
    float* out_cor  = out_res + 4194304;
    unsigned char* mask = (unsigned char*)(S + OFF_MASK);

    k_normcat<<<128, 256>>>(q, pos, S + OFF_QUERY);
    k_normcat<<<128, 256>>>(k, pos, S + OFF_KEYT);
    k_transpose<<<dim3(8,128,2), dim3(32,8)>>>(v,  S + OFF_VT);
    k_transpose<<<dim3(8,128,2), dim3(32,8)>>>(v2, S + OFF_V2T);
    k_gemm<<<dim3(5,128), 256>>>(S + OFF_QUERY, f_w,  f_b,  S + OFF_QF, CQK_, CQK_);
    k_gemm<<<dim3(5,128), 256>>>(S + OFF_KEYT,  g_w,  g_b,  S + OFF_KF, CQK_, CQK_);
    k_gemm<<<dim3(1,128), 256>>>(S + OFF_QUERY, fp_w, fp_b, S + OFF_QP, CQK_, DP_);
    k_gemm<<<dim3(1,128), 256>>>(S + OFF_KEYT,  gp_w, gp_b, S + OFF_KP, CQK_, DP_);
    k_gemm<<<dim3(4,128), 256>>>(S + OFF_VT,    h_w,  h_b,  S + OFF_VH, CV_,  CV_);
    k_cor2<<<dim3(32,32,2), 256>>>(S + OFF_QF, S + OFF_KF, out_cor);
    k_mask<<<dim3(32,32,2), 256>>>(S + OFF_QP, S + OFF_KP, mask);
    k_rowstats<<<8192, 256>>>(out_cor, mask, S + OFF_STATS, S + OFF_CONF);
    k_av<<<dim3(4,32,2), 256>>>(out_cor, mask, S + OFF_STATS, S + OFF_VH,
                                S + OFF_V2T, S + OFF_OUT, out_out2);
    k_conv3<<<dim3(2,64,2), 256>>>(seg, sp_s_w, sp_s_b, S + OFF_ACTV, 3, 128, 1, nullptr);
    k_conv3<<<dim3(4,64,2), 256>>>(S + OFF_ACTV, sp_g_w, sp_g_b, S + OFF_GAMMA, 128, 256, 0, nullptr);
    k_conv3<<<dim3(4,64,2), 256>>>(S + OFF_ACTV, sp_b_w, sp_b_b, S + OFF_BETA,  128, 256, 0, nullptr);
    k_instnorm<<<512, 256>>>(q, S + OFF_INNM);
    k_spade_pono<<<128, 256>>>(q, S + OFF_GAMMA, S + OFF_BETA, S + OFF_OUT,
                               S + OFF_CONF, S + OFF_INNM, S + OFF_Y);
    k_conv3<<<dim3(4,64,2), 256>>>(S + OFF_Y,  r1_w, r1_b, S + OFF_T1, 256, 256, 1, nullptr);
    k_conv3<<<dim3(4,64,2), 256>>>(S + OFF_T1, r2_w, r2_b, out_res,    256, 256, 2, S + OFF_Y);
}

// round 4
// speedup vs baseline: 2.0587x; 1.0676x over previous
#include <cuda_runtime.h>
#include <math.h>

#define CV_   256
#define CQK_  320
#define DP_   64
#define NPIX_ 4096

#define OFF_QUERY  0u
#define OFF_KEYT   (OFF_QUERY + 2621440u)
#define OFF_QF     (OFF_KEYT  + 2621440u)
#define OFF_KF     (OFF_QF    + 2621440u)
#define OFF_QP     (OFF_KF    + 2621440u)
#define OFF_KP     (OFF_QP    + 524288u)
#define OFF_VT     (OFF_KP    + 524288u)
#define OFF_V2T    (OFF_VT    + 2097152u)
#define OFF_VH     (OFF_V2T   + 2097152u)
#define OFF_STATS  (OFF_VH    + 2097152u)
#define OFF_CONF   (OFF_STATS + 32768u)
#define OFF_OUT    (OFF_CONF  + 8192u)
#define OFF_ACTV   (OFF_OUT   + 2097152u)
#define OFF_GAMMA  (OFF_ACTV  + 1048576u)
#define OFF_BETA   (OFF_GAMMA + 2097152u)
#define OFF_Y      (OFF_BETA  + 2097152u)
#define OFF_T1     (OFF_Y     + 2097152u)
#define OFF_INNM   (OFF_T1    + 2097152u)
#define OFF_MASK   (OFF_INNM  + 1024u)
#define SCRATCH_FLOATS (OFF_MASK + 8388608u)

__device__ float g_scratch[SCRATCH_FLOATS];

typedef unsigned long long ull;
__device__ __forceinline__ ull pk2(float lo, float hi) {
    ull r; asm("mov.b64 %0,{%1,%2};" : "=l"(r) : "f"(lo), "f"(hi)); return r;
}
__device__ __forceinline__ void fma2(ull& d, ull a, ull b) {
    asm("fma.rn.f32x2 %0,%1,%2,%0;" : "+l"(d) : "l"(a), "l"(b));
}
__device__ __forceinline__ float2 up2(ull v) {
    float2 f; asm("mov.b64 {%0,%1},%2;" : "=f"(f.x), "=f"(f.y) : "l"(v)); return f;
}

// normalize src over channels, concat pos -> dst[b][n][320]
__global__ void k_normcat(const float* __restrict__ src, const float* __restrict__ pos,
                          float* __restrict__ dst) {
    int b = blockIdx.x >> 6, n0 = (blockIdx.x & 63) << 6, tid = threadIdx.x;
    __shared__ float red[4][64], rnorm[64];
    int nn = tid & 63, cp = tid >> 6;
    const float* sp = src + (size_t)b * CV_ * NPIX_ + n0 + nn;
    float acc = 0.f;
    for (int c = cp; c < CV_; c += 4) { float x = sp[(size_t)c * NPIX_]; acc += x * x; }
    red[cp][nn] = acc;
    __syncthreads();
    if (tid < 64) {
        float s = red[0][tid] + red[1][tid] + red[2][tid] + red[3][tid];
        rnorm[tid] = 1.f / (sqrtf(s) + 2.220446049250313e-16f);
    }
    __syncthreads();
    for (int i = 0; i < 80; i++) {
        int idx = i * 256 + tid, n = idx / CQK_, c = idx - n * CQK_;
        float v = (c < CV_) ? src[(size_t)(b * CV_ + c) * NPIX_ + n0 + n] * rnorm[n]
                            : pos[(size_t)(c - CV_) * NPIX_ + n0 + n];
        dst[((size_t)b * NPIX_ + n0 + n) * CQK_ + c] = v;
    }
}

__global__ void k_transpose(const float* __restrict__ src, float* __restrict__ dst) {
    __shared__ float t[32][33];
    int c0 = blockIdx.x * 32, n0 = blockIdx.y * 32, b = blockIdx.z;
    int tx = threadIdx.x, ty = threadIdx.y;
    const float* s = src + (size_t)b * CV_ * NPIX_;
    float* d = dst + (size_t)b * NPIX_ * CV_;
    for (int j = 0; j < 32; j += 8) t[ty + j][tx] = s[(size_t)(c0 + ty + j) * NPIX_ + n0 + tx];
    __syncthreads();
    for (int j = 0; j < 32; j += 8) d[(size_t)(n0 + ty + j) * CV_ + c0 + tx] = t[tx][ty + j];
}

// C[p][o] = sum_k A[p][k]*W[o][k] + bias[o]  (64x64 tiles, f32x2)
__global__ void k_gemm(const float* __restrict__ A, const float* __restrict__ W,
                       const float* __restrict__ bias, float* __restrict__ C, int K, int O) {
    __shared__ float As[16][64], Ws[16][64];
    int p0 = blockIdx.y << 6, o0 = blockIdx.x << 6, tid = threadIdx.x;
    int tx4 = (tid & 15) * 4, ty4 = (tid >> 4) * 4;
    ull acc[4][2];
    #pragma unroll
    for (int i = 0; i < 4; i++) { acc[i][0] = 0ull; acc[i][1] = 0ull; }
    for (int k0 = 0; k0 < K; k0 += 16) {
        #pragma unroll
        for (int i = 0; i < 4; i++) {
            int idx = i * 256 + tid, pp = idx >> 4, kk = idx & 15;
            As[kk][pp] = A[(size_t)(p0 + pp) * K + k0 + kk];
            Ws[kk][pp] = W[(size_t)(o0 + pp) * K + k0 + kk];
        }
        __syncthreads();
        #pragma unroll
        for (int kk = 0; kk < 16; kk++) {
            float4 a = *(const float4*)&As[kk][ty4];
            ull b0 = *(const ull*)&Ws[kk][tx4];
            ull b1 = *(const ull*)&Ws[kk][tx4 + 2];
            float av[4] = {a.x, a.y, a.z, a.w};
            #pragma unroll
            for (int ii = 0; ii < 4; ii++) {
                ull pa = pk2(av[ii], av[ii]);
                fma2(acc[ii][0], pa, b0);
                fma2(acc[ii][1], pa, b1);
            }
        }
        __syncthreads();
    }
    for (int ii = 0; ii < 4; ii++) {
        float2 q0 = up2(acc[ii][0]), q1 = up2(acc[ii][1]);
        float4 r;
        r.x = q0.x + bias[o0+tx4+0]; r.y = q0.y + bias[o0+tx4+1];
        r.z = q1.x + bias[o0+tx4+2]; r.w = q1.y + bias[o0+tx4+3];
        *(float4*)&C[(size_t)(p0 + ty4 + ii) * O + o0 + tx4] = r;
    }
}

// cor = Qf·Kf^T / sqrt(320)   (128x128 tiles, 8x8 microtiles, f32x2)
__global__ void k_cor2(const float* __restrict__ Qf, const float* __restrict__ Kf,
                       float* __restrict__ cor) {
    __shared__ float As[8][132], Bs[8][132];
    int b = blockIdx.z, n0 = blockIdx.y << 7, m0 = blockIdx.x << 7;
    int tid = threadIdx.x, tx = tid & 15, ty = tid >> 4;
    int r = tid >> 1, kq = (tid & 1) << 2;
    const float* A  = Qf + (size_t)(b * NPIX_ + n0) * CQK_;
    const float* Bk = Kf + (size_t)(b * NPIX_ + m0) * CQK_;
    ull acc[8][4];
    #pragma unroll
    for (int i = 0; i < 8; i++)
        #pragma unroll
        for (int j = 0; j < 4; j++) acc[i][j] = 0ull;
    for (int k0 = 0; k0 < CQK_; k0 += 8) {
        float4 av = *(const float4*)&A [(size_t)r * CQK_ + k0 + kq];
        float4 bv = *(const float4*)&Bk[(size_t)r * CQK_ + k0 + kq];
        As[kq+0][r] = av.x; As[kq+1][r] = av.y; As[kq+2][r] = av.z; As[kq+3][r] = av.w;
        Bs[kq+0][r] = bv.x; Bs[kq+1][r] = bv.y; Bs[kq+2][r] = bv.z; Bs[kq+3][r] = bv.w;
        __syncthreads();
        #pragma unroll
        for (int kk = 0; kk < 8; kk++) {
            float4 a0 = *(const float4*)&As[kk][ty << 3];
            float4 a1 = *(const float4*)&As[kk][(ty << 3) + 4];
            ull bb[4];
            #pragma unroll
            for (int j = 0; j < 4; j++) bb[j] = *(const ull*)&Bs[kk][(tx << 3) + 2*j];
            float aa[8] = {a0.x,a0.y,a0.z,a0.w,a1.x,a1.y,a1.z,a1.w};
            #pragma unroll
            for (int i = 0; i < 8; i++) {
                ull pa = pk2(aa[i], aa[i]);
                #pragma unroll
                for (int j = 0; j < 4; j++) fma2(acc[i][j], pa, bb[j]);
            }
        }
        __syncthreads();
    }
    const float s = 0.05590169943749474f;
    #pragma unroll
    for (int i = 0; i < 8; i++) {
        int n = n0 + (ty << 3) + i;
        float2 p0 = up2(acc[i][0]), p1 = up2(acc[i][1]), p2 = up2(acc[i][2]), p3 = up2(acc[i][3]);
        float4 w0 = {p0.x*s, p0.y*s, p1.x*s, p1.y*s};
        float4 w1 = {p2.x*s, p2.y*s, p3.x*s, p3.y*s};
        float* dst = &cor[((size_t)b * NPIX_ + n) * NPIX_ + m0 + (tx << 3)];
        *(float4*)dst = w0; *(float4*)(dst + 4) = w1;
    }
}

// mask = (Qp·Kp^T > 0)   (128x128 tiles, bytes out)
__global__ void k_mask(const float* __restrict__ Qp, const float* __restrict__ Kp,
                       unsigned char* __restrict__ mask) {
    __shared__ float As[8][132], Bs[8][132];
    int b = blockIdx.z, n0 = blockIdx.y << 7, m0 = blockIdx.x << 7;
    int tid = threadIdx.x, tx = tid & 15, ty = tid >> 4;
    int r = tid >> 1, kq = (tid & 1) << 2;
    const float* A  = Qp + (size_t)(b * NPIX_ + n0) * DP_;
    const float* Bk = Kp + (size_t)(b * NPIX_ + m0) * DP_;
    ull acc[8][4];
    #pragma unroll
    for (int i = 0; i < 8; i++)
        #pragma unroll
        for (int j = 0; j < 4; j++) acc[i][j] = 0ull;
    for (int k0 = 0; k0 < DP_; k0 += 8) {
        float4 av = *(const float4*)&A [(size_t)r * DP_ + k0 + kq];
        float4 bv = *(const float4*)&Bk[(size_t)r * DP_ + k0 + kq];
        As[kq+0][r] = av.x; As[kq+1][r] = av.y; As[kq+2][r] = av.z; As[kq+3][r] = av.w;
        Bs[kq+0][r] = bv.x; Bs[kq+1][r] = bv.y; Bs[kq+2][r] = bv.z; Bs[kq+3][r] = bv.w;
        __syncthreads();
        #pragma unroll
        for (int kk = 0; kk < 8; kk++) {
            float4 a0 = *(const float4*)&As[kk][ty << 3];
            float4 a1 = *(const float4*)&As[kk][(ty << 3) + 4];
            ull bb[4];
            #pragma unroll
            for (int j = 0; j < 4; j++) bb[j] = *(const ull*)&Bs[kk][(tx << 3) + 2*j];
            float aa[8] = {a0.x,a0.y,a0.z,a0.w,a1.x,a1.y,a1.z,a1.w};
            #pragma unroll
            for (int i = 0; i < 8; i++) {
                ull pa = pk2(aa[i], aa[i]);
                #pragma unroll
                for (int j = 0; j < 4; j++) fma2(acc[i][j], pa, bb[j]);
            }
        }
        __syncthreads();
    }
    #pragma unroll
    for (int i = 0; i < 8; i++) {
        int n = n0 + (ty << 3) + i;
        float2 p0 = up2(acc[i][0]), p1 = up2(acc[i][1]), p2 = up2(acc[i][2]), p3 = up2(acc[i][3]);
        unsigned lo = (p0.x>0.f?1u:0u) | ((p0.y>0.f?1u:0u)<<8) | ((p1.x>0.f?1u:0u)<<16) | ((p1.y>0.f?1u:0u)<<24);
        unsigned hi = (p2.x>0.f?1u:0u) | ((p2.y>0.f?1u:0u)<<8) | ((p3.x>0.f?1u:0u)<<16) | ((p3.y>0.f?1u:0u)<<24);
        unsigned char* dst = &mask[((size_t)b * NPIX_ + n) * NPIX_ + m0 + (tx << 3)];
        *(unsigned*)dst = lo; *(unsigned*)(dst + 4) = hi;
    }
}

__global__ void k_rowstats(const float* __restrict__ cor, const unsigned char* __restrict__ mask,
                           float* __restrict__ stats, float* __restrict__ conf) {
    int row = blockIdx.x, tid = threadIdx.x;
    const float* r = cor + (size_t)row * NPIX_;
    const unsigned char* mk = mask + (size_t)row * NPIX_;
    __shared__ float sa[256], sb[256], sc[256];
    float mx1 = -3.0e38f, mx2 = -3.0e38f;
    for (int m = tid; m < NPIX_; m += 256) {
        float x = r[m];
        mx1 = fmaxf(mx1, x);
        mx2 = fmaxf(mx2, mk[m] ? -10000.f : x);
    }
    sa[tid] = mx1; sb[tid] = mx2;
    __syncthreads();
    for (int s = 128; s > 0; s >>= 1) {
        if (tid < s) { sa[tid] = fmaxf(sa[tid], sa[tid+s]); sb[tid] = fmaxf(sb[tid], sb[tid+s]); }
        __syncthreads();
    }
    mx1 = sa[0]; mx2 = sb[0];
    __syncthreads();
    float s1 = 0.f, sm = 0.f, s2 = 0.f;
    for (int m = tid; m < NPIX_; m += 256) {
        float x = r[m], mv = mk[m] ? 1.f : 0.f;
        float e1 = __expf(x - mx1);
        s1 += e1; sm += mv * e1;
        s2 += __expf((mv > 0.f ? -10000.f : x) - mx2);
    }
    sa[tid] = s1; sb[tid] = sm; sc[tid] = s2;
    __syncthreads();
    for (int s = 128; s > 0; s >>= 1) {
        if (tid < s) { sa[tid] += sa[tid+s]; sb[tid] += sb[tid+s]; sc[tid] += sc[tid+s]; }
        __syncthreads();
    }
    if (tid == 0) {
        stats[row*4+0] = mx1; stats[row*4+1] = 1.f / sa[0];
        stats[row*4+2] = mx2; stats[row*4+3] = 1.f / sc[0];
        conf[row] = sb[0] / sa[0];
    }
}

// out[n][c] = sum_m w(cor,mask)[n][m] * V[m][c]
__global__ void k_av(const float* __restrict__ cor, const unsigned char* __restrict__ mask,
                     const float* __restrict__ stats, const float* __restrict__ Vh,
                     const float* __restrict__ V2t, float* __restrict__ outat,
                     float* __restrict__ out2) {
    __shared__ float As[8][132], Bs[8][132];
    __shared__ float smx[128], sinv[128];
    int b = blockIdx.z;
    int g = blockIdx.x >> 1, ct = blockIdx.x & 1;
    int n0 = blockIdx.y << 7, c0 = ct << 7;
    int tid = threadIdx.x, tx = tid & 15, ty = tid >> 4;
    int ar = tid >> 1, amq = (tid & 1) << 2;
    int br = tid >> 5, bcq = (tid & 31) << 2;
    if (tid < 128) {
        smx[tid]  = stats[((size_t)b * NPIX_ + n0 + tid) * 4 + g * 2 + 0];
        sinv[tid] = stats[((size_t)b * NPIX_ + n0 + tid) * 4 + g * 2 + 1];
    }
    const float* V = (g ? V2t : Vh) + (size_t)b * NPIX_ * CV_ + c0;
    const float* C = cor + ((size_t)b * NPIX_ + n0) * NPIX_;
    const unsigned char* M = mask + ((size_t)b * NPIX_ + n0) * NPIX_;
    ull acc[8][4];
    #pragma unroll
    for (int i = 0; i < 8; i++)
        #pragma unroll
        for (int j = 0; j < 4; j++) acc[i][j] = 0ull;
    __syncthreads();
    for (int k0 = 0; k0 < NPIX_; k0 += 8) {
        float4 cv = *(const float4*)&C[(size_t)ar * NPIX_ + k0 + amq];
        uchar4 mv = *(const uchar4*)&M[(size_t)ar * NPIX_ + k0 + amq];
        float mx = smx[ar], iv = sinv[ar];
        float x[4] = {cv.x, cv.y, cv.z, cv.w};
        unsigned char mm[4] = {mv.x, mv.y, mv.z, mv.w};
        #pragma unroll
        for (int t = 0; t < 4; t++) {
            float w;
            if (g == 0) w = mm[t] ? __expf(x[t] - mx) * iv : 0.f;
            else        w = __expf((mm[t] ? -10000.f : x[t]) - mx) * iv;
            As[amq + t][ar] = w;
        }
        float4 vv = *(const float4*)&V[(size_t)(k0 + br) * CV_ + bcq];
        *(float4*)&Bs[br][bcq] = vv;
        __syncthreads();
        #pragma unroll
        for (int kk = 0; kk < 8; kk++) {
            float4 a0 = *(const float4*)&As[kk][ty << 3];
            float4 a1 = *(const float4*)&As[kk][(ty << 3) + 4];
            ull bb[4];
            #pragma unroll
            for (int j = 0; j < 4; j++) bb[j] = *(const ull*)&Bs[kk][(tx << 3) + 2*j];
            float aa[8] = {a0.x,a0.y,a0.z,a0.w,a1.x,a1.y,a1.z,a1.w};
            #pragma unroll
            for (int i = 0; i < 8; i++) {
                ull pa = pk2(aa[i], aa[i]);
                #pragma unroll
                for (int j = 0; j < 4; j++) fma2(acc[i][j], pa, bb[j]);
            }
        }
        __syncthreads();
    }
    float* O = g ? out2 : outat;
    float rr[8][8];
    #pragma unroll
    for (int i = 0; i < 8; i++)
        #pragma unroll
        for (int jp = 0; jp < 4; jp++) {
            float2 p = up2(acc[i][jp]);
            rr[i][2*jp] = p.x; rr[i][2*jp+1] = p.y;
        }
    #pragma unroll
    for (int j = 0; j < 8; j++) {
        int c = c0 + (tx << 3) + j;
        float4 w0 = {rr[0][j], rr[1][j], rr[2][j], rr[3][j]};
        float4 w1 = {rr[4][j], rr[5][j], rr[6][j], rr[7][j]};
        float* dst = &O[((size_t)b * CV_ + c) * NPIX_ + n0 + (ty << 3)];
        *(float4*)dst = w0; *(float4*)(dst + 4) = w1;
    }
}

// 3x3 conv SAME, NCHW. Tile 128oc x 64px, 8oc x 4px/thread, hoisted x-window.
// flags: 1=relu, 2=add res
__global__ void k_conv3(const float* __restrict__ in, const float* __restrict__ wgt,
                        const float* __restrict__ bias, float* __restrict__ out,
                        int Cin, int Cout, int flags, const float* __restrict__ res) {
    extern __shared__ float sm[];
    float* ws  = sm;          // 16 icl * 9 taps * 128 oc = 18432
    float* ins = sm + 18432;  // 16 icl * 10*10 = 1600
    int b = blockIdx.z, t = blockIdx.y, oc0 = blockIdx.x << 7;
    int y0 = (t >> 3) << 3, x0 = (t & 7) << 3, tid = threadIdx.x;
    int tx = tid & 15, ty = tid >> 4;
    int pyb = tx >> 1, pxb = (tx & 1) << 2;
    ull acc[4][4];
    #pragma unroll
    for (int p = 0; p < 4; p++)
        #pragma unroll
        for (int j = 0; j < 4; j++) acc[p][j] = 0ull;
    for (int ic0 = 0; ic0 < Cin; ic0 += 16) {
        for (int i = tid; i < 1600; i += 256) {
            int icl = i / 100, rem = i - icl * 100, hy = rem / 10, hx = rem - hy * 10;
            int gy = y0 + hy - 1, gx = x0 + hx - 1, ic = ic0 + icl;
            float v = 0.f;
            if (ic < Cin && (unsigned)gy < 64u && (unsigned)gx < 64u)
                v = in[(((size_t)b * Cin + ic) * 64 + gy) * 64 + gx];
            ins[i] = v;
        }
        for (int i = tid; i < 18432; i += 256) {
            int oc = i & 127, kk = i >> 7, icl = kk / 9, tap = kk - icl * 9, ic = ic0 + icl;
            ws[i] = (ic < Cin) ? wgt[(((size_t)(oc0 + oc)) * Cin + ic) * 9 + tap] : 0.f;
        }
        __syncthreads();
        int icm = (Cin - ic0 < 16) ? (Cin - ic0) : 16;
        for (int icl = 0; icl < icm; icl++) {
            ull xb[3][6];
            const float* iw = &ins[icl * 100 + pyb * 10 + pxb];
            #pragma unroll
            for (int ky = 0; ky < 3; ky++)
                #pragma unroll
                for (int c = 0; c < 6; c++) {
                    float v = iw[ky * 10 + c];
                    xb[ky][c] = pk2(v, v);
                }
            #pragma unroll
            for (int ky = 0; ky < 3; ky++)
                #pragma unroll
                for (int kx = 0; kx < 3; kx++) {
                    const float* wp = &ws[(icl * 9 + ky * 3 + kx) * 128 + (ty << 3)];
                    ull w0 = *(const ull*)wp, w1 = *(const ull*)(wp + 2);
                    ull w2 = *(const ull*)(wp + 4), w3 = *(const ull*)(wp + 6);
                    #pragma unroll
                    for (int p = 0; p < 4; p++) {
                        ull xq = xb[ky][kx + p];
                        fma2(acc[p][0], xq, w0); fma2(acc[p][1], xq, w1);
                        fma2(acc[p][2], xq, w2); fma2(acc[p][3], xq, w3);
                    }
                }
        }
        __syncthreads();
    }
    #pragma unroll
    for (int j = 0; j < 4; j++) {
        int ocA = oc0 + (ty << 3) + 2 * j;
        float bA = bias[ocA], bB = bias[ocA + 1];
        size_t rowA = (((size_t)b * Cout + ocA) * 64 + y0 + pyb) * 64 + x0 + pxb;
        size_t rowB = rowA + 4096;
        #pragma unroll
        for (int p = 0; p < 4; p++) {
            float2 vpair = up2(acc[p][j]);
            float va = vpair.x + bA, vb = vpair.y + bB;
            if (flags & 1) { va = fmaxf(va, 0.f); vb = fmaxf(vb, 0.f); }
            if (flags & 2) { va += res[rowA + p]; vb += res[rowB + p]; }
            out[rowA + p] = va;
            out[rowB + p] = vb;
        }
    }
}

__global__ void k_instnorm(const float* __restrict__ x, float* __restrict__ st) {
    int row = blockIdx.x, tid = threadIdx.x;
    const float* p = x + (size_t)row * NPIX_;
    float s = 0.f, ss = 0.f;
    for (int i = tid; i < NPIX_; i += 256) { float v = p[i]; s += v; ss += v * v; }
    __shared__ float r1[256], r2[256];
    r1[tid] = s; r2[tid] = ss;
    __syncthreads();
    for (int k = 128; k > 0; k >>= 1) {
        if (tid < k) { r1[tid] += r1[tid+k]; r2[tid] += r2[tid+k]; }
        __syncthreads();
    }
    if (tid == 0) {
        float m = r1[0] * (1.f / NPIX_);
        float v = r2[0] * (1.f / NPIX_) - m * m;
        st[row*2] = m; st[row*2+1] = rsqrtf(v + 1e-5f);
    }
}

__global__ void k_spade_pono(const float* __restrict__ q, const float* __restrict__ gam,
                             const float* __restrict__ bet, const float* __restrict__ outat,
                             const float* __restrict__ conf, const float* __restrict__ innm,
                             float* __restrict__ y) {
    int b = blockIdx.x >> 6, n0 = (blockIdx.x & 63) << 6, tid = threadIdx.x;
    int nn = tid & 63, cp = tid >> 6;
    __shared__ float ps[4][64], pss[4][64], pm[64], pr[64];
    float cf = conf[(size_t)b * NPIX_ + n0 + nn];
    float s = 0.f, ss = 0.f;
    for (int base = 0; base < CV_; base += 4) {
        int cc = base + cp;
        size_t o = ((size_t)b * CV_ + cc) * NPIX_ + n0 + nn;
        float m = innm[(b*CV_+cc)*2], rs = innm[(b*CV_+cc)*2+1];
        float qv = q[o];
        float sp = (qv - m) * rs * (1.f + gam[o]) + bet[o];
        float tv = outat[o] + (1.f - cf) * sp + qv;
        s += tv; ss += tv * tv;
    }
    ps[cp][nn] = s; pss[cp][nn] = ss;
    __syncthreads();
    if (tid < 64) {
        float S = ps[0][tid]+ps[1][tid]+ps[2][tid]+ps[3][tid];
        float SS = pss[0][tid]+pss[1][tid]+pss[2][tid]+pss[3][tid];
        float m = S * (1.f/256.f), v = SS * (1.f/256.f) - m * m;
        pm[tid] = m; pr[tid] = rsqrtf(v + 1e-5f);
    }
    __syncthreads();
    float mmu = pm[nn], rr = pr[nn];
    for (int base = 0; base < CV_; base += 4) {
        int cc = base + cp;
        size_t o = ((size_t)b * CV_ + cc) * NPIX_ + n0 + nn;
        float m = innm[(b*CV_+cc)*2], rs = innm[(b*CV_+cc)*2+1];
        float qv = q[o];
        float sp = (qv - m) * rs * (1.f + gam[o]) + bet[o];
        float tv = outat[o] + (1.f - cf) * sp + qv;
        y[o] = (tv - mmu) * rr;
    }
}

extern "C" void kernel_launch(void* const* d_in, const int* in_sizes, int n_in,
                              void* d_out, int out_size) {
    const float *q = (const float*)d_in[0], *k = (const float*)d_in[1],
                *v = (const float*)d_in[2], *pos = (const float*)d_in[3],
                *seg = (const float*)d_in[4], *v2 = (const float*)d_in[5],
                *f_w = (const float*)d_in[6], *f_b = (const float*)d_in[7],
                *g_w = (const float*)d_in[8], *g_b = (const float*)d_in[9],
                *h_w = (const float*)d_in[10], *h_b = (const float*)d_in[11],
                *fp_w = (const float*)d_in[12], *fp_b = (const float*)d_in[13],
                *gp_w = (const float*)d_in[14], *gp_b = (const float*)d_in[15],
                *sp_s_w = (const float*)d_in[16], *sp_s_b = (const float*)d_in[17],
                *sp_g_w = (const float*)d_in[18], *sp_g_b = (const float*)d_in[19],
                *sp_b_w = (const float*)d_in[20], *sp_b_b = (const float*)d_in[21],
                *r1_w = (const float*)d_in[22], *r1_b = (const float*)d_in[23],
                *r2_w = (const float*)d_in[24], *r2_b = (const float*)d_in[25];
    float* S;
    cudaGetSymbolAddress((void**)&S, g_scratch);
    float* out_res  = (float*)d_out;
    float* out_out2 = out_res + 2097152;
    float* out_cor  = out_res + 4194304;
    unsigned char* mask = (unsigned char*)(S + OFF_MASK);
    static int smem_set = 0;
    if (!smem_set) {
        cudaFuncSetAttribute(k_conv3, cudaFuncAttributeMaxDynamicSharedMemorySize, 80128);
        smem_set = 1;
    }

    k_normcat<<<128, 256>>>(q, pos, S + OFF_QUERY);
    k_normcat<<<128, 256>>>(k, pos, S + OFF_KEYT);
    k_transpose<<<dim3(8,128,2), dim3(32,8)>>>(v,  S + OFF_VT);
    k_transpose<<<dim3(8,128,2), dim3(32,8)>>>(v2, S + OFF_V2T);
    k_gemm<<<dim3(5,128), 256>>>(S + OFF_QUERY, f_w,  f_b,  S + OFF_QF, CQK_, CQK_);
    k_gemm<<<dim3(5,128), 256>>>(S + OFF_KEYT,  g_w,  g_b,  S + OFF_KF, CQK_, CQK_);
    k_gemm<<<dim3(1,128), 256>>>(S + OFF_QUERY, fp_w, fp_b, S + OFF_QP, CQK_, DP_);
    k_gemm<<<dim3(1,128), 256>>>(S + OFF_KEYT,  gp_w, gp_b, S + OFF_KP, CQK_, DP_);
    k_gemm<<<dim3(4,128), 256>>>(S + OFF_VT,    h_w,  h_b,  S + OFF_VH, CV_,  CV_);
    k_cor2<<<dim3(32,32,2), 256>>>(S + OFF_QF, S + OFF_KF, out_cor);
    k_mask<<<dim3(32,32,2), 256>>>(S + OFF_QP, S + OFF_KP, mask);
    k_rowstats<<<8192, 256>>>(out_cor, mask, S + OFF_STATS, S + OFF_CONF);
    k_av<<<dim3(4,32,2), 256>>>(out_cor, mask, S + OFF_STATS, S + OFF_VH,
                                S + OFF_V2T, S + OFF_OUT, out_out2);
    k_conv3<<<dim3(1,64,2), 256, 80128>>>(seg, sp_s_w, sp_s_b, S + OFF_ACTV, 3, 128, 1, nullptr);
    k_conv3<<<dim3(2,64,2), 256, 80128>>>(S + OFF_ACTV, sp_g_w, sp_g_b, S + OFF_GAMMA, 128, 256, 0, nullptr);
    k_conv3<<<dim3(2,64,2), 256, 80128>>>(S + OFF_ACTV, sp_b_w, sp_b_b, S + OFF_BETA,  128, 256, 0, nullptr);
    k_instnorm<<<512, 256>>>(q, S + OFF_INNM);
    k_spade_pono<<<128, 256>>>(q, S + OFF_GAMMA, S + OFF_BETA, S + OFF_OUT,
                               S + OFF_CONF, S + OFF_INNM, S + OFF_Y);
    k_conv3<<<dim3(2,64,2), 256, 80128>>>(S + OFF_Y,  r1_w, r1_b, S + OFF_T1, 256, 256, 1, nullptr);
    k_conv3<<<dim3(2,64,2), 256, 80128>>>(S + OFF_T1, r2_w, r2_b, out_res,    256, 256, 2, S + OFF_Y);
}

// round 8
// speedup vs baseline: 2.0624x; 1.0018x over previous
#include <cuda_runtime.h>
#include <cuda_bf16.h>
#include <math.h>

#define CV_   256
#define CQK_  320
#define DP_   64
#define NPIX_ 4096

#define OFF_QUERY  0u
#define OFF_KEYT   (OFF_QUERY + 2621440u)
#define OFF_QF     (OFF_KEYT  + 2621440u)
#define OFF_KF     (OFF_QF    + 2621440u)
#define OFF_QP     (OFF_KF    + 2621440u)
#define OFF_KP     (OFF_QP    + 524288u)
#define OFF_VH     (OFF_KP    + 524288u)
#define OFF_STATS  (OFF_VH    + 2097152u)
#define OFF_CONF   (OFF_STATS + 32768u)
#define OFF_OUT    (OFF_CONF  + 8192u)
#define OFF_ACTV   (OFF_OUT   + 2097152u)
#define OFF_GAMMA  (OFF_ACTV  + 1048576u)
#define OFF_BETA   (OFF_GAMMA + 2097152u)
#define OFF_Y      (OFF_BETA  + 2097152u)
#define OFF_T1     (OFF_Y     + 2097152u)
#define OFF_INNM   (OFF_T1    + 2097152u)
#define OFF_MASK   (OFF_INNM  + 1024u)
#define OFF_VHI    (OFF_MASK  + 8388608u)
#define OFF_VLO    (OFF_VHI   + 1048576u)
#define OFF_V2HI   (OFF_VLO   + 1048576u)
#define OFF_V2LO   (OFF_V2HI  + 1048576u)
#define SCRATCH_FLOATS (OFF_V2LO + 1048576u)

__device__ float g_scratch[SCRATCH_FLOATS];

typedef unsigned long long ull;
__device__ __forceinline__ ull pk2(float lo, float hi) {
    ull r; asm("mov.b64 %0,{%1,%2};" : "=l"(r) : "f"(lo), "f"(hi)); return r;
}
__device__ __forceinline__ void fma2(ull& d, ull a, ull b) {
    asm("fma.rn.f32x2 %0,%1,%2,%0;" : "+l"(d) : "l"(a), "l"(b));
}
__device__ __forceinline__ float2 up2(ull v) {
    float2 f; asm("mov.b64 {%0,%1},%2;" : "=f"(f.x), "=f"(f.y) : "l"(v)); return f;
}
__device__ __forceinline__ unsigned bfp(float a, float b) {
    __nv_bfloat162 t = __floats2bfloat162_rn(a, b); return *(unsigned*)&t;
}
__device__ __forceinline__ void mma16816(float* c, const unsigned* a, unsigned b0, unsigned b1) {
    asm volatile("mma.sync.aligned.m16n8k16.row.col.f32.bf16.bf16.f32 "
        "{%0,%1,%2,%3},{%4,%5,%6,%7},{%8,%9},{%0,%1,%2,%3};"
        : "+f"(c[0]), "+f"(c[1]), "+f"(c[2]), "+f"(c[3])
        : "r"(a[0]), "r"(a[1]), "r"(a[2]), "r"(a[3]), "r"(b0), "r"(b1));
}

__global__ void k_normcat(const float* __restrict__ src, const float* __restrict__ pos,
                          float* __restrict__ dst) {
    int b = blockIdx.x >> 6, n0 = (blockIdx.x & 63) << 6, tid = threadIdx.x;
    __shared__ float red[4][64], rnorm[64];
    int nn = tid & 63, cp = tid >> 6;
    const float* sp = src + (size_t)b * CV_ * NPIX_ + n0 + nn;
    float acc = 0.f;
    for (int c = cp; c < CV_; c += 4) { float x = sp[(size_t)c * NPIX_]; acc += x * x; }
    red[cp][nn] = acc;
    __syncthreads();
    if (tid < 64) {
        float s = red[0][tid] + red[1][tid] + red[2][tid] + red[3][tid];
        rnorm[tid] = 1.f / (sqrtf(s) + 2.220446049250313e-16f);
    }
    __syncthreads();
    for (int i = 0; i < 80; i++) {
        int idx = i * 256 + tid, n = idx / CQK_, c = idx - n * CQK_;
        float v = (c < CV_) ? src[(size_t)(b * CV_ + c) * NPIX_ + n0 + n] * rnorm[n]
                            : pos[(size_t)(c - CV_) * NPIX_ + n0 + n];
        dst[((size_t)b * NPIX_ + n0 + n) * CQK_ + c] = v;
    }
}

__global__ void k_gemm(const float* __restrict__ A, const float* __restrict__ W,
                       const float* __restrict__ bias, float* __restrict__ C, int K, int O) {
    __shared__ float As[16][64], Ws[16][64];
    int p0 = blockIdx.y << 6, o0 = blockIdx.x << 6, tid = threadIdx.x;
    int tx4 = (tid & 15) * 4, ty4 = (tid >> 4) * 4;
    ull acc[4][2];
    #pragma unroll
    for (int i = 0; i < 4; i++) { acc[i][0] = 0ull; acc[i][1] = 0ull; }
    for (int k0 = 0; k0 < K; k0 += 16) {
        #pragma unroll
        for (int i = 0; i < 4; i++) {
            int idx = i * 256 + tid, pp = idx >> 4, kk = idx & 15;
            As[kk][pp] = A[(size_t)(p0 + pp) * K + k0 + kk];
            Ws[kk][pp] = W[(size_t)(o0 + pp) * K + k0 + kk];
        }
        __syncthreads();
        #pragma unroll
        for (int kk = 0; kk < 16; kk++) {
            float4 a = *(const float4*)&As[kk][ty4];
            ull b0 = *(const ull*)&Ws[kk][tx4];
            ull b1 = *(const ull*)&Ws[kk][tx4 + 2];
            float av[4] = {a.x, a.y, a.z, a.w};
            #pragma unroll
            for (int ii = 0; ii < 4; ii++) {
                ull pa = pk2(av[ii], av[ii]);
                fma2(acc[ii][0], pa, b0);
                fma2(acc[ii][1], pa, b1);
            }
        }
        __syncthreads();
    }
    for (int ii = 0; ii < 4; ii++) {
        float2 q0 = up2(acc[ii][0]), q1 = up2(acc[ii][1]);
        float4 r;
        r.x = q0.x + bias[o0+tx4+0]; r.y = q0.y + bias[o0+tx4+1];
        r.z = q1.x + bias[o0+tx4+2]; r.w = q1.y + bias[o0+tx4+3];
        *(float4*)&C[(size_t)(p0 + ty4 + ii) * O + o0 + tx4] = r;
    }
}

// C[b][o][p] = sum_k W[o][k]*A[b][k][p] + bias[o]
__global__ void k_gemmW(const float* __restrict__ A, const float* __restrict__ W,
                        const float* __restrict__ bias, float* __restrict__ C) {
    __shared__ float As[16][64], Ws[16][64];
    int b = blockIdx.z, o0 = blockIdx.x << 6, p0 = blockIdx.y << 6, tid = threadIdx.x;
    int tx4 = (tid & 15) * 4, ty4 = (tid >> 4) * 4;
    ull acc[4][2];
    #pragma unroll
    for (int i = 0; i < 4; i++) { acc[i][0] = 0ull; acc[i][1] = 0ull; }
    for (int k0 = 0; k0 < 256; k0 += 16) {
        #pragma unroll
        for (int i = 0; i < 4; i++) {
            int idx = i * 256 + tid;
            int kk = idx >> 6, pp = idx & 63;
            As[kk][pp] = A[((size_t)b * 256 + k0 + kk) * NPIX_ + p0 + pp];
            int oo = idx >> 4, k2 = idx & 15;
            Ws[k2][oo] = W[(size_t)(o0 + oo) * 256 + k0 + k2];
        }
        __syncthreads();
        #pragma unroll
        for (int kk = 0; kk < 16; kk++) {
            float4 w = *(const float4*)&Ws[kk][ty4];
            ull a0 = *(const ull*)&As[kk][tx4], a1 = *(const ull*)&As[kk][tx4 + 2];
            float wv[4] = {w.x, w.y, w.z, w.w};
            #pragma unroll
            for (int oi = 0; oi < 4; oi++) {
                ull pw = pk2(wv[oi], wv[oi]);
                fma2(acc[oi][0], pw, a0);
                fma2(acc[oi][1], pw, a1);
            }
        }
        __syncthreads();
    }
    for (int oi = 0; oi < 4; oi++) {
        float bv = bias[o0 + ty4 + oi];
        float2 q0 = up2(acc[oi][0]), q1 = up2(acc[oi][1]);
        float4 r = {q0.x + bv, q0.y + bv, q1.x + bv, q1.y + bv};
        *(float4*)&C[((size_t)b * 256 + o0 + ty4 + oi) * NPIX_ + p0 + tx4] = r;
    }
}

__global__ void k_split(const float* __restrict__ x, __nv_bfloat16* __restrict__ hi,
                        __nv_bfloat16* __restrict__ lo) {
    int i = blockIdx.x * 256 + threadIdx.x;
    float v = x[i];
    __nv_bfloat16 h = __float2bfloat16(v);
    hi[i] = h;
    lo[i] = __float2bfloat16(v - __bfloat162float(h));
}

__global__ void k_cor2(const float* __restrict__ Qf, const float* __restrict__ Kf,
                       float* __restrict__ cor) {
    __shared__ float As[8][132], Bs[8][132];
    int b = blockIdx.z, n0 = blockIdx.y << 7, m0 = blockIdx.x << 7;
    int tid = threadIdx.x, tx = tid & 15, ty = tid >> 4;
    int r = tid >> 1, kq = (tid & 1) << 2;
    const float* A  = Qf + (size_t)(b * NPIX_ + n0) * CQK_;
    const float* Bk = Kf + (size_t)(b * NPIX_ + m0) * CQK_;
    ull acc[8][4];
    #pragma unroll
    for (int i = 0; i < 8; i++)
        #pragma unroll
        for (int j = 0; j < 4; j++) acc[i][j] = 0ull;
    for (int k0 = 0; k0 < CQK_; k0 += 8) {
        float4 av = *(const float4*)&A [(size_t)r * CQK_ + k0 + kq];
        float4 bv = *(const float4*)&Bk[(size_t)r * CQK_ + k0 + kq];
        As[kq+0][r] = av.x; As[kq+1][r] = av.y; As[kq+2][r] = av.z; As[kq+3][r] = av.w;
        Bs[kq+0][r] = bv.x; Bs[kq+1][r] = bv.y; Bs[kq+2][r] = bv.z; Bs[kq+3][r] = bv.w;
        __syncthreads();
        #pragma unroll
        for (int kk = 0; kk < 8; kk++) {
            float4 a0 = *(const float4*)&As[kk][ty << 3];
            float4 a1 = *(const float4*)&As[kk][(ty << 3) + 4];
            ull bb[4];
            #pragma unroll
            for (int j = 0; j < 4; j++) bb[j] = *(const ull*)&Bs[kk][(tx << 3) + 2*j];
            float aa[8] = {a0.x,a0.y,a0.z,a0.w,a1.x,a1.y,a1.z,a1.w};
            #pragma unroll
            for (int i = 0; i < 8; i++) {
                ull pa = pk2(aa[i], aa[i]);
                #pragma unroll
                for (int j = 0; j < 4; j++) fma2(acc[i][j], pa, bb[j]);
            }
        }
        __syncthreads();
    }
    const float s = 0.05590169943749474f;
    #pragma unroll
    for (int i = 0; i < 8; i++) {
        int n = n0 + (ty << 3) + i;
        float2 p0 = up2(acc[i][0]), p1 = up2(acc[i][1]), p2 = up2(acc[i][2]), p3 = up2(acc[i][3]);
        float4 w0 = {p0.x*s, p0.y*s, p1.x*s, p1.y*s};
        float4 w1 = {p2.x*s, p2.y*s, p3.x*s, p3.y*s};
        float* dst = &cor[((size_t)b * NPIX_ + n) * NPIX_ + m0 + (tx << 3)];
        *(float4*)dst = w0; *(float4*)(dst + 4) = w1;
    }
}

__global__ void k_mask(const float* __restrict__ Qp, const float* __restrict__ Kp,
                       unsigned char* __restrict__ mask) {
    __shared__ float As[8][132], Bs[8][132];
    int b = blockIdx.z, n0 = blockIdx.y << 7, m0 = blockIdx.x << 7;
    int tid = threadIdx.x, tx = tid & 15, ty = tid >> 4;
    int r = tid >> 1, kq = (tid & 1) << 2;
    const float* A  = Qp + (size_t)(b * NPIX_ + n0) * DP_;
    const float* Bk = Kp + (size_t)(b * NPIX_ + m0) * DP_;
    ull acc[8][4];
    #pragma unroll
    for (int i = 0; i < 8; i++)
        #pragma unroll
        for (int j = 0; j < 4; j++) acc[i][j] = 0ull;
    for (int k0 = 0; k0 < DP_; k0 += 8) {
        float4 av = *(const float4*)&A [(size_t)r * DP_ + k0 + kq];
        float4 bv = *(const float4*)&Bk[(size_t)r * DP_ + k0 + kq];
        As[kq+0][r] = av.x; As[kq+1][r] = av.y; As[kq+2][r] = av.z; As[kq+3][r] = av.w;
        Bs[kq+0][r] = bv.x; Bs[kq+1][r] = bv.y; Bs[kq+2][r] = bv.z; Bs[kq+3][r] = bv.w;
        __syncthreads();
        #pragma unroll
        for (int kk = 0; kk < 8; kk++) {
            float4 a0 = *(const float4*)&As[kk][ty << 3];
            float4 a1 = *(const float4*)&As[kk][(ty << 3) + 4];
            ull bb[4];
            #pragma unroll
            for (int j = 0; j < 4; j++) bb[j] = *(const ull*)&Bs[kk][(tx << 3) + 2*j];
            float aa[8] = {a0.x,a0.y,a0.z,a0.w,a1.x,a1.y,a1.z,a1.w};
            #pragma unroll
            for (int i = 0; i < 8; i++) {
                ull pa = pk2(aa[i], aa[i]);
                #pragma unroll
                for (int j = 0; j < 4; j++) fma2(acc[i][j], pa, bb[j]);
            }
        }
        __syncthreads();
    }
    #pragma unroll
    for (int i = 0; i < 8; i++) {
        int n = n0 + (ty << 3) + i;
        float2 p0 = up2(acc[i][0]), p1 = up2(acc[i][1]), p2 = up2(acc[i][2]), p3 = up2(acc[i][3]);
        unsigned lo = (p0.x>0.f?1u:0u) | ((p0.y>0.f?1u:0u)<<8) | ((p1.x>0.f?1u:0u)<<16) | ((p1.y>0.f?1u:0u)<<24);
        unsigned hi = (p2.x>0.f?1u:0u) | ((p2.y>0.f?1u:0u)<<8) | ((p3.x>0.f?1u:0u)<<16) | ((p3.y>0.f?1u:0u)<<24);
        unsigned char* dst = &mask[((size_t)b * NPIX_ + n) * NPIX_ + m0 + (tx << 3)];
        *(unsigned*)dst = lo; *(unsigned*)(dst + 4) = hi;
    }
}

__global__ void k_rowstats(const float* __restrict__ cor, const unsigned char* __restrict__ mask,
                           float* __restrict__ stats, float* __restrict__ conf) {
    int row = blockIdx.x, tid = threadIdx.x;
    const float* r = cor + (size_t)row * NPIX_;
    const unsigned char* mk = mask + (size_t)row * NPIX_;
    __shared__ float sa[256], sb[256], sc[256];
    float mx1 = -3.0e38f, mx2 = -3.0e38f;
    for (int m = tid; m < NPIX_; m += 256) {
        float x = r[m];
        mx1 = fmaxf(mx1, x);
        mx2 = fmaxf(mx2, mk[m] ? -10000.f : x);
    }
    sa[tid] = mx1; sb[tid] = mx2;
    __syncthreads();
    for (int s = 128; s > 0; s >>= 1) {
        if (tid < s) { sa[tid] = fmaxf(sa[tid], sa[tid+s]); sb[tid] = fmaxf(sb[tid], sb[tid+s]); }
        __syncthreads();
    }
    mx1 = sa[0]; mx2 = sb[0];
    __syncthreads();
    float s1 = 0.f, sm = 0.f, s2 = 0.f;
    for (int m = tid; m < NPIX_; m += 256) {
        float x = r[m], mv = mk[m] ? 1.f : 0.f;
        float e1 = __expf(x - mx1);
        s1 += e1; sm += mv * e1;
        s2 += __expf((mv > 0.f ? -10000.f : x) - mx2);
    }
    sa[tid] = s1; sb[tid] = sm; sc[tid] = s2;
    __syncthreads();
    for (int s = 128; s > 0; s >>= 1) {
        if (tid < s) { sa[tid] += sa[tid+s]; sb[tid] += sb[tid+s]; sc[tid] += sc[tid+s]; }
        __syncthreads();
    }
    if (tid == 0) {
        stats[row*4+0] = mx1; stats[row*4+1] = 1.f / sa[0];
        stats[row*4+2] = mx2; stats[row*4+3] = 1.f / sc[0];
        conf[row] = sb[0] / sa[0];
    }
}

// HMMA: O[b][c0..c0+127][n0..n0+127] += softmax-weights x V (bf16 hi/lo split)
__global__ __launch_bounds__(256) void k_av_mma(
    const float* __restrict__ cor, const unsigned char* __restrict__ mask,
    const float* __restrict__ stats, const __nv_bfloat16* __restrict__ vhi,
    const __nv_bfloat16* __restrict__ vlo, float* __restrict__ O, int g) {
    extern __shared__ __nv_bfloat16 sm[];
    __nv_bfloat16* Ah = sm;            // [128][72]
    __nv_bfloat16* Al = sm + 9216;
    __nv_bfloat16* Bh = sm + 18432;    // [128c][72k]
    __nv_bfloat16* Bl = sm + 27648;
    int tid = threadIdx.x, lane = tid & 31, w = tid >> 5;
    int wm = w & 3, wn = w >> 2;
    int gq = lane >> 2, tg = lane & 3;
    int b = blockIdx.z, n0 = blockIdx.x << 7, c0 = blockIdx.y << 7;
    int r = tid >> 1, ml0 = (tid & 1) << 5;
    float mx = stats[((size_t)b * NPIX_ + n0 + r) * 4 + g * 2];
    float iv = stats[((size_t)b * NPIX_ + n0 + r) * 4 + g * 2 + 1];
    const float* C = cor + ((size_t)(b * NPIX_ + n0) + r) * NPIX_;
    const unsigned char* M = mask + ((size_t)(b * NPIX_ + n0) + r) * NPIX_;
    int bc = tid & 127, bhh = tid >> 7;
    const __nv_bfloat16* BHsrc = vhi + ((size_t)b * CV_ + c0 + bc) * NPIX_ + bhh * 32;
    const __nv_bfloat16* BLsrc = vlo + ((size_t)b * CV_ + c0 + bc) * NPIX_ + bhh * 32;
    float acc[2][8][4];
    #pragma unroll
    for (int i = 0; i < 2; i++)
        #pragma unroll
        for (int j = 0; j < 8; j++)
            #pragma unroll
            for (int t = 0; t < 4; t++) acc[i][j][t] = 0.f;
    for (int ch = 0; ch < 64; ch++) {
        int m0 = ch << 6;
        #pragma unroll
        for (int j = 0; j < 16; j++) {
            float2 cv = *(const float2*)&C[m0 + ml0 + 2*j];
            unsigned char q0 = M[m0 + ml0 + 2*j], q1 = M[m0 + ml0 + 2*j + 1];
            float w0, w1;
            if (g == 0) {
                w0 = q0 ? __expf(cv.x - mx) * iv : 0.f;
                w1 = q1 ? __expf(cv.y - mx) * iv : 0.f;
            } else {
                w0 = __expf((q0 ? -10000.f : cv.x) - mx) * iv;
                w1 = __expf((q1 ? -10000.f : cv.y) - mx) * iv;
            }
            float h0 = __bfloat162float(__float2bfloat16(w0));
            float h1 = __bfloat162float(__float2bfloat16(w1));
            int off = r * 72 + ml0 + 2*j;
            *(unsigned*)&Ah[off] = bfp(w0, w1);
            *(unsigned*)&Al[off] = bfp(w0 - h0, w1 - h1);
        }
        {
            const uint4* sh = (const uint4*)(BHsrc + m0);
            const uint4* sl = (const uint4*)(BLsrc + m0);
            uint4* dh = (uint4*)&Bh[bc * 72 + bhh * 32];
            uint4* dl = (uint4*)&Bl[bc * 72 + bhh * 32];
            dh[0] = sh[0]; dh[1] = sh[1]; dh[2] = sh[2]; dh[3] = sh[3];
            dl[0] = sl[0]; dl[1] = sl[1]; dl[2] = sl[2]; dl[3] = sl[3];
        }
        __syncthreads();
        #pragma unroll
        for (int ks = 0; ks < 4; ks++) {
            int k16 = ks << 4;
            unsigned ah[2][4], al[2][4];
            #pragma unroll
            for (int mt = 0; mt < 2; mt++) {
                const __nv_bfloat16* pa = &Ah[(wm*32 + mt*16 + gq) * 72 + k16 + tg*2];
                ah[mt][0] = *(const unsigned*)pa;
                ah[mt][1] = *(const unsigned*)(pa + 8*72);
                ah[mt][2] = *(const unsigned*)(pa + 8);
                ah[mt][3] = *(const unsigned*)(pa + 8*72 + 8);
                const __nv_bfloat16* pl = &Al[(wm*32 + mt*16 + gq) * 72 + k16 + tg*2];
                al[mt][0] = *(const unsigned*)pl;
                al[mt][1] = *(const unsigned*)(pl + 8*72);
                al[mt][2] = *(const unsigned*)(pl + 8);
                al[mt][3] = *(const unsigned*)(pl + 8*72 + 8);
            }
            #pragma unroll
            for (int nt = 0; nt < 8; nt++) {
                const __nv_bfloat16* pb = &Bh[(wn*64 + nt*8 + gq) * 72 + k16 + tg*2];
                unsigned b0 = *(const unsigned*)pb;
                unsigned b1 = *(const unsigned*)(pb + 8);
                const __nv_bfloat16* pbl = &Bl[(wn*64 + nt*8 + gq) * 72 + k16 + tg*2];
                unsigned l0 = *(const unsigned*)pbl;
                unsigned l1 = *(const unsigned*)(pbl + 8);
                #pragma unroll
                for (int mt = 0; mt < 2; mt++) {
                    mma16816(acc[mt][nt], ah[mt], b0, b1);
                    mma16816(acc[mt][nt], ah[mt], l0, l1);
                    mma16816(acc[mt][nt], al[mt], b0, b1);
                }
            }
        }
        __syncthreads();
    }
    #pragma unroll
    for (int mt = 0; mt < 2; mt++) {
        int row = n0 + wm*32 + mt*16 + gq;
        #pragma unroll
        for (int nt = 0; nt < 8; nt++) {
            int col = c0 + wn*64 + nt*8 + tg*2;
            float* p0 = &O[((size_t)b * CV_ + col) * NPIX_ + row];
            float* p1 = p0 + NPIX_;
            p0[0] = acc[mt][nt][0]; p1[0] = acc[mt][nt][1];
            p0[8] = acc[mt][nt][2]; p1[8] = acc[mt][nt][3];
        }
    }
}

__global__ void k_conv3(const float* __restrict__ in, const float* __restrict__ wgt,
                        const float* __restrict__ bias, float* __restrict__ out,
                        int Cin, int Cout, int flags, const float* __restrict__ res) {
    extern __shared__ float smf[];
    float* ws  = smf;
    float* ins = smf + 18432;
    int b = blockIdx.z, t = blockIdx.y, oc0 = blockIdx.x << 7;
    int y0 = (t >> 3) << 3, x0 = (t & 7) << 3, tid = threadIdx.x;
    int tx = tid & 15, ty = tid >> 4;
    int pyb = tx >> 1, pxb = (tx & 1) << 2;
    ull acc[4][4];
    #pragma unroll
    for (int p = 0; p < 4; p++)
        #pragma unroll
        for (int j = 0; j < 4; j++) acc[p][j] = 0ull;
    for (int ic0 = 0; ic0 < Cin; ic0 += 16) {
        for (int i = tid; i < 1600; i += 256) {
            int icl = i / 100, rem = i - icl * 100, hy = rem / 10, hx = rem - hy * 10;
            int gy = y0 + hy - 1, gx = x0 + hx - 1, ic = ic0 + icl;
            float v = 0.f;
            if (ic < Cin && (unsigned)gy < 64u && (unsigned)gx < 64u)
                v = in[(((size_t)b * Cin + ic) * 64 + gy) * 64 + gx];
            ins[i] = v;
        }
        for (int i = tid; i < 18432; i += 256) {
            int oc = i & 127, kk = i >> 7, icl = kk / 9, tap = kk - icl * 9, ic = ic0 + icl;
            ws[i] = (ic < Cin) ? wgt[(((size_t)(oc0 + oc)) * Cin + ic) * 9 + tap] : 0.f;
        }
        __syncthreads();
        int icm = (Cin - ic0 < 16) ? (Cin - ic0) : 16;
        for (int icl = 0; icl < icm; icl++) {
            ull xb[3][6];
            const float* iw = &ins[icl * 100 + pyb * 10 + pxb];
            #pragma unroll
            for (int ky = 0; ky < 3; ky++)
                #pragma unroll
                for (int c = 0; c < 6; c++) {
                    float v = iw[ky * 10 + c];
                    xb[ky][c] = pk2(v, v);
                }
            #pragma unroll
            for (int ky = 0; ky < 3; ky++)
                #pragma unroll
                for (int kx = 0; kx < 3; kx++) {
                    const float* wp = &ws[(icl * 9 + ky * 3 + kx) * 128 + (ty << 3)];
                    ull w0 = *(const ull*)wp, w1 = *(const ull*)(wp + 2);
                    ull w2 = *(const ull*)(wp + 4), w3 = *(const ull*)(wp + 6);
                    #pragma unroll
                    for (int p = 0; p < 4; p++) {
                        ull xq = xb[ky][kx + p];
                        fma2(acc[p][0], xq, w0); fma2(acc[p][1], xq, w1);
                        fma2(acc[p][2], xq, w2); fma2(acc[p][3], xq, w3);
                    }
                }
        }
        __syncthreads();
    }
    #pragma unroll
    for (int j = 0; j < 4; j++) {
        int ocA = oc0 + (ty << 3) + 2 * j;
        float bA = bias[ocA], bB = bias[ocA + 1];
        size_t rowA = (((size_t)b * Cout + ocA) * 64 + y0 + pyb) * 64 + x0 + pxb;
        size_t rowB = rowA + 4096;
        #pragma unroll
        for (int p = 0; p < 4; p++) {
            float2 vpair = up2(acc[p][j]);
            float va = vpair.x + bA, vb = vpair.y + bB;
            if (flags & 1) { va = fmaxf(va, 0.f); vb = fmaxf(vb, 0.f); }
            if (flags & 2) { va += res[rowA + p]; vb += res[rowB + p]; }
            out[rowA + p] = va;
            out[rowB + p] = vb;
        }
    }
}

__global__ void k_instnorm(const float* __restrict__ x, float* __restrict__ st) {
    int row = blockIdx.x, tid = threadIdx.x;
    const float* p = x + (size_t)row * NPIX_;
    float s = 0.f, ss = 0.f;
    for (int i = tid; i < NPIX_; i += 256) { float v = p[i]; s += v; ss += v * v; }
    __shared__ float r1[256], r2[256];
    r1[tid] = s; r2[tid] = ss;
    __syncthreads();
    for (int k = 128; k > 0; k >>= 1) {
        if (tid < k) { r1[tid] += r1[tid+k]; r2[tid] += r2[tid+k]; }
        __syncthreads();
    }
    if (tid == 0) {
        float m = r1[0] * (1.f / NPIX_);
        float v = r2[0] * (1.f / NPIX_) - m * m;
        st[row*2] = m; st[row*2+1] = rsqrtf(v + 1e-5f);
    }
}

__global__ void k_spade_pono(const float* __restrict__ q, const float* __restrict__ gam,
                             const float* __restrict__ bet, const float* __restrict__ outat,
                             const float* __restrict__ conf, const float* __restrict__ innm,
                             float* __restrict__ y) {
    int b = blockIdx.x >> 6, n0 = (blockIdx.x & 63) << 6, tid = threadIdx.x;
    int nn = tid & 63, cp = tid >> 6;
    __shared__ float ps[4][64], pss[4][64], pm[64], pr[64];
    float cf = conf[(size_t)b * NPIX_ + n0 + nn];
    float s = 0.f, ss = 0.f;
    for (int base = 0; base < CV_; base += 4) {
        int cc = base + cp;
        size_t o = ((size_t)b * CV_ + cc) * NPIX_ + n0 + nn;
        float m = innm[(b*CV_+cc)*2], rs = innm[(b*CV_+cc)*2+1];
        float qv = q[o];
        float sp = (qv - m) * rs * (1.f + gam[o]) + bet[o];
        float tv = outat[o] + (1.f - cf) * sp + qv;
        s += tv; ss += tv * tv;
    }
    ps[cp][nn] = s; pss[cp][nn] = ss;
    __syncthreads();
    if (tid < 64) {
        float S = ps[0][tid]+ps[1][tid]+ps[2][tid]+ps[3][tid];
        float SS = pss[0][tid]+pss[1][tid]+pss[2][tid]+pss[3][tid];
        float m = S * (1.f/256.f), v = SS * (1.f/256.f) - m * m;
        pm[tid] = m; pr[tid] = rsqrtf(v + 1e-5f);
    }
    __syncthreads();
    float mmu = pm[nn], rr = pr[nn];
    for (int base = 0; base < CV_; base += 4) {
        int cc = base + cp;
        size_t o = ((size_t)b * CV_ + cc) * NPIX_ + n0 + nn;
        float m = innm[(b*CV_+cc)*2], rs = innm[(b*CV_+cc)*2+1];
        float qv = q[o];
        float sp = (qv - m) * rs * (1.f + gam[o]) + bet[o];
        float tv = outat[o] + (1.f - cf) * sp + qv;
        y[o] = (tv - mmu) * rr;
    }
}

extern "C" void kernel_launch(void* const* d_in, const int* in_sizes, int n_in,
                              void* d_out, int out_size) {
    const float *q = (const float*)d_in[0], *k = (const float*)d_in[1],
                *v = (const float*)d_in[2], *pos = (const float*)d_in[3],
                *seg = (const float*)d_in[4], *v2 = (const float*)d_in[5],
                *f_w = (const float*)d_in[6], *f_b = (const float*)d_in[7],
                *g_w = (const float*)d_in[8], *g_b = (const float*)d_in[9],
                *h_w = (const float*)d_in[10], *h_b = (const float*)d_in[11],
                *fp_w = (const float*)d_in[12], *fp_b = (const float*)d_in[13],
                *gp_w = (const float*)d_in[14], *gp_b = (const float*)d_in[15],
                *sp_s_w = (const float*)d_in[16], *sp_s_b = (const float*)d_in[17],
                *sp_g_w = (const float*)d_in[18], *sp_g_b = (const float*)d_in[19],
                *sp_b_w = (const float*)d_in[20], *sp_b_b = (const float*)d_in[21],
                *r1_w = (const float*)d_in[22], *r1_b = (const float*)d_in[23],
                *r2_w = (const float*)d_in[24], *r2_b = (const float*)d_in[25];
    float* S;
    cudaGetSymbolAddress((void**)&S, g_scratch);
    float* out_res  = (float*)d_out;
    float* out_out2 = out_res + 2097152;
    float* out_cor  = out_res + 4194304;
    unsigned char* mask = (unsigned char*)(S + OFF_MASK);
    __nv_bfloat16* VHI  = (__nv_bfloat16*)(S + OFF_VHI);
    __nv_bfloat16* VLO  = (__nv_bfloat16*)(S + OFF_VLO);
    __nv_bfloat16* V2HI = (__nv_bfloat16*)(S + OFF_V2HI);
    __nv_bfloat16* V2LO = (__nv_bfloat16*)(S + OFF_V2LO);
    cudaFuncSetAttribute(k_conv3, cudaFuncAttributeMaxDynamicSharedMemorySize, 80128);
    cudaFuncSetAttribute(k_av_mma, cudaFuncAttributeMaxDynamicSharedMemorySize, 73728);

    k_normcat<<<128, 256>>>(q, pos, S + OFF_QUERY);
    k_normcat<<<128, 256>>>(k, pos, S + OFF_KEYT);
    k_gemm<<<dim3(5,128), 256>>>(S + OFF_QUERY, f_w,  f_b,  S + OFF_QF, CQK_, CQK_);
    k_gemm<<<dim3(5,128), 256>>>(S + OFF_KEYT,  g_w,  g_b,  S + OFF_KF, CQK_, CQK_);
    k_gemm<<<dim3(1,128), 256>>>(S + OFF_QUERY, fp_w, fp_b, S + OFF_QP, CQK_, DP_);
    k_gemm<<<dim3(1,128), 256>>>(S + OFF_KEYT,  gp_w, gp_b, S + OFF_KP, CQK_, DP_);
    k_gemmW<<<dim3(4,64,2), 256>>>(v, h_w, h_b, S + OFF_VH);
    k_split<<<8192, 256>>>(S + OFF_VH, VHI, VLO);
    k_split<<<8192, 256>>>(v2, V2HI, V2LO);
    k_cor2<<<dim3(32,32,2), 256>>>(S + OFF_QF, S + OFF_KF, out_cor);
    k_mask<<<dim3(32,32,2), 256>>>(S + OFF_QP, S + OFF_KP, mask);
    k_rowstats<<<8192, 256>>>(out_cor, mask, S + OFF_STATS, S + OFF_CONF);
    k_av_mma<<<dim3(32,2,2), 256, 73728>>>(out_cor, mask, S + OFF_STATS, VHI, VLO, S + OFF_OUT, 0);
    k_av_mma<<<dim3(32,2,2), 256, 73728>>>(out_cor, mask, S + OFF_STATS, V2HI, V2LO, out_out2, 1);
    k_conv3<<<dim3(1,64,2), 256, 80128>>>(seg, sp_s_w, sp_s_b, S + OFF_ACTV, 3, 128, 1, nullptr);
    k_conv3<<<dim3(2,64,2), 256, 80128>>>(S + OFF_ACTV, sp_g_w, sp_g_b, S + OFF_GAMMA, 128, 256, 0, nullptr);
    k_conv3<<<dim3(2,64,2), 256, 80128>>>(S + OFF_ACTV, sp_b_w, sp_b_b, S + OFF_BETA,  128, 256, 0, nullptr);
    k_instnorm<<<512, 256>>>(q, S + OFF_INNM);
    k_spade_pono<<<128, 256>>>(q, S + OFF_GAMMA, S + OFF_BETA, S + OFF_OUT,
                               S + OFF_CONF, S + OFF_INNM, S + OFF_Y);
    k_conv3<<<dim3(2,64,2), 256, 80128>>>(S + OFF_Y,  r1_w, r1_b, S + OFF_T1, 256, 256, 1, nullptr);
    k_conv3<<<dim3(2,64,2), 256, 80128>>>(S + OFF_T1, r2_w, r2_b, out_res,    256, 256, 2, S + OFF_Y);
}

// round 10
// speedup vs baseline: 2.2066x; 1.0699x over previous
#include <cuda_runtime.h>
#include <cuda_bf16.h>
#include <math.h>

#define CV_   256
#define CQK_  320
#define DP_   64
#define NPIX_ 4096

#define OFF_QUERY  0u
#define OFF_KEYT   (OFF_QUERY + 2621440u)
#define OFF_QF     (OFF_KEYT  + 2621440u)
#define OFF_KF     (OFF_QF    + 2621440u)
#define OFF_QP     (OFF_KF    + 2621440u)
#define OFF_KP     (OFF_QP    + 524288u)
#define OFF_VH     (OFF_KP    + 524288u)
#define OFF_STATS  (OFF_VH    + 2097152u)
#define OFF_CONF   (OFF_STATS + 32768u)
#define OFF_OUT    (OFF_CONF  + 8192u)
#define OFF_ACTV   (OFF_OUT   + 2097152u)
#define OFF_GAMMA  (OFF_ACTV  + 1048576u)
#define OFF_BETA   (OFF_GAMMA + 2097152u)
#define OFF_Y      (OFF_BETA  + 2097152u)
#define OFF_T1     (OFF_Y     + 2097152u)
#define OFF_INNM   (OFF_T1    + 2097152u)
#define OFF_MASK   (OFF_INNM  + 1024u)
#define OFF_VHI    (OFF_MASK  + 8388608u)
#define OFF_VLO    (OFF_VHI   + 1048576u)
#define OFF_V2HI   (OFF_VLO   + 1048576u)
#define OFF_V2LO   (OFF_V2HI  + 1048576u)
#define OFF_QFH    (OFF_V2LO  + 1048576u)
#define OFF_QFL    (OFF_QFH   + 1310720u)
#define OFF_KFH    (OFF_QFL   + 1310720u)
#define OFF_KFL    (OFF_KFH   + 1310720u)
#define SCRATCH_FLOATS (OFF_KFL + 1310720u)

__device__ float g_scratch[SCRATCH_FLOATS];

typedef unsigned long long ull;
__device__ __forceinline__ ull pk2(float lo, float hi) {
    ull r; asm("mov.b64 %0,{%1,%2};" : "=l"(r) : "f"(lo), "f"(hi)); return r;
}
__device__ __forceinline__ void fma2(ull& d, ull a, ull b) {
    asm("fma.rn.f32x2 %0,%1,%2,%0;" : "+l"(d) : "l"(a), "l"(b));
}
__device__ __forceinline__ float2 up2(ull v) {
    float2 f; asm("mov.b64 {%0,%1},%2;" : "=f"(f.x), "=f"(f.y) : "l"(v)); return f;
}
__device__ __forceinline__ unsigned bfp(float a, float b) {
    __nv_bfloat162 t = __floats2bfloat162_rn(a, b); return *(unsigned*)&t;
}
__device__ __forceinline__ void mma16816(float* c, const unsigned* a, unsigned b0, unsigned b1) {
    asm volatile("mma.sync.aligned.m16n8k16.row.col.f32.bf16.bf16.f32 "
        "{%0,%1,%2,%3},{%4,%5,%6,%7},{%8,%9},{%0,%1,%2,%3};"
        : "+f"(c[0]), "+f"(c[1]), "+f"(c[2]), "+f"(c[3])
        : "r"(a[0]), "r"(a[1]), "r"(a[2]), "r"(a[3]), "r"(b0), "r"(b1));
}

__global__ void k_normcat(const float* __restrict__ src, const float* __restrict__ pos,
                          float* __restrict__ dst) {
    int b = blockIdx.x >> 6, n0 = (blockIdx.x & 63) << 6, tid = threadIdx.x;
    __shared__ float red[4][64], rnorm[64];
    int nn = tid & 63, cp = tid >> 6;
    const float* sp = src + (size_t)b * CV_ * NPIX_ + n0 + nn;
    float acc = 0.f;
    for (int c = cp; c < CV_; c += 4) { float x = sp[(size_t)c * NPIX_]; acc += x * x; }
    red[cp][nn] = acc;
    __syncthreads();
    if (tid < 64) {
        float s = red[0][tid] + red[1][tid] + red[2][tid] + red[3][tid];
        rnorm[tid] = 1.f / (sqrtf(s) + 2.220446049250313e-16f);
    }
    __syncthreads();
    for (int i = 0; i < 80; i++) {
        int idx = i * 256 + tid, n = idx / CQK_, c = idx - n * CQK_;
        float v = (c < CV_) ? src[(size_t)(b * CV_ + c) * NPIX_ + n0 + n] * rnorm[n]
                            : pos[(size_t)(c - CV_) * NPIX_ + n0 + n];
        dst[((size_t)b * NPIX_ + n0 + n) * CQK_ + c] = v;
    }
}

__global__ void k_gemm(const float* __restrict__ A, const float* __restrict__ W,
                       const float* __restrict__ bias, float* __restrict__ C, int K, int O) {
    __shared__ float As[16][64], Ws[16][64];
    int p0 = blockIdx.y << 6, o0 = blockIdx.x << 6, tid = threadIdx.x;
    int tx4 = (tid & 15) * 4, ty4 = (tid >> 4) * 4;
    ull acc[4][2];
    #pragma unroll
    for (int i = 0; i < 4; i++) { acc[i][0] = 0ull; acc[i][1] = 0ull; }
    for (int k0 = 0; k0 < K; k0 += 16) {
        #pragma unroll
        for (int i = 0; i < 4; i++) {
            int idx = i * 256 + tid, pp = idx >> 4, kk = idx & 15;
            As[kk][pp] = A[(size_t)(p0 + pp) * K + k0 + kk];
            Ws[kk][pp] = W[(size_t)(o0 + pp) * K + k0 + kk];
        }
        __syncthreads();
        #pragma unroll
        for (int kk = 0; kk < 16; kk++) {
            float4 a = *(const float4*)&As[kk][ty4];
            ull b0 = *(const ull*)&Ws[kk][tx4];
            ull b1 = *(const ull*)&Ws[kk][tx4 + 2];
            float av[4] = {a.x, a.y, a.z, a.w};
            #pragma unroll
            for (int ii = 0; ii < 4; ii++) {
                ull pa = pk2(av[ii], av[ii]);
                fma2(acc[ii][0], pa, b0);
                fma2(acc[ii][1], pa, b1);
            }
        }
        __syncthreads();
    }
    for (int ii = 0; ii < 4; ii++) {
        float2 q0 = up2(acc[ii][0]), q1 = up2(acc[ii][1]);
        float4 r;
        r.x = q0.x + bias[o0+tx4+0]; r.y = q0.y + bias[o0+tx4+1];
        r.z = q1.x + bias[o0+tx4+2]; r.w = q1.y + bias[o0+tx4+3];
        *(float4*)&C[(size_t)(p0 + ty4 + ii) * O + o0 + tx4] = r;
    }
}

// C[b][o][p] = sum_k W[o][k]*A[b][k][p] + bias[o]
__global__ void k_gemmW(const float* __restrict__ A, const float* __restrict__ W,
                        const float* __restrict__ bias, float* __restrict__ C) {
    __shared__ float As[16][64], Ws[16][64];
    int b = blockIdx.z, o0 = blockIdx.x << 6, p0 = blockIdx.y << 6, tid = threadIdx.x;
    int tx4 = (tid & 15) * 4, ty4 = (tid >> 4) * 4;
    ull acc[4][2];
    #pragma unroll
    for (int i = 0; i < 4; i++) { acc[i][0] = 0ull; acc[i][1] = 0ull; }
    for (int k0 = 0; k0 < 256; k0 += 16) {
        #pragma unroll
        for (int i = 0; i < 4; i++) {
            int idx = i * 256 + tid;
            int kk = idx >> 6, pp = idx & 63;
            As[kk][pp] = A[((size_t)b * 256 + k0 + kk) * NPIX_ + p0 + pp];
            int oo = idx >> 4, k2 = idx & 15;
            Ws[k2][oo] = W[(size_t)(o0 + oo) * 256 + k0 + k2];
        }
        __syncthreads();
        #pragma unroll
        for (int kk = 0; kk < 16; kk++) {
            float4 w = *(const float4*)&Ws[kk][ty4];
            ull a0 = *(const ull*)&As[kk][tx4], a1 = *(const ull*)&As[kk][tx4 + 2];
            float wv[4] = {w.x, w.y, w.z, w.w};
            #pragma unroll
            for (int oi = 0; oi < 4; oi++) {
                ull pw = pk2(wv[oi], wv[oi]);
                fma2(acc[oi][0], pw, a0);
                fma2(acc[oi][1], pw, a1);
            }
        }
        __syncthreads();
    }
    for (int oi = 0; oi < 4; oi++) {
        float bv = bias[o0 + ty4 + oi];
        float2 q0 = up2(acc[oi][0]), q1 = up2(acc[oi][1]);
        float4 r = {q0.x + bv, q0.y + bv, q1.x + bv, q1.y + bv};
        *(float4*)&C[((size_t)b * 256 + o0 + ty4 + oi) * NPIX_ + p0 + tx4] = r;
    }
}

__global__ void k_split(const float* __restrict__ x, __nv_bfloat16* __restrict__ hi,
                        __nv_bfloat16* __restrict__ lo) {
    int i = blockIdx.x * 256 + threadIdx.x;
    float v = x[i];
    __nv_bfloat16 h = __float2bfloat16(v);
    hi[i] = h;
    lo[i] = __float2bfloat16(v - __bfloat162float(h));
}

// HMMA: cor[b][n0..+127][m0..+127] = (QfH+QfL)·(KfH+KfL)^T / sqrt(320)
__global__ __launch_bounds__(256) void k_cor_mma(
    const __nv_bfloat16* __restrict__ qh, const __nv_bfloat16* __restrict__ ql,
    const __nv_bfloat16* __restrict__ kh, const __nv_bfloat16* __restrict__ kl,
    float* __restrict__ cor) {
    extern __shared__ __nv_bfloat16 sm[];
    __nv_bfloat16* Ah = sm;            // [128][72]
    __nv_bfloat16* Al = sm + 9216;
    __nv_bfloat16* Bh = sm + 18432;
    __nv_bfloat16* Bl = sm + 27648;
    int tid = threadIdx.x, lane = tid & 31, w = tid >> 5;
    int wm = w & 3, wn = w >> 2;
    int gq = lane >> 2, tg = lane & 3;
    int b = blockIdx.z, n0 = blockIdx.x << 7, m0 = blockIdx.y << 7;
    int r = tid >> 1, hh = tid & 1;
    const __nv_bfloat16* A0 = qh + ((size_t)(b * NPIX_) + n0 + r) * CQK_ + hh * 32;
    const __nv_bfloat16* A1 = ql + ((size_t)(b * NPIX_) + n0 + r) * CQK_ + hh * 32;
    const __nv_bfloat16* B0 = kh + ((size_t)(b * NPIX_) + m0 + r) * CQK_ + hh * 32;
    const __nv_bfloat16* B1 = kl + ((size_t)(b * NPIX_) + m0 + r) * CQK_ + hh * 32;
    __nv_bfloat16* dA0 = &Ah[r * 72 + hh * 32];
    __nv_bfloat16* dA1 = &Al[r * 72 + hh * 32];
    __nv_bfloat16* dB0 = &Bh[r * 72 + hh * 32];
    __nv_bfloat16* dB1 = &Bl[r * 72 + hh * 32];
    float acc[2][8][4];
    #pragma unroll
    for (int i = 0; i < 2; i++)
        #pragma unroll
        for (int j = 0; j < 8; j++)
            #pragma unroll
            for (int t = 0; t < 4; t++) acc[i][j][t] = 0.f;
    for (int kc = 0; kc < CQK_; kc += 64) {
        {
            const uint4* s0 = (const uint4*)(A0 + kc);
            const uint4* s1 = (const uint4*)(A1 + kc);
            const uint4* s2 = (const uint4*)(B0 + kc);
            const uint4* s3 = (const uint4*)(B1 + kc);
            uint4* d0 = (uint4*)dA0; uint4* d1 = (uint4*)dA1;
            uint4* d2 = (uint4*)dB0; uint4* d3 = (uint4*)dB1;
            #pragma unroll
            for (int i = 0; i < 4; i++) {
                d0[i] = s0[i]; d1[i] = s1[i]; d2[i] = s2[i]; d3[i] = s3[i];
            }
        }
        __syncthreads();
        #pragma unroll
        for (int ks = 0; ks < 4; ks++) {
            int k16 = ks << 4;
            unsigned ah[2][4], al[2][4];
            #pragma unroll
            for (int mt = 0; mt < 2; mt++) {
                const __nv_bfloat16* pa = &Ah[(wm*32 + mt*16 + gq) * 72 + k16 + tg*2];
                ah[mt][0] = *(const unsigned*)pa;
                ah[mt][1] = *(const unsigned*)(pa + 8*72);
                ah[mt][2] = *(const unsigned*)(pa + 8);
                ah[mt][3] = *(const unsigned*)(pa + 8*72 + 8);
                const __nv_bfloat16* pl = &Al[(wm*32 + mt*16 + gq) * 72 + k16 + tg*2];
                al[mt][0] = *(const unsigned*)pl;
                al[mt][1] = *(const unsigned*)(pl + 8*72);
                al[mt][2] = *(const unsigned*)(pl + 8);
                al[mt][3] = *(const unsigned*)(pl + 8*72 + 8);
            }
            #pragma unroll
            for (int nt = 0; nt < 8; nt++) {
                const __nv_bfloat16* pb = &Bh[(wn*64 + nt*8 + gq) * 72 + k16 + tg*2];
                unsigned b0 = *(const unsigned*)pb;
                unsigned b1 = *(const unsigned*)(pb + 8);
                const __nv_bfloat16* pbl = &Bl[(wn*64 + nt*8 + gq) * 72 + k16 + tg*2];
                unsigned l0 = *(const unsigned*)pbl;
                unsigned l1 = *(const unsigned*)(pbl + 8);
                #pragma unroll
                for (int mt = 0; mt < 2; mt++) {
                    mma16816(acc[mt][nt], ah[mt], b0, b1);
                    mma16816(acc[mt][nt], ah[mt], l0, l1);
                    mma16816(acc[mt][nt], al[mt], b0, b1);
                }
            }
        }
        __syncthreads();
    }
    const float s = 0.05590169943749474f;
    #pragma unroll
    for (int mt = 0; mt < 2; mt++) {
        int row = n0 + wm*32 + mt*16 + gq;
        #pragma unroll
        for (int nt = 0; nt < 8; nt++) {
            int col = m0 + wn*64 + nt*8 + tg*2;
            float2 v0 = {acc[mt][nt][0]*s, acc[mt][nt][1]*s};
            float2 v1 = {acc[mt][nt][2]*s, acc[mt][nt][3]*s};
            *(float2*)&cor[((size_t)(b * NPIX_) + row) * NPIX_ + col] = v0;
            *(float2*)&cor[((size_t)(b * NPIX_) + row + 8) * NPIX_ + col] = v1;
        }
    }
}

__global__ void k_mask(const float* __restrict__ Qp, const float* __restrict__ Kp,
                       unsigned char* __restrict__ mask) {
    __shared__ float As[8][132], Bs[8][132];
    int b = blockIdx.z, n0 = blockIdx.y << 7, m0 = blockIdx.x << 7;
    int tid = threadIdx.x, tx = tid & 15, ty = tid >> 4;
    int r = tid >> 1, kq = (tid & 1) << 2;
    const float* A  = Qp + (size_t)(b * NPIX_ + n0) * DP_;
    const float* Bk = Kp + (size_t)(b * NPIX_ + m0) * DP_;
    ull acc[8][4];
    #pragma unroll
    for (int i = 0; i < 8; i++)
        #pragma unroll
        for (int j = 0; j < 4; j++) acc[i][j] = 0ull;
    for (int k0 = 0; k0 < DP_; k0 += 8) {
        float4 av = *(const float4*)&A [(size_t)r * DP_ + k0 + kq];
        float4 bv = *(const float4*)&Bk[(size_t)r * DP_ + k0 + kq];
        As[kq+0][r] = av.x; As[kq+1][r] = av.y; As[kq+2][r] = av.z; As[kq+3][r] = av.w;
        Bs[kq+0][r] = bv.x; Bs[kq+1][r] = bv.y; Bs[kq+2][r] = bv.z; Bs[kq+3][r] = bv.w;
        __syncthreads();
        #pragma unroll
        for (int kk = 0; kk < 8; kk++) {
            float4 a0 = *(const float4*)&As[kk][ty << 3];
            float4 a1 = *(const float4*)&As[kk][(ty << 3) + 4];
            ull bb[4];
            #pragma unroll
            for (int j = 0; j < 4; j++) bb[j] = *(const ull*)&Bs[kk][(tx << 3) + 2*j];
            float aa[8] = {a0.x,a0.y,a0.z,a0.w,a1.x,a1.y,a1.z,a1.w};
            #pragma unroll
            for (int i = 0; i < 8; i++) {
                ull pa = pk2(aa[i], aa[i]);
                #pragma unroll
                for (int j = 0; j < 4; j++) fma2(acc[i][j], pa, bb[j]);
            }
        }
        __syncthreads();
    }
    #pragma unroll
    for (int i = 0; i < 8; i++) {
        int n = n0 + (ty << 3) + i;
        float2 p0 = up2(acc[i][0]), p1 = up2(acc[i][1]), p2 = up2(acc[i][2]), p3 = up2(acc[i][3]);
        unsigned lo = (p0.x>0.f?1u:0u) | ((p0.y>0.f?1u:0u)<<8) | ((p1.x>0.f?1u:0u)<<16) | ((p1.y>0.f?1u:0u)<<24);
        unsigned hi = (p2.x>0.f?1u:0u) | ((p2.y>0.f?1u:0u)<<8) | ((p3.x>0.f?1u:0u)<<16) | ((p3.y>0.f?1u:0u)<<24);
        unsigned char* dst = &mask[((size_t)b * NPIX_ + n) * NPIX_ + m0 + (tx << 3)];
        *(unsigned*)dst = lo; *(unsigned*)(dst + 4) = hi;
    }
}

__global__ void k_rowstats(const float* __restrict__ cor, const unsigned char* __restrict__ mask,
                           float* __restrict__ stats, float* __restrict__ conf) {
    int row = blockIdx.x, tid = threadIdx.x;
    const float* r = cor + (size_t)row * NPIX_;
    const unsigned char* mk = mask + (size_t)row * NPIX_;
    __shared__ float sa[256], sb[256], sc[256];
    float mx1 = -3.0e38f, mx2 = -3.0e38f;
    for (int m = tid; m < NPIX_; m += 256) {
        float x = r[m];
        mx1 = fmaxf(mx1, x);
        mx2 = fmaxf(mx2, mk[m] ? -10000.f : x);
    }
    sa[tid] = mx1; sb[tid] = mx2;
    __syncthreads();
    for (int s = 128; s > 0; s >>= 1) {
        if (tid < s) { sa[tid] = fmaxf(sa[tid], sa[tid+s]); sb[tid] = fmaxf(sb[tid], sb[tid+s]); }
        __syncthreads();
    }
    mx1 = sa[0]; mx2 = sb[0];
    __syncthreads();
    float s1 = 0.f, sm = 0.f, s2 = 0.f;
    for (int m = tid; m < NPIX_; m += 256) {
        float x = r[m], mv = mk[m] ? 1.f : 0.f;
        float e1 = __expf(x - mx1);
        s1 += e1; sm += mv * e1;
        s2 += __expf((mv > 0.f ? -10000.f : x) - mx2);
    }
    sa[tid] = s1; sb[tid] = sm; sc[tid] = s2;
    __syncthreads();
    for (int s = 128; s > 0; s >>= 1) {
        if (tid < s) { sa[tid] += sa[tid+s]; sb[tid] += sb[tid+s]; sc[tid] += sc[tid+s]; }
        __syncthreads();
    }
    if (tid == 0) {
        stats[row*4+0] = mx1; stats[row*4+1] = 1.f / sa[0];
        stats[row*4+2] = mx2; stats[row*4+3] = 1.f / sc[0];
        conf[row] = sb[0] / sa[0];
    }
}

// HMMA: O[b][c0..c0+127][n0..n0+127] += softmax-weights x V (bf16 hi/lo split)
__global__ __launch_bounds__(256) void k_av_mma(
    const float* __restrict__ cor, const unsigned char* __restrict__ mask,
    const float* __restrict__ stats, const __nv_bfloat16* __restrict__ vhi,
    const __nv_bfloat16* __restrict__ vlo, float* __restrict__ O, int g) {
    extern __shared__ __nv_bfloat16 sm[];
    __nv_bfloat16* Ah = sm;            // [128][72]
    __nv_bfloat16* Al = sm + 9216;
    __nv_bfloat16* Bh = sm + 18432;    // [128c][72k]
    __nv_bfloat16* Bl = sm + 27648;
    int tid = threadIdx.x, lane = tid & 31, w = tid >> 5;
    int wm = w & 3, wn = w >> 2;
    int gq = lane >> 2, tg = lane & 3;
    int b = blockIdx.z, n0 = blockIdx.x << 7, c0 = blockIdx.y << 7;
    int r = tid >> 1, ml0 = (tid & 1) << 5;
    float mx = stats[((size_t)b * NPIX_ + n0 + r) * 4 + g * 2];
    float iv = stats[((size_t)b * NPIX_ + n0 + r) * 4 + g * 2 + 1];
    const float* C = cor + ((size_t)(b * NPIX_ + n0) + r) * NPIX_;
    const unsigned char* M = mask + ((size_t)(b * NPIX_ + n0) + r) * NPIX_;
    int bc = tid & 127, bhh = tid >> 7;
    const __nv_bfloat16* BHsrc = vhi + ((size_t)b * CV_ + c0 + bc) * NPIX_ + bhh * 32;
    const __nv_bfloat16* BLsrc = vlo + ((size_t)b * CV_ + c0 + bc) * NPIX_ + bhh * 32;
    float acc[2][8][4];
    #pragma unroll
    for (int i = 0; i < 2; i++)
        #pragma unroll
        for (int j = 0; j < 8; j++)
            #pragma unroll
            for (int t = 0; t < 4; t++) acc[i][j][t] = 0.f;
    for (int ch = 0; ch < 64; ch++) {
        int m0 = ch << 6;
        #pragma unroll
        for (int j = 0; j < 16; j++) {
            float2 cv = *(const float2*)&C[m0 + ml0 + 2*j];
            unsigned char q0 = M[m0 + ml0 + 2*j], q1 = M[m0 + ml0 + 2*j + 1];
            float w0, w1;
            if (g == 0) {
                w0 = q0 ? __expf(cv.x - mx) * iv : 0.f;
                w1 = q1 ? __expf(cv.y - mx) * iv : 0.f;
            } else {
                w0 = __expf((q0 ? -10000.f : cv.x) - mx) * iv;
                w1 = __expf((q1 ? -10000.f : cv.y) - mx) * iv;
            }
            float h0 = __bfloat162float(__float2bfloat16(w0));
            float h1 = __bfloat162float(__float2bfloat16(w1));
            int off = r * 72 + ml0 + 2*j;
            *(unsigned*)&Ah[off] = bfp(w0, w1);
            *(unsigned*)&Al[off] = bfp(w0 - h0, w1 - h1);
        }
        {
            const uint4* sh = (const uint4*)(BHsrc + m0);
            const uint4* sl = (const uint4*)(BLsrc + m0);
            uint4* dh = (uint4*)&Bh[bc * 72 + bhh * 32];
            uint4* dl = (uint4*)&Bl[bc * 72 + bhh * 32];
            dh[0] = sh[0]; dh[1] = sh[1]; dh[2] = sh[2]; dh[3] = sh[3];
            dl[0] = sl[0]; dl[1] = sl[1]; dl[2] = sl[2]; dl[3] = sl[3];
        }
        __syncthreads();
        #pragma unroll
        for (int ks = 0; ks < 4; ks++) {
            int k16 = ks << 4;
            unsigned ah[2][4], al[2][4];
            #pragma unroll
            for (int mt = 0; mt < 2; mt++) {
                const __nv_bfloat16* pa = &Ah[(wm*32 + mt*16 + gq) * 72 + k16 + tg*2];
                ah[mt][0] = *(const unsigned*)pa;
                ah[mt][1] = *(const unsigned*)(pa + 8*72);
                ah[mt][2] = *(const unsigned*)(pa + 8);
                ah[mt][3] = *(const unsigned*)(pa + 8*72 + 8);
                const __nv_bfloat16* pl = &Al[(wm*32 + mt*16 + gq) * 72 + k16 + tg*2];
                al[mt][0] = *(const unsigned*)pl;
                al[mt][1] = *(const unsigned*)(pl + 8*72);
                al[mt][2] = *(const unsigned*)(pl + 8);
                al[mt][3] = *(const unsigned*)(pl + 8*72 + 8);
            }
            #pragma unroll
            for (int nt = 0; nt < 8; nt++) {
                const __nv_bfloat16* pb = &Bh[(wn*64 + nt*8 + gq) * 72 + k16 + tg*2];
                unsigned b0 = *(const unsigned*)pb;
                unsigned b1 = *(const unsigned*)(pb + 8);
                const __nv_bfloat16* pbl = &Bl[(wn*64 + nt*8 + gq) * 72 + k16 + tg*2];
                unsigned l0 = *(const unsigned*)pbl;
                unsigned l1 = *(const unsigned*)(pbl + 8);
                #pragma unroll
                for (int mt = 0; mt < 2; mt++) {
                    mma16816(acc[mt][nt], ah[mt], b0, b1);
                    mma16816(acc[mt][nt], ah[mt], l0, l1);
                    mma16816(acc[mt][nt], al[mt], b0, b1);
                }
            }
        }
        __syncthreads();
    }
    #pragma unroll
    for (int mt = 0; mt < 2; mt++) {
        int row = n0 + wm*32 + mt*16 + gq;
        #pragma unroll
        for (int nt = 0; nt < 8; nt++) {
            int col = c0 + wn*64 + nt*8 + tg*2;
            float* p0 = &O[((size_t)b * CV_ + col) * NPIX_ + row];
            float* p1 = p0 + NPIX_;
            p0[0] = acc[mt][nt][0]; p1[0] = acc[mt][nt][1];
            p0[8] = acc[mt][nt][2]; p1[8] = acc[mt][nt][3];
        }
    }
}

__global__ void k_conv3(const float* __restrict__ in, const float* __restrict__ wgt,
                        const float* __restrict__ bias, float* __restrict__ out,
                        int Cin, int Cout, int flags, const float* __restrict__ res) {
    extern __shared__ float smf[];
    float* ws  = smf;
    float* ins = smf + 18432;
    int b = blockIdx.z, t = blockIdx.y, oc0 = blockIdx.x << 7;
    int y0 = (t >> 3) << 3, x0 = (t & 7) << 3, tid = threadIdx.x;
    int tx = tid & 15, ty = tid >> 4;
    int pyb = tx >> 1, pxb = (tx & 1) << 2;
    ull acc[4][4];
    #pragma unroll
    for (int p = 0; p < 4; p++)
        #pragma unroll
        for (int j = 0; j < 4; j++) acc[p][j] = 0ull;
    for (int ic0 = 0; ic0 < Cin; ic0 += 16) {
        for (int i = tid; i < 1600; i += 256) {
            int icl = i / 100, rem = i - icl * 100, hy = rem / 10, hx = rem - hy * 10;
            int gy = y0 + hy - 1, gx = x0 + hx - 1, ic = ic0 + icl;
            float v = 0.f;
            if (ic < Cin && (unsigned)gy < 64u && (unsigned)gx < 64u)
                v = in[(((size_t)b * Cin + ic) * 64 + gy) * 64 + gx];
            ins[i] = v;
        }
        for (int i = tid; i < 18432; i += 256) {
            int oc = i & 127, kk = i >> 7, icl = kk / 9, tap = kk - icl * 9, ic = ic0 + icl;
            ws[i] = (ic < Cin) ? wgt[(((size_t)(oc0 + oc)) * Cin + ic) * 9 + tap] : 0.f;
        }
        __syncthreads();
        int icm = (Cin - ic0 < 16) ? (Cin - ic0) : 16;
        for (int icl = 0; icl < icm; icl++) {
            ull xb[3][6];
            const float* iw = &ins[icl * 100 + pyb * 10 + pxb];
            #pragma unroll
            for (int ky = 0; ky < 3; ky++)
                #pragma unroll
                for (int c = 0; c < 6; c++) {
                    float v = iw[ky * 10 + c];
                    xb[ky][c] = pk2(v, v);
                }
            #pragma unroll
            for (int ky = 0; ky < 3; ky++)
                #pragma unroll
                for (int kx = 0; kx < 3; kx++) {
                    const float* wp = &ws[(icl * 9 + ky * 3 + kx) * 128 + (ty << 3)];
                    ull w0 = *(const ull*)wp, w1 = *(const ull*)(wp + 2);
                    ull w2 = *(const ull*)(wp + 4), w3 = *(const ull*)(wp + 6);
                    #pragma unroll
                    for (int p = 0; p < 4; p++) {
                        ull xq = xb[ky][kx + p];
                        fma2(acc[p][0], xq, w0); fma2(acc[p][1], xq, w1);
                        fma2(acc[p][2], xq, w2); fma2(acc[p][3], xq, w3);
                    }
                }
        }
        __syncthreads();
    }
    #pragma unroll
    for (int j = 0; j < 4; j++) {
        int ocA = oc0 + (ty << 3) + 2 * j;
        float bA = bias[ocA], bB = bias[ocA + 1];
        size_t rowA = (((size_t)b * Cout + ocA) * 64 + y0 + pyb) * 64 + x0 + pxb;
        size_t rowB = rowA + 4096;
        #pragma unroll
        for (int p = 0; p < 4; p++) {
            float2 vpair = up2(acc[p][j]);
            float va = vpair.x + bA, vb = vpair.y + bB;
            if (flags & 1) { va = fmaxf(va, 0.f); vb = fmaxf(vb, 0.f); }
            if (flags & 2) { va += res[rowA + p]; vb += res[rowB + p]; }
            out[rowA + p] = va;
            out[rowB + p] = vb;
        }
    }
}

__global__ void k_instnorm(const float* __restrict__ x, float* __restrict__ st) {
    int row = blockIdx.x, tid = threadIdx.x;
    const float* p = x + (size_t)row * NPIX_;
    float s = 0.f, ss = 0.f;
    for (int i = tid; i < NPIX_; i += 256) { float v = p[i]; s += v; ss += v * v; }
    __shared__ float r1[256], r2[256];
    r1[tid] = s; r2[tid] = ss;
    __syncthreads();
    for (int k = 128; k > 0; k >>= 1) {
        if (tid < k) { r1[tid] += r1[tid+k]; r2[tid] += r2[tid+k]; }
        __syncthreads();
    }
    if (tid == 0) {
        float m = r1[0] * (1.f / NPIX_);
        float v = r2[0] * (1.f / NPIX_) - m * m;
        st[row*2] = m; st[row*2+1] = rsqrtf(v + 1e-5f);
    }
}

__global__ void k_spade_pono(const float* __restrict__ q, const float* __restrict__ gam,
                             const float* __restrict__ bet, const float* __restrict__ outat,
                             const float* __restrict__ conf, const float* __restrict__ innm,
                             float* __restrict__ y) {
    int b = blockIdx.x >> 6, n0 = (blockIdx.x & 63) << 6, tid = threadIdx.x;
    int nn = tid & 63, cp = tid >> 6;
    __shared__ float ps[4][64], pss[4][64], pm[64], pr[64];
    float cf = conf[(size_t)b * NPIX_ + n0 + nn];
    float s = 0.f, ss = 0.f;
    for (int base = 0; base < CV_; base += 4) {
        int cc = base + cp;
        size_t o = ((size_t)b * CV_ + cc) * NPIX_ + n0 + nn;
        float m = innm[(b*CV_+cc)*2], rs = innm[(b*CV_+cc)*2+1];
        float qv = q[o];
        float sp = (qv - m) * rs * (1.f + gam[o]) + bet[o];
        float tv = outat[o] + (1.f - cf) * sp + qv;
        s += tv; ss += tv * tv;
    }
    ps[cp][nn] = s; pss[cp][nn] = ss;
    __syncthreads();
    if (tid < 64) {
        float S = ps[0][tid]+ps[1][tid]+ps[2][tid]+ps[3][tid];
        float SS = pss[0][tid]+pss[1][tid]+pss[2][tid]+pss[3][tid];
        float m = S * (1.f/256.f), v = SS * (1.f/256.f) - m * m;
        pm[tid] = m; pr[tid] = rsqrtf(v + 1e-5f);
    }
    __syncthreads();
    float mmu = pm[nn], rr = pr[nn];
    for (int base = 0; base < CV_; base += 4) {
        int cc = base + cp;
        size_t o = ((size_t)b * CV_ + cc) * NPIX_ + n0 + nn;
        float m = innm[(b*CV_+cc)*2], rs = innm[(b*CV_+cc)*2+1];
        float qv = q[o];
        float sp = (qv - m) * rs * (1.f + gam[o]) + bet[o];
        float tv = outat[o] + (1.f - cf) * sp + qv;
        y[o] = (tv - mmu) * rr;
    }
}

extern "C" void kernel_launch(void* const* d_in, const int* in_sizes, int n_in,
                              void* d_out, int out_size) {
    const float *q = (const float*)d_in[0], *k = (const float*)d_in[1],
                *v = (const float*)d_in[2], *pos = (const float*)d_in[3],
                *seg = (const float*)d_in[4], *v2 = (const float*)d_in[5],
                *f_w = (const float*)d_in[6], *f_b = (const float*)d_in[7],
                *g_w = (const float*)d_in[8], *g_b = (const float*)d_in[9],
                *h_w = (const float*)d_in[10], *h_b = (const float*)d_in[11],
                *fp_w = (const float*)d_in[12], *fp_b = (const float*)d_in[13],
                *gp_w = (const float*)d_in[14], *gp_b = (const float*)d_in[15],
                *sp_s_w = (const float*)d_in[16], *sp_s_b = (const float*)d_in[17],
                *sp_g_w = (const float*)d_in[18], *sp_g_b = (const float*)d_in[19],
                *sp_b_w = (const float*)d_in[20], *sp_b_b = (const float*)d_in[21],
                *r1_w = (const float*)d_in[22], *r1_b = (const float*)d_in[23],
                *r2_w = (const float*)d_in[24], *r2_b = (const float*)d_in[25];
    float* S;
    cudaGetSymbolAddress((void**)&S, g_scratch);
    float* out_res  = (float*)d_out;
    float* out_out2 = out_res + 2097152;
    float* out_cor  = out_res + 4194304;
    unsigned char* mask = (unsigned char*)(S + OFF_MASK);
    __nv_bfloat16* VHI  = (__nv_bfloat16*)(S + OFF_VHI);
    __nv_bfloat16* VLO  = (__nv_bfloat16*)(S + OFF_VLO);
    __nv_bfloat16* V2HI = (__nv_bfloat16*)(S + OFF_V2HI);
    __nv_bfloat16* V2LO = (__nv_bfloat16*)(S + OFF_V2LO);
    __nv_bfloat16* QFH  = (__nv_bfloat16*)(S + OFF_QFH);
    __nv_bfloat16* QFL  = (__nv_bfloat16*)(S + OFF_QFL);
    __nv_bfloat16* KFH  = (__nv_bfloat16*)(S + OFF_KFH);
    __nv_bfloat16* KFL  = (__nv_bfloat16*)(S + OFF_KFL);
    cudaFuncSetAttribute(k_conv3, cudaFuncAttributeMaxDynamicSharedMemorySize, 80128);
    cudaFuncSetAttribute(k_av_mma, cudaFuncAttributeMaxDynamicSharedMemorySize, 73728);
    cudaFuncSetAttribute(k_cor_mma, cudaFuncAttributeMaxDynamicSharedMemorySize, 73728);

    k_normcat<<<128, 256>>>(q, pos, S + OFF_QUERY);
    k_normcat<<<128, 256>>>(k, pos, S + OFF_KEYT);
    k_gemm<<<dim3(5,128), 256>>>(S + OFF_QUERY, f_w,  f_b,  S + OFF_QF, CQK_, CQK_);
    k_gemm<<<dim3(5,128), 256>>>(S + OFF_KEYT,  g_w,  g_b,  S + OFF_KF, CQK_, CQK_);
    k_gemm<<<dim3(1,128), 256>>>(S + OFF_QUERY, fp_w, fp_b, S + OFF_QP, CQK_, DP_);
    k_gemm<<<dim3(1,128), 256>>>(S + OFF_KEYT,  gp_w, gp_b, S + OFF_KP, CQK_, DP_);
    k_gemmW<<<dim3(4,64,2), 256>>>(v, h_w, h_b, S + OFF_VH);
    k_split<<<10240, 256>>>(S + OFF_QF, QFH, QFL);
    k_split<<<10240, 256>>>(S + OFF_KF, KFH, KFL);
    k_split<<<8192, 256>>>(S + OFF_VH, VHI, VLO);
    k_split<<<8192, 256>>>(v2, V2HI, V2LO);
    k_cor_mma<<<dim3(32,32,2), 256, 73728>>>(QFH, QFL, KFH, KFL, out_cor);
    k_mask<<<dim3(32,32,2), 256>>>(S + OFF_QP, S + OFF_KP, mask);
    k_rowstats<<<8192, 256>>>(out_cor, mask, S + OFF_STATS, S + OFF_CONF);
    k_av_mma<<<dim3(32,2,2), 256, 73728>>>(out_cor, mask, S + OFF_STATS, VHI, VLO, S + OFF_OUT, 0);
    k_av_mma<<<dim3(32,2,2), 256, 73728>>>(out_cor, mask, S + OFF_STATS, V2HI, V2LO, out_out2, 1);
    k_conv3<<<dim3(1,64,2), 256, 80128>>>(seg, sp_s_w, sp_s_b, S + OFF_ACTV, 3, 128, 1, nullptr);
    k_conv3<<<dim3(2,64,2), 256, 80128>>>(S + OFF_ACTV, sp_g_w, sp_g_b, S + OFF_GAMMA, 128, 256, 0, nullptr);
    k_conv3<<<dim3(2,64,2), 256, 80128>>>(S + OFF_ACTV, sp_b_w, sp_b_b, S + OFF_BETA,  128, 256, 0, nullptr);
    k_instnorm<<<512, 256>>>(q, S + OFF_INNM);
    k_spade_pono<<<128, 256>>>(q, S + OFF_GAMMA, S + OFF_BETA, S + OFF_OUT,
                               S + OFF_CONF, S + OFF_INNM, S + OFF_Y);
    k_conv3<<<dim3(2,64,2), 256, 80128>>>(S + OFF_Y,  r1_w, r1_b, S + OFF_T1, 256, 256, 1, nullptr);
    k_conv3<<<dim3(2,64,2), 256, 80128>>>(S + OFF_T1, r2_w, r2_b, out_res,    256, 256, 2, S + OFF_Y);
}

// round 11
// speedup vs baseline: 2.8920x; 1.3106x over previous
#include <cuda_runtime.h>
#include <cuda_bf16.h>
#include <math.h>

#define CV_   256
#define CQK_  320
#define DP_   64
#define NPIX_ 4096

#define OFF_QUERY  0u
#define OFF_KEYT   (OFF_QUERY + 2621440u)
#define OFF_QF     (OFF_KEYT  + 2621440u)
#define OFF_KF     (OFF_QF    + 2621440u)
#define OFF_QP     (OFF_KF    + 2621440u)
#define OFF_KP     (OFF_QP    + 524288u)
#define OFF_VH     (OFF_KP    + 524288u)
#define OFF_STATS  (OFF_VH    + 2097152u)
#define OFF_CONF   (OFF_STATS + 32768u)
#define OFF_OUT    (OFF_CONF  + 8192u)
#define OFF_ACTV   (OFF_OUT   + 2097152u)
#define OFF_GAMMA  (OFF_ACTV  + 1048576u)
#define OFF_BETA   (OFF_GAMMA + 2097152u)
#define OFF_Y      (OFF_BETA  + 2097152u)
#define OFF_T1     (OFF_Y     + 2097152u)
#define OFF_INNM   (OFF_T1    + 2097152u)
#define OFF_MASK   (OFF_INNM  + 1024u)
#define OFF_VHI    (OFF_MASK  + 8388608u)
#define OFF_VLO    (OFF_VHI   + 1048576u)
#define OFF_V2HI   (OFF_VLO   + 1048576u)
#define OFF_V2LO   (OFF_V2HI  + 1048576u)
#define OFF_QFH    (OFF_V2LO  + 1048576u)
#define OFF_QFL    (OFF_QFH   + 1310720u)
#define OFF_KFH    (OFF_QFL   + 1310720u)
#define OFF_KFL    (OFF_KFH   + 1310720u)
#define OFF_WR1    (OFF_KFL   + 1310720u)
#define OFF_WR2    (OFF_WR1   + 589824u)
#define OFF_WG     (OFF_WR2   + 589824u)
#define OFF_WB     (OFF_WG    + 294912u)
#define SCRATCH_FLOATS (OFF_WB + 294912u)

__device__ float g_scratch[SCRATCH_FLOATS];

typedef unsigned long long ull;
__device__ __forceinline__ ull pk2(float lo, float hi) {
    ull r; asm("mov.b64 %0,{%1,%2};" : "=l"(r) : "f"(lo), "f"(hi)); return r;
}
__device__ __forceinline__ void fma2(ull& d, ull a, ull b) {
    asm("fma.rn.f32x2 %0,%1,%2,%0;" : "+l"(d) : "l"(a), "l"(b));
}
__device__ __forceinline__ float2 up2(ull v) {
    float2 f; asm("mov.b64 {%0,%1},%2;" : "=f"(f.x), "=f"(f.y) : "l"(v)); return f;
}
__device__ __forceinline__ unsigned bfp(float a, float b) {
    __nv_bfloat162 t = __floats2bfloat162_rn(a, b); return *(unsigned*)&t;
}
__device__ __forceinline__ void mma16816(float* c, const unsigned* a, unsigned b0, unsigned b1) {
    asm volatile("mma.sync.aligned.m16n8k16.row.col.f32.bf16.bf16.f32 "
        "{%0,%1,%2,%3},{%4,%5,%6,%7},{%8,%9},{%0,%1,%2,%3};"
        : "+f"(c[0]), "+f"(c[1]), "+f"(c[2]), "+f"(c[3])
        : "r"(a[0]), "r"(a[1]), "r"(a[2]), "r"(a[3]), "r"(b0), "r"(b1));
}

__global__ void k_normcat(const float* __restrict__ src, const float* __restrict__ pos,
                          float* __restrict__ dst) {
    int b = blockIdx.x >> 6, n0 = (blockIdx.x & 63) << 6, tid = threadIdx.x;
    __shared__ float red[4][64], rnorm[64];
    int nn = tid & 63, cp = tid >> 6;
    const float* sp = src + (size_t)b * CV_ * NPIX_ + n0 + nn;
    float acc = 0.f;
    for (int c = cp; c < CV_; c += 4) { float x = sp[(size_t)c * NPIX_]; acc += x * x; }
    red[cp][nn] = acc;
    __syncthreads();
    if (tid < 64) {
        float s = red[0][tid] + red[1][tid] + red[2][tid] + red[3][tid];
        rnorm[tid] = 1.f / (sqrtf(s) + 2.220446049250313e-16f);
    }
    __syncthreads();
    for (int i = 0; i < 80; i++) {
        int idx = i * 256 + tid, n = idx / CQK_, c = idx - n * CQK_;
        float v = (c < CV_) ? src[(size_t)(b * CV_ + c) * NPIX_ + n0 + n] * rnorm[n]
                            : pos[(size_t)(c - CV_) * NPIX_ + n0 + n];
        dst[((size_t)b * NPIX_ + n0 + n) * CQK_ + c] = v;
    }
}

__global__ void k_gemm(const float* __restrict__ A, const float* __restrict__ W,
                       const float* __restrict__ bias, float* __restrict__ C, int K, int O) {
    __shared__ float As[16][64], Ws[16][64];
    int p0 = blockIdx.y << 6, o0 = blockIdx.x << 6, tid = threadIdx.x;
    int tx4 = (tid & 15) * 4, ty4 = (tid >> 4) * 4;
    ull acc[4][2];
    #pragma unroll
    for (int i = 0; i < 4; i++) { acc[i][0] = 0ull; acc[i][1] = 0ull; }
    for (int k0 = 0; k0 < K; k0 += 16) {
        #pragma unroll
        for (int i = 0; i < 4; i++) {
            int idx = i * 256 + tid, pp = idx >> 4, kk = idx & 15;
            As[kk][pp] = A[(size_t)(p0 + pp) * K + k0 + kk];
            Ws[kk][pp] = W[(size_t)(o0 + pp) * K + k0 + kk];
        }
        __syncthreads();
        #pragma unroll
        for (int kk = 0; kk < 16; kk++) {
            float4 a = *(const float4*)&As[kk][ty4];
            ull b0 = *(const ull*)&Ws[kk][tx4];
            ull b1 = *(const ull*)&Ws[kk][tx4 + 2];
            float av[4] = {a.x, a.y, a.z, a.w};
            #pragma unroll
            for (int ii = 0; ii < 4; ii++) {
                ull pa = pk2(av[ii], av[ii]);
                fma2(acc[ii][0], pa, b0);
                fma2(acc[ii][1], pa, b1);
            }
        }
        __syncthreads();
    }
    for (int ii = 0; ii < 4; ii++) {
        float2 q0 = up2(acc[ii][0]), q1 = up2(acc[ii][1]);
        float4 r;
        r.x = q0.x + bias[o0+tx4+0]; r.y = q0.y + bias[o0+tx4+1];
        r.z = q1.x + bias[o0+tx4+2]; r.w = q1.y + bias[o0+tx4+3];
        *(float4*)&C[(size_t)(p0 + ty4 + ii) * O + o0 + tx4] = r;
    }
}

__global__ void k_gemmW(const float* __restrict__ A, const float* __restrict__ W,
                        const float* __restrict__ bias, float* __restrict__ C) {
    __shared__ float As[16][64], Ws[16][64];
    int b = blockIdx.z, o0 = blockIdx.x << 6, p0 = blockIdx.y << 6, tid = threadIdx.x;
    int tx4 = (tid & 15) * 4, ty4 = (tid >> 4) * 4;
    ull acc[4][2];
    #pragma unroll
    for (int i = 0; i < 4; i++) { acc[i][0] = 0ull; acc[i][1] = 0ull; }
    for (int k0 = 0; k0 < 256; k0 += 16) {
        #pragma unroll
        for (int i = 0; i < 4; i++) {
            int idx = i * 256 + tid;
            int kk = idx >> 6, pp = idx & 63;
            As[kk][pp] = A[((size_t)b * 256 + k0 + kk) * NPIX_ + p0 + pp];
            int oo = idx >> 4, k2 = idx & 15;
            Ws[k2][oo] = W[(size_t)(o0 + oo) * 256 + k0 + k2];
        }
        __syncthreads();
        #pragma unroll
        for (int kk = 0; kk < 16; kk++) {
            float4 w = *(const float4*)&Ws[kk][ty4];
            ull a0 = *(const ull*)&As[kk][tx4], a1 = *(const ull*)&As[kk][tx4 + 2];
            float wv[4] = {w.x, w.y, w.z, w.w};
            #pragma unroll
            for (int oi = 0; oi < 4; oi++) {
                ull pw = pk2(wv[oi], wv[oi]);
                fma2(acc[oi][0], pw, a0);
                fma2(acc[oi][1], pw, a1);
            }
        }
        __syncthreads();
    }
    for (int oi = 0; oi < 4; oi++) {
        float bv = bias[o0 + ty4 + oi];
        float2 q0 = up2(acc[oi][0]), q1 = up2(acc[oi][1]);
        float4 r = {q0.x + bv, q0.y + bv, q1.x + bv, q1.y + bv};
        *(float4*)&C[((size_t)b * 256 + o0 + ty4 + oi) * NPIX_ + p0 + tx4] = r;
    }
}

__global__ void k_split(const float* __restrict__ x, __nv_bfloat16* __restrict__ hi,
                        __nv_bfloat16* __restrict__ lo) {
    int i = blockIdx.x * 256 + threadIdx.x;
    float v = x[i];
    __nv_bfloat16 h = __float2bfloat16(v);
    hi[i] = h;
    lo[i] = __float2bfloat16(v - __bfloat162float(h));
}

// weights [oc][ic][tap] fp32 -> packed (hiBits | loBits<<16) in [tap][oc][ic]
__global__ void k_wprep(const float* __restrict__ w, unsigned* __restrict__ o,
                        int Cout, int Cin) {
    int i = blockIdx.x * 256 + threadIdx.x;
    int tot = Cout * Cin * 9;
    if (i >= tot) return;
    int tap = i % 9, t2 = i / 9;
    int ic = t2 % Cin, oc = t2 / Cin;
    float v = w[i];
    __nv_bfloat16 h = __float2bfloat16(v);
    __nv_bfloat16 l = __float2bfloat16(v - __bfloat162float(h));
    unsigned pk = (unsigned)*(unsigned short*)&h | ((unsigned)*(unsigned short*)&l << 16);
    o[((size_t)tap * Cout + oc) * Cin + ic] = pk;
}

// HMMA: cor[b][n0..+127][m0..+127] = (QfH+QfL)·(KfH+KfL)^T / sqrt(320)
__global__ __launch_bounds__(256) void k_cor_mma(
    const __nv_bfloat16* __restrict__ qh, const __nv_bfloat16* __restrict__ ql,
    const __nv_bfloat16* __restrict__ kh, const __nv_bfloat16* __restrict__ kl,
    float* __restrict__ cor) {
    extern __shared__ __nv_bfloat16 sm[];
    __nv_bfloat16* Ah = sm;
    __nv_bfloat16* Al = sm + 9216;
    __nv_bfloat16* Bh = sm + 18432;
    __nv_bfloat16* Bl = sm + 27648;
    int tid = threadIdx.x, lane = tid & 31, w = tid >> 5;
    int wm = w & 3, wn = w >> 2;
    int gq = lane >> 2, tg = lane & 3;
    int b = blockIdx.z, n0 = blockIdx.x << 7, m0 = blockIdx.y << 7;
    int r = tid >> 1, hh = tid & 1;
    const __nv_bfloat16* A0 = qh + ((size_t)(b * NPIX_) + n0 + r) * CQK_ + hh * 32;
    const __nv_bfloat16* A1 = ql + ((size_t)(b * NPIX_) + n0 + r) * CQK_ + hh * 32;
    const __nv_bfloat16* B0 = kh + ((size_t)(b * NPIX_) + m0 + r) * CQK_ + hh * 32;
    const __nv_bfloat16* B1 = kl + ((size_t)(b * NPIX_) + m0 + r) * CQK_ + hh * 32;
    __nv_bfloat16* dA0 = &Ah[r * 72 + hh * 32];
    __nv_bfloat16* dA1 = &Al[r * 72 + hh * 32];
    __nv_bfloat16* dB0 = &Bh[r * 72 + hh * 32];
    __nv_bfloat16* dB1 = &Bl[r * 72 + hh * 32];
    float acc[2][8][4];
    #pragma unroll
    for (int i = 0; i < 2; i++)
        #pragma unroll
        for (int j = 0; j < 8; j++)
            #pragma unroll
            for (int t = 0; t < 4; t++) acc[i][j][t] = 0.f;
    for (int kc = 0; kc < CQK_; kc += 64) {
        {
            const uint4* s0 = (const uint4*)(A0 + kc);
            const uint4* s1 = (const uint4*)(A1 + kc);
            const uint4* s2 = (const uint4*)(B0 + kc);
            const uint4* s3 = (const uint4*)(B1 + kc);
            uint4* d0 = (uint4*)dA0; uint4* d1 = (uint4*)dA1;
            uint4* d2 = (uint4*)dB0; uint4* d3 = (uint4*)dB1;
            #pragma unroll
            for (int i = 0; i < 4; i++) {
                d0[i] = s0[i]; d1[i] = s1[i]; d2[i] = s2[i]; d3[i] = s3[i];
            }
        }
        __syncthreads();
        #pragma unroll
        for (int ks = 0; ks < 4; ks++) {
            int k16 = ks << 4;
            unsigned ah[2][4], al[2][4];
            #pragma unroll
            for (int mt = 0; mt < 2; mt++) {
                const __nv_bfloat16* pa = &Ah[(wm*32 + mt*16 + gq) * 72 + k16 + tg*2];
                ah[mt][0] = *(const unsigned*)pa;
                ah[mt][1] = *(const unsigned*)(pa + 8*72);
                ah[mt][2] = *(const unsigned*)(pa + 8);
                ah[mt][3] = *(const unsigned*)(pa + 8*72 + 8);
                const __nv_bfloat16* pl = &Al[(wm*32 + mt*16 + gq) * 72 + k16 + tg*2];
                al[mt][0] = *(const unsigned*)pl;
                al[mt][1] = *(const unsigned*)(pl + 8*72);
                al[mt][2] = *(const unsigned*)(pl + 8);
                al[mt][3] = *(const unsigned*)(pl + 8*72 + 8);
            }
            #pragma unroll
            for (int nt = 0; nt < 8; nt++) {
                const __nv_bfloat16* pb = &Bh[(wn*64 + nt*8 + gq) * 72 + k16 + tg*2];
                unsigned b0 = *(const unsigned*)pb;
                unsigned b1 = *(const unsigned*)(pb + 8);
                const __nv_bfloat16* pbl = &Bl[(wn*64 + nt*8 + gq) * 72 + k16 + tg*2];
                unsigned l0 = *(const unsigned*)pbl;
                unsigned l1 = *(const unsigned*)(pbl + 8);
                #pragma unroll
                for (int mt = 0; mt < 2; mt++) {
                    mma16816(acc[mt][nt], ah[mt], b0, b1);
                    mma16816(acc[mt][nt], ah[mt], l0, l1);
                    mma16816(acc[mt][nt], al[mt], b0, b1);
                }
            }
        }
        __syncthreads();
    }
    const float s = 0.05590169943749474f;
    #pragma unroll
    for (int mt = 0; mt < 2; mt++) {
        int row = n0 + wm*32 + mt*16 + gq;
        #pragma unroll
        for (int nt = 0; nt < 8; nt++) {
            int col = m0 + wn*64 + nt*8 + tg*2;
            float2 v0 = {acc[mt][nt][0]*s, acc[mt][nt][1]*s};
            float2 v1 = {acc[mt][nt][2]*s, acc[mt][nt][3]*s};
            *(float2*)&cor[((size_t)(b * NPIX_) + row) * NPIX_ + col] = v0;
            *(float2*)&cor[((size_t)(b * NPIX_) + row + 8) * NPIX_ + col] = v1;
        }
    }
}

__global__ void k_mask(const float* __restrict__ Qp, const float* __restrict__ Kp,
                       unsigned char* __restrict__ mask) {
    __shared__ float As[8][132], Bs[8][132];
    int b = blockIdx.z, n0 = blockIdx.y << 7, m0 = blockIdx.x << 7;
    int tid = threadIdx.x, tx = tid & 15, ty = tid >> 4;
    int r = tid >> 1, kq = (tid & 1) << 2;
    const float* A  = Qp + (size_t)(b * NPIX_ + n0) * DP_;
    const float* Bk = Kp + (size_t)(b * NPIX_ + m0) * DP_;
    ull acc[8][4];
    #pragma unroll
    for (int i = 0; i < 8; i++)
        #pragma unroll
        for (int j = 0; j < 4; j++) acc[i][j] = 0ull;
    for (int k0 = 0; k0 < DP_; k0 += 8) {
        float4 av = *(const float4*)&A [(size_t)r * DP_ + k0 + kq];
        float4 bv = *(const float4*)&Bk[(size_t)r * DP_ + k0 + kq];
        As[kq+0][r] = av.x; As[kq+1][r] = av.y; As[kq+2][r] = av.z; As[kq+3][r] = av.w;
        Bs[kq+0][r] = bv.x; Bs[kq+1][r] = bv.y; Bs[kq+2][r] = bv.z; Bs[kq+3][r] = bv.w;
        __syncthreads();
        #pragma unroll
        for (int kk = 0; kk < 8; kk++) {
            float4 a0 = *(const float4*)&As[kk][ty << 3];
            float4 a1 = *(const float4*)&As[kk][(ty << 3) + 4];
            ull bb[4];
            #pragma unroll
            for (int j = 0; j < 4; j++) bb[j] = *(const ull*)&Bs[kk][(tx << 3) + 2*j];
            float aa[8] = {a0.x,a0.y,a0.z,a0.w,a1.x,a1.y,a1.z,a1.w};
            #pragma unroll
            for (int i = 0; i < 8; i++) {
                ull pa = pk2(aa[i], aa[i]);
                #pragma unroll
                for (int j = 0; j < 4; j++) fma2(acc[i][j], pa, bb[j]);
            }
        }
        __syncthreads();
    }
    #pragma unroll
    for (int i = 0; i < 8; i++) {
        int n = n0 + (ty << 3) + i;
        float2 p0 = up2(acc[i][0]), p1 = up2(acc[i][1]), p2 = up2(acc[i][2]), p3 = up2(acc[i][3]);
        unsigned lo = (p0.x>0.f?1u:0u) | ((p0.y>0.f?1u:0u)<<8) | ((p1.x>0.f?1u:0u)<<16) | ((p1.y>0.f?1u:0u)<<24);
        unsigned hi = (p2.x>0.f?1u:0u) | ((p2.y>0.f?1u:0u)<<8) | ((p3.x>0.f?1u:0u)<<16) | ((p3.y>0.f?1u:0u)<<24);
        unsigned char* dst = &mask[((size_t)b * NPIX_ + n) * NPIX_ + m0 + (tx << 3)];
        *(unsigned*)dst = lo; *(unsigned*)(dst + 4) = hi;
    }
}

__global__ void k_rowstats(const float* __restrict__ cor, const unsigned char* __restrict__ mask,
                           float* __restrict__ stats, float* __restrict__ conf) {
    int row = blockIdx.x, tid = threadIdx.x;
    const float* r = cor + (size_t)row * NPIX_;
    const unsigned char* mk = mask + (size_t)row * NPIX_;
    __shared__ float sa[256], sb[256], sc[256];
    float mx1 = -3.0e38f, mx2 = -3.0e38f;
    for (int m = tid; m < NPIX_; m += 256) {
        float x = r[m];
        mx1 = fmaxf(mx1, x);
        mx2 = fmaxf(mx2, mk[m] ? -10000.f : x);
    }
    sa[tid] = mx1; sb[tid] = mx2;
    __syncthreads();
    for (int s = 128; s > 0; s >>= 1) {
        if (tid < s) { sa[tid] = fmaxf(sa[tid], sa[tid+s]); sb[tid] = fmaxf(sb[tid], sb[tid+s]); }
        __syncthreads();
    }
    mx1 = sa[0]; mx2 = sb[0];
    __syncthreads();
    float s1 = 0.f, sm = 0.f, s2 = 0.f;
    for (int m = tid; m < NPIX_; m += 256) {
        float x = r[m], mv = mk[m] ? 1.f : 0.f;
        float e1 = __expf(x - mx1);
        s1 += e1; sm += mv * e1;
        s2 += __expf((mv > 0.f ? -10000.f : x) - mx2);
    }
    sa[tid] = s1; sb[tid] = sm; sc[tid] = s2;
    __syncthreads();
    for (int s = 128; s > 0; s >>= 1) {
        if (tid < s) { sa[tid] += sa[tid+s]; sb[tid] += sb[tid+s]; sc[tid] += sc[tid+s]; }
        __syncthreads();
    }
    if (tid == 0) {
        stats[row*4+0] = mx1; stats[row*4+1] = 1.f / sa[0];
        stats[row*4+2] = mx2; stats[row*4+3] = 1.f / sc[0];
        conf[row] = sb[0] / sa[0];
    }
}

// HMMA attention x V
__global__ __launch_bounds__(256) void k_av_mma(
    const float* __restrict__ cor, const unsigned char* __restrict__ mask,
    const float* __restrict__ stats, const __nv_bfloat16* __restrict__ vhi,
    const __nv_bfloat16* __restrict__ vlo, float* __restrict__ O, int g) {
    extern __shared__ __nv_bfloat16 sm[];
    __nv_bfloat16* Ah = sm;
    __nv_bfloat16* Al = sm + 9216;
    __nv_bfloat16* Bh = sm + 18432;
    __nv_bfloat16* Bl = sm + 27648;
    int tid = threadIdx.x, lane = tid & 31, w = tid >> 5;
    int wm = w & 3, wn = w >> 2;
    int gq = lane >> 2, tg = lane & 3;
    int b = blockIdx.z, n0 = blockIdx.x << 7, c0 = blockIdx.y << 7;
    int r = tid >> 1, ml0 = (tid & 1) << 5;
    float mx = stats[((size_t)b * NPIX_ + n0 + r) * 4 + g * 2];
    float iv = stats[((size_t)b * NPIX_ + n0 + r) * 4 + g * 2 + 1];
    const float* C = cor + ((size_t)(b * NPIX_ + n0) + r) * NPIX_;
    const unsigned char* M = mask + ((size_t)(b * NPIX_ + n0) + r) * NPIX_;
    int bc = tid & 127, bhh = tid >> 7;
    const __nv_bfloat16* BHsrc = vhi + ((size_t)b * CV_ + c0 + bc) * NPIX_ + bhh * 32;
    const __nv_bfloat16* BLsrc = vlo + ((size_t)b * CV_ + c0 + bc) * NPIX_ + bhh * 32;
    float acc[2][8][4];
    #pragma unroll
    for (int i = 0; i < 2; i++)
        #pragma unroll
        for (int j = 0; j < 8; j++)
            #pragma unroll
            for (int t = 0; t < 4; t++) acc[i][j][t] = 0.f;
    for (int ch = 0; ch < 64; ch++) {
        int m0 = ch << 6;
        #pragma unroll
        for (int j = 0; j < 16; j++) {
            float2 cv = *(const float2*)&C[m0 + ml0 + 2*j];
            unsigned char q0 = M[m0 + ml0 + 2*j], q1 = M[m0 + ml0 + 2*j + 1];
            float w0, w1;
            if (g == 0) {
                w0 = q0 ? __expf(cv.x - mx) * iv : 0.f;
                w1 = q1 ? __expf(cv.y - mx) * iv : 0.f;
            } else {
                w0 = __expf((q0 ? -10000.f : cv.x) - mx) * iv;
                w1 = __expf((q1 ? -10000.f : cv.y) - mx) * iv;
            }
            float h0 = __bfloat162float(__float2bfloat16(w0));
            float h1 = __bfloat162float(__float2bfloat16(w1));
            int off = r * 72 + ml0 + 2*j;
            *(unsigned*)&Ah[off] = bfp(w0, w1);
            *(unsigned*)&Al[off] = bfp(w0 - h0, w1 - h1);
        }
        {
            const uint4* sh = (const uint4*)(BHsrc + m0);
            const uint4* sl = (const uint4*)(BLsrc + m0);
            uint4* dh = (uint4*)&Bh[bc * 72 + bhh * 32];
            uint4* dl = (uint4*)&Bl[bc * 72 + bhh * 32];
            dh[0] = sh[0]; dh[1] = sh[1]; dh[2] = sh[2]; dh[3] = sh[3];
            dl[0] = sl[0]; dl[1] = sl[1]; dl[2] = sl[2]; dl[3] = sl[3];
        }
        __syncthreads();
        #pragma unroll
        for (int ks = 0; ks < 4; ks++) {
            int k16 = ks << 4;
            unsigned ah[2][4], al[2][4];
            #pragma unroll
            for (int mt = 0; mt < 2; mt++) {
                const __nv_bfloat16* pa = &Ah[(wm*32 + mt*16 + gq) * 72 + k16 + tg*2];
                ah[mt][0] = *(const unsigned*)pa;
                ah[mt][1] = *(const unsigned*)(pa + 8*72);
                ah[mt][2] = *(const unsigned*)(pa + 8);
                ah[mt][3] = *(const unsigned*)(pa + 8*72 + 8);
                const __nv_bfloat16* pl = &Al[(wm*32 + mt*16 + gq) * 72 + k16 + tg*2];
                al[mt][0] = *(const unsigned*)pl;
                al[mt][1] = *(const unsigned*)(pl + 8*72);
                al[mt][2] = *(const unsigned*)(pl + 8);
                al[mt][3] = *(const unsigned*)(pl + 8*72 + 8);
            }
            #pragma unroll
            for (int nt = 0; nt < 8; nt++) {
                const __nv_bfloat16* pb = &Bh[(wn*64 + nt*8 + gq) * 72 + k16 + tg*2];
                unsigned b0 = *(const unsigned*)pb;
                unsigned b1 = *(const unsigned*)(pb + 8);
                const __nv_bfloat16* pbl = &Bl[(wn*64 + nt*8 + gq) * 72 + k16 + tg*2];
                unsigned l0 = *(const unsigned*)pbl;
                unsigned l1 = *(const unsigned*)(pbl + 8);
                #pragma unroll
                for (int mt = 0; mt < 2; mt++) {
                    mma16816(acc[mt][nt], ah[mt], b0, b1);
                    mma16816(acc[mt][nt], ah[mt], l0, l1);
                    mma16816(acc[mt][nt], al[mt], b0, b1);
                }
            }
        }
        __syncthreads();
    }
    #pragma unroll
    for (int mt = 0; mt < 2; mt++) {
        int row = n0 + wm*32 + mt*16 + gq;
        #pragma unroll
        for (int nt = 0; nt < 8; nt++) {
            int col = c0 + wn*64 + nt*8 + tg*2;
            float* p0 = &O[((size_t)b * CV_ + col) * NPIX_ + row];
            float* p1 = p0 + NPIX_;
            p0[0] = acc[mt][nt][0]; p1[0] = acc[mt][nt][1];
            p0[8] = acc[mt][nt][2]; p1[8] = acc[mt][nt][3];
        }
    }
}

// HMMA implicit-GEMM 3x3 conv. 128oc x 64px tile, 9 taps x K=16 per ic-chunk.
// Weights pre-packed by k_wprep into [tap][Cout][Cin] (hi|lo<<16).
__global__ __launch_bounds__(256) void k_conv_mma(
    const float* __restrict__ in, const unsigned* __restrict__ wp,
    const float* __restrict__ bias, float* __restrict__ out,
    int Cin, int Cout, int flags, const float* __restrict__ res) {
    extern __shared__ __nv_bfloat16 sm[];
    __nv_bfloat16* Hh = sm;             // [100 pos][18]
    __nv_bfloat16* Hl = sm + 1800;
    __nv_bfloat16* Wh = sm + 3600;      // [9*128 rows][18]
    __nv_bfloat16* Wl = sm + 24336;
    int tid = threadIdx.x, lane = tid & 31, w8 = tid >> 5;
    int wm = w8 & 3, wn = w8 >> 2;
    int gq = lane >> 2, tg = lane & 3;
    int b = blockIdx.z, t = blockIdx.y, oc0 = blockIdx.x << 7;
    int y0 = (t >> 3) << 3, x0 = (t & 7) << 3;
    float acc[8][4];
    #pragma unroll
    for (int j = 0; j < 8; j++)
        #pragma unroll
        for (int q = 0; q < 4; q++) acc[j][q] = 0.f;
    for (int ic0 = 0; ic0 < Cin; ic0 += 16) {
        for (int i = tid; i < 1600; i += 256) {
            int icl = i / 100, pos = i - icl * 100;
            int hy = pos / 10, hx = pos - hy * 10;
            int gy = y0 + hy - 1, gx = x0 + hx - 1;
            float v = ((unsigned)gy < 64u && (unsigned)gx < 64u)
                ? in[(((size_t)b * Cin + ic0 + icl) * 64 + gy) * 64 + gx] : 0.f;
            __nv_bfloat16 h = __float2bfloat16(v);
            Hh[pos * 18 + icl] = h;
            Hl[pos * 18 + icl] = __float2bfloat16(v - __bfloat162float(h));
        }
        for (int j = tid; j < 18432; j += 256) {
            int tap = j >> 11, rem = j & 2047;
            int oc = rem >> 4, icl = rem & 15;
            unsigned pk = wp[((size_t)tap * Cout + oc0 + oc) * Cin + ic0 + icl];
            unsigned short hb = (unsigned short)(pk & 0xFFFFu);
            unsigned short lb = (unsigned short)(pk >> 16);
            Wh[(tap * 128 + oc) * 18 + icl] = *(__nv_bfloat16*)&hb;
            Wl[(tap * 128 + oc) * 18 + icl] = *(__nv_bfloat16*)&lb;
        }
        __syncthreads();
        #pragma unroll
        for (int tap = 0; tap < 9; tap++) {
            int ky = tap / 3, kx = tap - ky * 3;
            int pA0 = ((wm * 2 + ky) * 10 + gq + kx) * 18 + tg * 2;
            int pA1 = pA0 + 180;
            unsigned ah[4], al[4];
            ah[0] = *(const unsigned*)&Hh[pA0];
            ah[1] = *(const unsigned*)&Hh[pA1];
            ah[2] = *(const unsigned*)&Hh[pA0 + 8];
            ah[3] = *(const unsigned*)&Hh[pA1 + 8];
            al[0] = *(const unsigned*)&Hl[pA0];
            al[1] = *(const unsigned*)&Hl[pA1];
            al[2] = *(const unsigned*)&Hl[pA0 + 8];
            al[3] = *(const unsigned*)&Hl[pA1 + 8];
            #pragma unroll
            for (int nt = 0; nt < 8; nt++) {
                int brow = (tap * 128 + wn * 64 + nt * 8 + gq) * 18 + tg * 2;
                unsigned b0 = *(const unsigned*)&Wh[brow];
                unsigned b1 = *(const unsigned*)&Wh[brow + 8];
                unsigned l0 = *(const unsigned*)&Wl[brow];
                unsigned l1 = *(const unsigned*)&Wl[brow + 8];
                mma16816(acc[nt], ah, b0, b1);
                mma16816(acc[nt], ah, l0, l1);
                mma16816(acc[nt], al, b0, b1);
            }
        }
        __syncthreads();
    }
    int yA = y0 + wm * 2, xA = x0 + gq;
    #pragma unroll
    for (int nt = 0; nt < 8; nt++) {
        int oc = oc0 + wn * 64 + nt * 8 + tg * 2;
        float b0 = bias[oc], b1 = bias[oc + 1];
        size_t a00 = (((size_t)b * Cout + oc) * 64 + yA) * 64 + xA;
        size_t a10 = a00 + 64;
        size_t a01 = a00 + 4096, a11 = a01 + 64;
        float v00 = acc[nt][0] + b0, v01 = acc[nt][1] + b1;
        float v10 = acc[nt][2] + b0, v11 = acc[nt][3] + b1;
        if (flags & 1) {
            v00 = fmaxf(v00, 0.f); v01 = fmaxf(v01, 0.f);
            v10 = fmaxf(v10, 0.f); v11 = fmaxf(v11, 0.f);
        }
        if (flags & 2) {
            v00 += res[a00]; v01 += res[a01];
            v10 += res[a10]; v11 += res[a11];
        }
        out[a00] = v00; out[a01] = v01;
        out[a10] = v10; out[a11] = v11;
    }
}

// scalar conv (seg: Cin=3)
__global__ void k_conv3(const float* __restrict__ in, const float* __restrict__ wgt,
                        const float* __restrict__ bias, float* __restrict__ out,
                        int Cin, int Cout, int flags, const float* __restrict__ res) {
    extern __shared__ float smf[];
    float* ws  = smf;
    float* ins = smf + 18432;
    int b = blockIdx.z, t = blockIdx.y, oc0 = blockIdx.x << 7;
    int y0 = (t >> 3) << 3, x0 = (t & 7) << 3, tid = threadIdx.x;
    int tx = tid & 15, ty = tid >> 4;
    int pyb = tx >> 1, pxb = (tx & 1) << 2;
    ull acc[4][4];
    #pragma unroll
    for (int p = 0; p < 4; p++)
        #pragma unroll
        for (int j = 0; j < 4; j++) acc[p][j] = 0ull;
    for (int ic0 = 0; ic0 < Cin; ic0 += 16) {
        for (int i = tid; i < 1600; i += 256) {
            int icl = i / 100, rem = i - icl * 100, hy = rem / 10, hx = rem - hy * 10;
            int gy = y0 + hy - 1, gx = x0 + hx - 1, ic = ic0 + icl;
            float v = 0.f;
            if (ic < Cin && (unsigned)gy < 64u && (unsigned)gx < 64u)
                v = in[(((size_t)b * Cin + ic) * 64 + gy) * 64 + gx];
            ins[i] = v;
        }
        for (int i = tid; i < 18432; i += 256) {
            int oc = i & 127, kk = i >> 7, icl = kk / 9, tap = kk - icl * 9, ic = ic0 + icl;
            ws[i] = (ic < Cin) ? wgt[(((size_t)(oc0 + oc)) * Cin + ic) * 9 + tap] : 0.f;
        }
        __syncthreads();
        int icm = (Cin - ic0 < 16) ? (Cin - ic0) : 16;
        for (int icl = 0; icl < icm; icl++) {
            ull xb[3][6];
            const float* iw = &ins[icl * 100 + pyb * 10 + pxb];
            #pragma unroll
            for (int ky = 0; ky < 3; ky++)
                #pragma unroll
                for (int c = 0; c < 6; c++) {
                    float v = iw[ky * 10 + c];
                    xb[ky][c] = pk2(v, v);
                }
            #pragma unroll
            for (int ky = 0; ky < 3; ky++)
                #pragma unroll
                for (int kx = 0; kx < 3; kx++) {
                    const float* wpv = &ws[(icl * 9 + ky * 3 + kx) * 128 + (ty << 3)];
                    ull w0 = *(const ull*)wpv, w1 = *(const ull*)(wpv + 2);
                    ull w2 = *(const ull*)(wpv + 4), w3 = *(const ull*)(wpv + 6);
                    #pragma unroll
                    for (int p = 0; p < 4; p++) {
                        ull xq = xb[ky][kx + p];
                        fma2(acc[p][0], xq, w0); fma2(acc[p][1], xq, w1);
                        fma2(acc[p][2], xq, w2); fma2(acc[p][3], xq, w3);
                    }
                }
        }
        __syncthreads();
    }
    #pragma unroll
    for (int j = 0; j < 4; j++) {
        int ocA = oc0 + (ty << 3) + 2 * j;
        float bA = bias[ocA], bB = bias[ocA + 1];
        size_t rowA = (((size_t)b * Cout + ocA) * 64 + y0 + pyb) * 64 + x0 + pxb;
        size_t rowB = rowA + 4096;
        #pragma unroll
        for (int p = 0; p < 4; p++) {
            float2 vpair = up2(acc[p][j]);
            float va = vpair.x + bA, vb = vpair.y + bB;
            if (flags & 1) { va = fmaxf(va, 0.f); vb = fmaxf(vb, 0.f); }
            if (flags & 2) { va += res[rowA + p]; vb += res[rowB + p]; }
            out[rowA + p] = va;
            out[rowB + p] = vb;
        }
    }
}

__global__ void k_instnorm(const float* __restrict__ x, float* __restrict__ st) {
    int row = blockIdx.x, tid = threadIdx.x;
    const float* p = x + (size_t)row * NPIX_;
    float s = 0.f, ss = 0.f;
    for (int i = tid; i < NPIX_; i += 256) { float v = p[i]; s += v; ss += v * v; }
    __shared__ float r1[256], r2[256];
    r1[tid] = s; r2[tid] = ss;
    __syncthreads();
    for (int k = 128; k > 0; k >>= 1) {
        if (tid < k) { r1[tid] += r1[tid+k]; r2[tid] += r2[tid+k]; }
        __syncthreads();
    }
    if (tid == 0) {
        float m = r1[0] * (1.f / NPIX_);
        float v = r2[0] * (1.f / NPIX_) - m * m;
        st[row*2] = m; st[row*2+1] = rsqrtf(v + 1e-5f);
    }
}

__global__ void k_spade_pono(const float* __restrict__ q, const float* __restrict__ gam,
                             const float* __restrict__ bet, const float* __restrict__ outat,
                             const float* __restrict__ conf, const float* __restrict__ innm,
                             float* __restrict__ y) {
    int b = blockIdx.x >> 6, n0 = (blockIdx.x & 63) << 6, tid = threadIdx.x;
    int nn = tid & 63, cp = tid >> 6;
    __shared__ float ps[4][64], pss[4][64], pm[64], pr[64];
    float cf = conf[(size_t)b * NPIX_ + n0 + nn];
    float s = 0.f, ss = 0.f;
    for (int base = 0; base < CV_; base += 4) {
        int cc = base + cp;
        size_t o = ((size_t)b * CV_ + cc) * NPIX_ + n0 + nn;
        float m = innm[(b*CV_+cc)*2], rs = innm[(b*CV_+cc)*2+1];
        float qv = q[o];
        float sp = (qv - m) * rs * (1.f + gam[o]) + bet[o];
        float tv = outat[o] + (1.f - cf) * sp + qv;
        s += tv; ss += tv * tv;
    }
    ps[cp][nn] = s; pss[cp][nn] = ss;
    __syncthreads();
    if (tid < 64) {
        float S = ps[0][tid]+ps[1][tid]+ps[2][tid]+ps[3][tid];
        float SS = pss[0][tid]+pss[1][tid]+pss[2][tid]+pss[3][tid];
        float m = S * (1.f/256.f), v = SS * (1.f/256.f) - m * m;
        pm[tid] = m; pr[tid] = rsqrtf(v + 1e-5f);
    }
    __syncthreads();
    float mmu = pm[nn], rr = pr[nn];
    for (int base = 0; base < CV_; base += 4) {
        int cc = base + cp;
        size_t o = ((size_t)b * CV_ + cc) * NPIX_ + n0 + nn;
        float m = innm[(b*CV_+cc)*2], rs = innm[(b*CV_+cc)*2+1];
        float qv = q[o];
        float sp = (qv - m) * rs * (1.f + gam[o]) + bet[o];
        float tv = outat[o] + (1.f - cf) * sp + qv;
        y[o] = (tv - mmu) * rr;
    }
}

extern "C" void kernel_launch(void* const* d_in, const int* in_sizes, int n_in,
                              void* d_out, int out_size) {
    const float *q = (const float*)d_in[0], *k = (const float*)d_in[1],
                *v = (const float*)d_in[2], *pos = (const float*)d_in[3],
                *seg = (const float*)d_in[4], *v2 = (const float*)d_in[5],
                *f_w = (const float*)d_in[6], *f_b = (const float*)d_in[7],
                *g_w = (const float*)d_in[8], *g_b = (const float*)d_in[9],
                *h_w = (const float*)d_in[10], *h_b = (const float*)d_in[11],
                *fp_w = (const float*)d_in[12], *fp_b = (const float*)d_in[13],
                *gp_w = (const float*)d_in[14], *gp_b = (const float*)d_in[15],
                *sp_s_w = (const float*)d_in[16], *sp_s_b = (const float*)d_in[17],
                *sp_g_w = (const float*)d_in[18], *sp_g_b = (const float*)d_in[19],
                *sp_b_w = (const float*)d_in[20], *sp_b_b = (const float*)d_in[21],
                *r1_w = (const float*)d_in[22], *r1_b = (const float*)d_in[23],
                *r2_w = (const float*)d_in[24], *r2_b = (const float*)d_in[25];
    float* S;
    cudaGetSymbolAddress((void**)&S, g_scratch);
    float* out_res  = (float*)d_out;
    float* out_out2 = out_res + 2097152;
    float* out_cor  = out_res + 4194304;
    unsigned char* mask = (unsigned char*)(S + OFF_MASK);
    __nv_bfloat16* VHI  = (__nv_bfloat16*)(S + OFF_VHI);
    __nv_bfloat16* VLO  = (__nv_bfloat16*)(S + OFF_VLO);
    __nv_bfloat16* V2HI = (__nv_bfloat16*)(S + OFF_V2HI);
    __nv_bfloat16* V2LO = (__nv_bfloat16*)(S + OFF_V2LO);
    __nv_bfloat16* QFH  = (__nv_bfloat16*)(S + OFF_QFH);
    __nv_bfloat16* QFL  = (__nv_bfloat16*)(S + OFF_QFL);
    __nv_bfloat16* KFH  = (__nv_bfloat16*)(S + OFF_KFH);
    __nv_bfloat16* KFL  = (__nv_bfloat16*)(S + OFF_KFL);
    unsigned* WR1 = (unsigned*)(S + OFF_WR1);
    unsigned* WR2 = (unsigned*)(S + OFF_WR2);
    unsigned* WG  = (unsigned*)(S + OFF_WG);
    unsigned* WB  = (unsigned*)(S + OFF_WB);
    cudaFuncSetAttribute(k_conv3, cudaFuncAttributeMaxDynamicSharedMemorySize, 80128);
    cudaFuncSetAttribute(k_av_mma, cudaFuncAttributeMaxDynamicSharedMemorySize, 73728);
    cudaFuncSetAttribute(k_cor_mma, cudaFuncAttributeMaxDynamicSharedMemorySize, 73728);
    cudaFuncSetAttribute(k_conv_mma, cudaFuncAttributeMaxDynamicSharedMemorySize, 90144);

    k_wprep<<<2304, 256>>>(r1_w, WR1, 256, 256);
    k_wprep<<<2304, 256>>>(r2_w, WR2, 256, 256);
    k_wprep<<<1152, 256>>>(sp_g_w, WG, 256, 128);
    k_wprep<<<1152, 256>>>(sp_b_w, WB, 256, 128);
    k_normcat<<<128, 256>>>(q, pos, S + OFF_QUERY);
    k_normcat<<<128, 256>>>(k, pos, S + OFF_KEYT);
    k_gemm<<<dim3(5,128), 256>>>(S + OFF_QUERY, f_w,  f_b,  S + OFF_QF, CQK_, CQK_);
    k_gemm<<<dim3(5,128), 256>>>(S + OFF_KEYT,  g_w,  g_b,  S + OFF_KF, CQK_, CQK_);
    k_gemm<<<dim3(1,128), 256>>>(S + OFF_QUERY, fp_w, fp_b, S + OFF_QP, CQK_, DP_);
    k_gemm<<<dim3(1,128), 256>>>(S + OFF_KEYT,  gp_w, gp_b, S + OFF_KP, CQK_, DP_);
    k_gemmW<<<dim3(4,64,2), 256>>>(v, h_w, h_b, S + OFF_VH);
    k_split<<<10240, 256>>>(S + OFF_QF, QFH, QFL);
    k_split<<<10240, 256>>>(S + OFF_KF, KFH, KFL);
    k_split<<<8192, 256>>>(S + OFF_VH, VHI, VLO);
    k_split<<<8192, 256>>>(v2, V2HI, V2LO);
    k_cor_mma<<<dim3(32,32,2), 256, 73728>>>(QFH, QFL, KFH, KFL, out_cor);
    k_mask<<<dim3(32,32,2), 256>>>(S + OFF_QP, S + OFF_KP, mask);
    k_rowstats<<<8192, 256>>>(out_cor, mask, S + OFF_STATS, S + OFF_CONF);
    k_av_mma<<<dim3(32,2,2), 256, 73728>>>(out_cor, mask, S + OFF_STATS, VHI, VLO, S + OFF_OUT, 0);
    k_av_mma<<<dim3(32,2,2), 256, 73728>>>(out_cor, mask, S + OFF_STATS, V2HI, V2LO, out_out2, 1);
    k_conv3<<<dim3(1,64,2), 256, 80128>>>(seg, sp_s_w, sp_s_b, S + OFF_ACTV, 3, 128, 1, nullptr);
    k_conv_mma<<<dim3(2,64,2), 256, 90144>>>(S + OFF_ACTV, WG, sp_g_b, S + OFF_GAMMA, 128, 256, 0, nullptr);
    k_conv_mma<<<dim3(2,64,2), 256, 90144>>>(S + OFF_ACTV, WB, sp_b_b, S + OFF_BETA,  128, 256, 0, nullptr);
    k_instnorm<<<512, 256>>>(q, S + OFF_INNM);
    k_spade_pono<<<128, 256>>>(q, S + OFF_GAMMA, S + OFF_BETA, S + OFF_OUT,
                               S + OFF_CONF, S + OFF_INNM, S + OFF_Y);
    k_conv_mma<<<dim3(2,64,2), 256, 90144>>>(S + OFF_Y,  WR1, r1_b, S + OFF_T1, 256, 256, 1, nullptr);
    k_conv_mma<<<dim3(2,64,2), 256, 90144>>>(S + OFF_T1, WR2, r2_b, out_res,    256, 256, 2, S + OFF_Y);
}

// round 12
// speedup vs baseline: 3.0287x; 1.0472x over previous
#include <cuda_runtime.h>
#include <cuda_bf16.h>
#include <math.h>

#define CV_   256
#define CQK_  320
#define DP_   64
#define NPIX_ 4096

#define OFF_QUERY  0u
#define OFF_KEYT   (OFF_QUERY + 2621440u)
#define OFF_QN     (OFF_KEYT  + 2621440u)   // QNH(1310720) + QNL(1310720)
#define OFF_KN     (OFF_QN    + 2621440u)
#define OFF_QP     (OFF_KN    + 2621440u)
#define OFF_KP     (OFF_QP    + 524288u)
#define OFF_VH     (OFF_KP    + 524288u)
#define OFF_STATS  (OFF_VH    + 2097152u)
#define OFF_CONF   (OFF_STATS + 32768u)
#define OFF_OUT    (OFF_CONF  + 8192u)
#define OFF_ACTV   (OFF_OUT   + 2097152u)
#define OFF_GAMMA  (OFF_ACTV  + 1048576u)
#define OFF_BETA   (OFF_GAMMA + 2097152u)
#define OFF_Y      (OFF_BETA  + 2097152u)
#define OFF_T1     (OFF_Y     + 2097152u)
#define OFF_INNM   (OFF_T1    + 2097152u)
#define OFF_MASK   (OFF_INNM  + 1024u)
#define OFF_VHI    (OFF_MASK  + 8388608u)
#define OFF_VLO    (OFF_VHI   + 1048576u)
#define OFF_V2HI   (OFF_VLO   + 1048576u)
#define OFF_V2LO   (OFF_V2HI  + 1048576u)
#define OFF_QFH    (OFF_V2LO  + 1048576u)
#define OFF_QFL    (OFF_QFH   + 1310720u)
#define OFF_KFH    (OFF_QFL   + 1310720u)
#define OFF_KFL    (OFF_KFH   + 1310720u)
#define OFF_WR1    (OFF_KFL   + 1310720u)
#define OFF_WR2    (OFF_WR1   + 589824u)
#define OFF_WG     (OFF_WR2   + 589824u)
#define OFF_WB     (OFF_WG    + 294912u)
#define OFF_WF1    (OFF_WB    + 294912u)
#define OFF_WG1    (OFF_WF1   + 102400u)
#define SCRATCH_FLOATS (OFF_WG1 + 102400u)

__device__ float g_scratch[SCRATCH_FLOATS];

typedef unsigned long long ull;
__device__ __forceinline__ ull pk2(float lo, float hi) {
    ull r; asm("mov.b64 %0,{%1,%2};" : "=l"(r) : "f"(lo), "f"(hi)); return r;
}
__device__ __forceinline__ void fma2(ull& d, ull a, ull b) {
    asm("fma.rn.f32x2 %0,%1,%2,%0;" : "+l"(d) : "l"(a), "l"(b));
}
__device__ __forceinline__ float2 up2(ull v) {
    float2 f; asm("mov.b64 {%0,%1},%2;" : "=f"(f.x), "=f"(f.y) : "l"(v)); return f;
}
__device__ __forceinline__ unsigned bfp(float a, float b) {
    __nv_bfloat162 t = __floats2bfloat162_rn(a, b); return *(unsigned*)&t;
}
__device__ __forceinline__ void mma16816(float* c, const unsigned* a, unsigned b0, unsigned b1) {
    asm volatile("mma.sync.aligned.m16n8k16.row.col.f32.bf16.bf16.f32 "
        "{%0,%1,%2,%3},{%4,%5,%6,%7},{%8,%9},{%0,%1,%2,%3};"
        : "+f"(c[0]), "+f"(c[1]), "+f"(c[2]), "+f"(c[3])
        : "r"(a[0]), "r"(a[1]), "r"(a[2]), "r"(a[3]), "r"(b0), "r"(b1));
}

// normalize + concat pos; writes fp32 AND bf16 hi/lo split
__global__ void k_normcat(const float* __restrict__ src, const float* __restrict__ pos,
                          float* __restrict__ dst, __nv_bfloat16* __restrict__ dh,
                          __nv_bfloat16* __restrict__ dl) {
    int b = blockIdx.x >> 6, n0 = (blockIdx.x & 63) << 6, tid = threadIdx.x;
    __shared__ float red[4][64], rnorm[64];
    int nn = tid & 63, cp = tid >> 6;
    const float* sp = src + (size_t)b * CV_ * NPIX_ + n0 + nn;
    float acc = 0.f;
    for (int c = cp; c < CV_; c += 4) { float x = sp[(size_t)c * NPIX_]; acc += x * x; }
    red[cp][nn] = acc;
    __syncthreads();
    if (tid < 64) {
        float s = red[0][tid] + red[1][tid] + red[2][tid] + red[3][tid];
        rnorm[tid] = 1.f / (sqrtf(s) + 2.220446049250313e-16f);
    }
    __syncthreads();
    for (int i = 0; i < 80; i++) {
        int idx = i * 256 + tid, n = idx / CQK_, c = idx - n * CQK_;
        float v = (c < CV_) ? src[(size_t)(b * CV_ + c) * NPIX_ + n0 + n] * rnorm[n]
                            : pos[(size_t)(c - CV_) * NPIX_ + n0 + n];
        size_t o = ((size_t)b * NPIX_ + n0 + n) * CQK_ + c;
        dst[o] = v;
        __nv_bfloat16 h = __float2bfloat16(v);
        dh[o] = h;
        dl[o] = __float2bfloat16(v - __bfloat162float(h));
    }
}

__global__ void k_gemm(const float* __restrict__ A, const float* __restrict__ W,
                       const float* __restrict__ bias, float* __restrict__ C, int K, int O) {
    __shared__ float As[16][64], Ws[16][64];
    int p0 = blockIdx.y << 6, o0 = blockIdx.x << 6, tid = threadIdx.x;
    int tx4 = (tid & 15) * 4, ty4 = (tid >> 4) * 4;
    ull acc[4][2];
    #pragma unroll
    for (int i = 0; i < 4; i++) { acc[i][0] = 0ull; acc[i][1] = 0ull; }
    for (int k0 = 0; k0 < K; k0 += 16) {
        #pragma unroll
        for (int i = 0; i < 4; i++) {
            int idx = i * 256 + tid, pp = idx >> 4, kk = idx & 15;
            As[kk][pp] = A[(size_t)(p0 + pp) * K + k0 + kk];
            Ws[kk][pp] = W[(size_t)(o0 + pp) * K + k0 + kk];
        }
        __syncthreads();
        #pragma unroll
        for (int kk = 0; kk < 16; kk++) {
            float4 a = *(const float4*)&As[kk][ty4];
            ull b0 = *(const ull*)&Ws[kk][tx4];
            ull b1 = *(const ull*)&Ws[kk][tx4 + 2];
            float av[4] = {a.x, a.y, a.z, a.w};
            #pragma unroll
            for (int ii = 0; ii < 4; ii++) {
                ull pa = pk2(av[ii], av[ii]);
                fma2(acc[ii][0], pa, b0);
                fma2(acc[ii][1], pa, b1);
            }
        }
        __syncthreads();
    }
    for (int ii = 0; ii < 4; ii++) {
        float2 q0 = up2(acc[ii][0]), q1 = up2(acc[ii][1]);
        float4 r;
        r.x = q0.x + bias[o0+tx4+0]; r.y = q0.y + bias[o0+tx4+1];
        r.z = q1.x + bias[o0+tx4+2]; r.w = q1.y + bias[o0+tx4+3];
        *(float4*)&C[(size_t)(p0 + ty4 + ii) * O + o0 + tx4] = r;
    }
}

__global__ void k_gemmW(const float* __restrict__ A, const float* __restrict__ W,
                        const float* __restrict__ bias, float* __restrict__ C) {
    __shared__ float As[16][64], Ws[16][64];
    int b = blockIdx.z, o0 = blockIdx.x << 6, p0 = blockIdx.y << 6, tid = threadIdx.x;
    int tx4 = (tid & 15) * 4, ty4 = (tid >> 4) * 4;
    ull acc[4][2];
    #pragma unroll
    for (int i = 0; i < 4; i++) { acc[i][0] = 0ull; acc[i][1] = 0ull; }
    for (int k0 = 0; k0 < 256; k0 += 16) {
        #pragma unroll
        for (int i = 0; i < 4; i++) {
            int idx = i * 256 + tid;
            int kk = idx >> 6, pp = idx & 63;
            As[kk][pp] = A[((size_t)b * 256 + k0 + kk) * NPIX_ + p0 + pp];
            int oo = idx >> 4, k2 = idx & 15;
            Ws[k2][oo] = W[(size_t)(o0 + oo) * 256 + k0 + k2];
        }
        __syncthreads();
        #pragma unroll
        for (int kk = 0; kk < 16; kk++) {
            float4 w = *(const float4*)&Ws[kk][ty4];
            ull a0 = *(const ull*)&As[kk][tx4], a1 = *(const ull*)&As[kk][tx4 + 2];
            float wv[4] = {w.x, w.y, w.z, w.w};
            #pragma unroll
            for (int oi = 0; oi < 4; oi++) {
                ull pw = pk2(wv[oi], wv[oi]);
                fma2(acc[oi][0], pw, a0);
                fma2(acc[oi][1], pw, a1);
            }
        }
        __syncthreads();
    }
    for (int oi = 0; oi < 4; oi++) {
        float bv = bias[o0 + ty4 + oi];
        float2 q0 = up2(acc[oi][0]), q1 = up2(acc[oi][1]);
        float4 r = {q0.x + bv, q0.y + bv, q1.x + bv, q1.y + bv};
        *(float4*)&C[((size_t)b * 256 + o0 + ty4 + oi) * NPIX_ + p0 + tx4] = r;
    }
}

__global__ void k_split(const float* __restrict__ x, __nv_bfloat16* __restrict__ hi,
                        __nv_bfloat16* __restrict__ lo) {
    int i = blockIdx.x * 256 + threadIdx.x;
    float v = x[i];
    __nv_bfloat16 h = __float2bfloat16(v);
    hi[i] = h;
    lo[i] = __float2bfloat16(v - __bfloat162float(h));
}

__global__ void k_wprep(const float* __restrict__ w, unsigned* __restrict__ o,
                        int Cout, int Cin) {
    int i = blockIdx.x * 256 + threadIdx.x;
    int tot = Cout * Cin * 9;
    if (i >= tot) return;
    int tap = i % 9, t2 = i / 9;
    int ic = t2 % Cin, oc = t2 / Cin;
    float v = w[i];
    __nv_bfloat16 h = __float2bfloat16(v);
    __nv_bfloat16 l = __float2bfloat16(v - __bfloat162float(h));
    unsigned pk = (unsigned)*(unsigned short*)&h | ((unsigned)*(unsigned short*)&l << 16);
    o[((size_t)tap * Cout + oc) * Cin + ic] = pk;
}

// 1x1 weights [o][k] fp32 -> u32 hi|lo same layout
__global__ void k_wprep1(const float* __restrict__ w, unsigned* __restrict__ o, int tot) {
    int i = blockIdx.x * 256 + threadIdx.x;
    if (i >= tot) return;
    float v = w[i];
    __nv_bfloat16 h = __float2bfloat16(v);
    __nv_bfloat16 l = __float2bfloat16(v - __bfloat162float(h));
    o[i] = (unsigned)*(unsigned short*)&h | ((unsigned)*(unsigned short*)&l << 16);
}

// HMMA 1x1 feature GEMM: C[p][o] = A[p][:]·W[o][:] + bias, split-bf16 output
__global__ __launch_bounds__(256) void k_gemm_mma(
    const __nv_bfloat16* __restrict__ anh, const __nv_bfloat16* __restrict__ anl,
    const unsigned* __restrict__ wp, const float* __restrict__ bias,
    __nv_bfloat16* __restrict__ oh, __nv_bfloat16* __restrict__ ol, int K, int Ost) {
    extern __shared__ __nv_bfloat16 sm[];
    __nv_bfloat16* Ah = sm;            // [128][72]
    __nv_bfloat16* Al = sm + 9216;
    __nv_bfloat16* Wh = sm + 18432;    // [64][72]
    __nv_bfloat16* Wl = sm + 23040;
    int tid = threadIdx.x, lane = tid & 31, w = tid >> 5;
    int wm = w & 3, wn = w >> 2;
    int gq = lane >> 2, tg = lane & 3;
    int p0 = blockIdx.x << 7, o0 = blockIdx.y << 6;
    int r = tid >> 1, hh = tid & 1;
    const __nv_bfloat16* A0 = anh + (size_t)(p0 + r) * K + hh * 32;
    const __nv_bfloat16* A1 = anl + (size_t)(p0 + r) * K + hh * 32;
    float acc[2][4][4];
    #pragma unroll
    for (int i = 0; i < 2; i++)
        #pragma unroll
        for (int j = 0; j < 4; j++)
            #pragma unroll
            for (int t = 0; t < 4; t++) acc[i][j][t] = 0.f;
    for (int kc = 0; kc < K; kc += 64) {
        {
            const uint4* s0 = (const uint4*)(A0 + kc);
            const uint4* s1 = (const uint4*)(A1 + kc);
            uint4* d0 = (uint4*)&Ah[r * 72 + hh * 32];
            uint4* d1 = (uint4*)&Al[r * 72 + hh * 32];
            #pragma unroll
            for (int i = 0; i < 4; i++) { d0[i] = s0[i]; d1[i] = s1[i]; }
        }
        for (int j = tid; j < 4096; j += 256) {
            int oc = j >> 6, kk = j & 63;
            unsigned pk = wp[(size_t)(o0 + oc) * K + kc + kk];
            unsigned short hb = (unsigned short)(pk & 0xFFFFu);
            unsigned short lb = (unsigned short)(pk >> 16);
            Wh[oc * 72 + kk] = *(__nv_bfloat16*)&hb;
            Wl[oc * 72 + kk] = *(__nv_bfloat16*)&lb;
        }
        __syncthreads();
        #pragma unroll
        for (int ks = 0; ks < 4; ks++) {
            int k16 = ks << 4;
            unsigned ah[2][4], al[2][4];
            #pragma unroll
            for (int mt = 0; mt < 2; mt++) {
                const __nv_bfloat16* pa = &Ah[(wm*32 + mt*16 + gq) * 72 + k16 + tg*2];
                ah[mt][0] = *(const unsigned*)pa;
                ah[mt][1] = *(const unsigned*)(pa + 8*72);
                ah[mt][2] = *(const unsigned*)(pa + 8);
                ah[mt][3] = *(const unsigned*)(pa + 8*72 + 8);
                const __nv_bfloat16* pl = &Al[(wm*32 + mt*16 + gq) * 72 + k16 + tg*2];
                al[mt][0] = *(const unsigned*)pl;
                al[mt][1] = *(const unsigned*)(pl + 8*72);
                al[mt][2] = *(const unsigned*)(pl + 8);
                al[mt][3] = *(const unsigned*)(pl + 8*72 + 8);
            }
            #pragma unroll
            for (int nt = 0; nt < 4; nt++) {
                int brow = (wn*32 + nt*8 + gq) * 72 + k16 + tg*2;
                unsigned b0 = *(const unsigned*)&Wh[brow];
                unsigned b1 = *(const unsigned*)&Wh[brow + 8];
                unsigned l0 = *(const unsigned*)&Wl[brow];
                unsigned l1 = *(const unsigned*)&Wl[brow + 8];
                #pragma unroll
                for (int mt = 0; mt < 2; mt++) {
                    mma16816(acc[mt][nt], ah[mt], b0, b1);
                    mma16816(acc[mt][nt], ah[mt], l0, l1);
                    mma16816(acc[mt][nt], al[mt], b0, b1);
                }
            }
        }
        __syncthreads();
    }
    #pragma unroll
    for (int mt = 0; mt < 2; mt++) {
        int row = p0 + wm*32 + mt*16 + gq;
        #pragma unroll
        for (int nt = 0; nt < 4; nt++) {
            int col = o0 + wn*32 + nt*8 + tg*2;
            float bv0 = bias[col], bv1 = bias[col + 1];
            #pragma unroll
            for (int half = 0; half < 2; half++) {
                int rr = row + half * 8;
                float v0 = acc[mt][nt][half*2]   + bv0;
                float v1 = acc[mt][nt][half*2+1] + bv1;
                __nv_bfloat16 h0 = __float2bfloat16(v0);
                __nv_bfloat16 h1 = __float2bfloat16(v1);
                size_t o = (size_t)rr * Ost + col;
                oh[o] = h0; oh[o+1] = h1;
                ol[o]   = __float2bfloat16(v0 - __bfloat162float(h0));
                ol[o+1] = __float2bfloat16(v1 - __bfloat162float(h1));
            }
        }
    }
}

// HMMA: cor = (QfH+QfL)·(KfH+KfL)^T / sqrt(320)
__global__ __launch_bounds__(256) void k_cor_mma(
    const __nv_bfloat16* __restrict__ qh, const __nv_bfloat16* __restrict__ ql,
    const __nv_bfloat16* __restrict__ kh, const __nv_bfloat16* __restrict__ kl,
    float* __restrict__ cor) {
    extern __shared__ __nv_bfloat16 sm[];
    __nv_bfloat16* Ah = sm;
    __nv_bfloat16* Al = sm + 9216;
    __nv_bfloat16* Bh = sm + 18432;
    __nv_bfloat16* Bl = sm + 27648;
    int tid = threadIdx.x, lane = tid & 31, w = tid >> 5;
    int wm = w & 3, wn = w >> 2;
    int gq = lane >> 2, tg = lane & 3;
    int b = blockIdx.z, n0 = blockIdx.x << 7, m0 = blockIdx.y << 7;
    int r = tid >> 1, hh = tid & 1;
    const __nv_bfloat16* A0 = qh + ((size_t)(b * NPIX_) + n0 + r) * CQK_ + hh * 32;
    const __nv_bfloat16* A1 = ql + ((size_t)(b * NPIX_) + n0 + r) * CQK_ + hh * 32;
    const __nv_bfloat16* B0 = kh + ((size_t)(b * NPIX_) + m0 + r) * CQK_ + hh * 32;
    const __nv_bfloat16* B1 = kl + ((size_t)(b * NPIX_) + m0 + r) * CQK_ + hh * 32;
    float acc[2][8][4];
    #pragma unroll
    for (int i = 0; i < 2; i++)
        #pragma unroll
        for (int j = 0; j < 8; j++)
            #pragma unroll
            for (int t = 0; t < 4; t++) acc[i][j][t] = 0.f;
    for (int kc = 0; kc < CQK_; kc += 64) {
        {
            const uint4* s0 = (const uint4*)(A0 + kc);
            const uint4* s1 = (const uint4*)(A1 + kc);
            const uint4* s2 = (const uint4*)(B0 + kc);
            const uint4* s3 = (const uint4*)(B1 + kc);
            uint4* d0 = (uint4*)&Ah[r * 72 + hh * 32];
            uint4* d1 = (uint4*)&Al[r * 72 + hh * 32];
            uint4* d2 = (uint4*)&Bh[r * 72 + hh * 32];
            uint4* d3 = (uint4*)&Bl[r * 72 + hh * 32];
            #pragma unroll
            for (int i = 0; i < 4; i++) {
                d0[i] = s0[i]; d1[i] = s1[i]; d2[i] = s2[i]; d3[i] = s3[i];
            }
        }
        __syncthreads();
        #pragma unroll
        for (int ks = 0; ks < 4; ks++) {
            int k16 = ks << 4;
            unsigned ah[2][4], al[2][4];
            #pragma unroll
            for (int mt = 0; mt < 2; mt++) {
                const __nv_bfloat16* pa = &Ah[(wm*32 + mt*16 + gq) * 72 + k16 + tg*2];
                ah[mt][0] = *(const unsigned*)pa;
                ah[mt][1] = *(const unsigned*)(pa + 8*72);
                ah[mt][2] = *(const unsigned*)(pa + 8);
                ah[mt][3] = *(const unsigned*)(pa + 8*72 + 8);
                const __nv_bfloat16* pl = &Al[(wm*32 + mt*16 + gq) * 72 + k16 + tg*2];
                al[mt][0] = *(const unsigned*)pl;
                al[mt][1] = *(const unsigned*)(pl + 8*72);
                al[mt][2] = *(const unsigned*)(pl + 8);
                al[mt][3] = *(const unsigned*)(pl + 8*72 + 8);
            }
            #pragma unroll
            for (int nt = 0; nt < 8; nt++) {
                const __nv_bfloat16* pb = &Bh[(wn*64 + nt*8 + gq) * 72 + k16 + tg*2];
                unsigned b0 = *(const unsigned*)pb;
                unsigned b1 = *(const unsigned*)(pb + 8);
                const __nv_bfloat16* pbl = &Bl[(wn*64 + nt*8 + gq) * 72 + k16 + tg*2];
                unsigned l0 = *(const unsigned*)pbl;
                unsigned l1 = *(const unsigned*)(pbl + 8);
                #pragma unroll
                for (int mt = 0; mt < 2; mt++) {
                    mma16816(acc[mt][nt], ah[mt], b0, b1);
                    mma16816(acc[mt][nt], ah[mt], l0, l1);
                    mma16816(acc[mt][nt], al[mt], b0, b1);
                }
            }
        }
        __syncthreads();
    }
    const float s = 0.05590169943749474f;
    #pragma unroll
    for (int mt = 0; mt < 2; mt++) {
        int row = n0 + wm*32 + mt*16 + gq;
        #pragma unroll
        for (int nt = 0; nt < 8; nt++) {
            int col = m0 + wn*64 + nt*8 + tg*2;
            float2 v0 = {acc[mt][nt][0]*s, acc[mt][nt][1]*s};
            float2 v1 = {acc[mt][nt][2]*s, acc[mt][nt][3]*s};
            *(float2*)&cor[((size_t)(b * NPIX_) + row) * NPIX_ + col] = v0;
            *(float2*)&cor[((size_t)(b * NPIX_) + row + 8) * NPIX_ + col] = v1;
        }
    }
}

__global__ void k_mask(const float* __restrict__ Qp, const float* __restrict__ Kp,
                       unsigned char* __restrict__ mask) {
    __shared__ float As[8][132], Bs[8][132];
    int b = blockIdx.z, n0 = blockIdx.y << 7, m0 = blockIdx.x << 7;
    int tid = threadIdx.x, tx = tid & 15, ty = tid >> 4;
    int r = tid >> 1, kq = (tid & 1) << 2;
    const float* A  = Qp + (size_t)(b * NPIX_ + n0) * DP_;
    const float* Bk = Kp + (size_t)(b * NPIX_ + m0) * DP_;
    ull acc[8][4];
    #pragma unroll
    for (int i = 0; i < 8; i++)
        #pragma unroll
        for (int j = 0; j < 4; j++) acc[i][j] = 0ull;
    for (int k0 = 0; k0 < DP_; k0 += 8) {
        float4 av = *(const float4*)&A [(size_t)r * DP_ + k0 + kq];
        float4 bv = *(const float4*)&Bk[(size_t)r * DP_ + k0 + kq];
        As[kq+0][r] = av.x; As[kq+1][r] = av.y; As[kq+2][r] = av.z; As[kq+3][r] = av.w;
        Bs[kq+0][r] = bv.x; Bs[kq+1][r] = bv.y; Bs[kq+2][r] = bv.z; Bs[kq+3][r] = bv.w;
        __syncthreads();
        #pragma unroll
        for (int kk = 0; kk < 8; kk++) {
            float4 a0 = *(const float4*)&As[kk][ty << 3];
            float4 a1 = *(const float4*)&As[kk][(ty << 3) + 4];
            ull bb[4];
            #pragma unroll
            for (int j = 0; j < 4; j++) bb[j] = *(const ull*)&Bs[kk][(tx << 3) + 2*j];
            float aa[8] = {a0.x,a0.y,a0.z,a0.w,a1.x,a1.y,a1.z,a1.w};
            #pragma unroll
            for (int i = 0; i < 8; i++) {
                ull pa = pk2(aa[i], aa[i]);
                #pragma unroll
                for (int j = 0; j < 4; j++) fma2(acc[i][j], pa, bb[j]);
            }
        }
        __syncthreads();
    }
    #pragma unroll
    for (int i = 0; i < 8; i++) {
        int n = n0 + (ty << 3) + i;
        float2 p0 = up2(acc[i][0]), p1 = up2(acc[i][1]), p2 = up2(acc[i][2]), p3 = up2(acc[i][3]);
        unsigned lo = (p0.x>0.f?1u:0u) | ((p0.y>0.f?1u:0u)<<8) | ((p1.x>0.f?1u:0u)<<16) | ((p1.y>0.f?1u:0u)<<24);
        unsigned hi = (p2.x>0.f?1u:0u) | ((p2.y>0.f?1u:0u)<<8) | ((p3.x>0.f?1u:0u)<<16) | ((p3.y>0.f?1u:0u)<<24);
        unsigned char* dst = &mask[((size_t)b * NPIX_ + n) * NPIX_ + m0 + (tx << 3)];
        *(unsigned*)dst = lo; *(unsigned*)(dst + 4) = hi;
    }
}

__global__ void k_rowstats(const float* __restrict__ cor, const unsigned char* __restrict__ mask,
                           float* __restrict__ stats, float* __restrict__ conf) {
    int row = blockIdx.x, tid = threadIdx.x;
    const float* r = cor + (size_t)row * NPIX_;
    const unsigned char* mk = mask + (size_t)row * NPIX_;
    __shared__ float sa[256], sb[256], sc[256];
    float mx1 = -3.0e38f, mx2 = -3.0e38f;
    for (int m = tid; m < NPIX_; m += 256) {
        float x = r[m];
        mx1 = fmaxf(mx1, x);
        mx2 = fmaxf(mx2, mk[m] ? -10000.f : x);
    }
    sa[tid] = mx1; sb[tid] = mx2;
    __syncthreads();
    for (int s = 128; s > 0; s >>= 1) {
        if (tid < s) { sa[tid] = fmaxf(sa[tid], sa[tid+s]); sb[tid] = fmaxf(sb[tid], sb[tid+s]); }
        __syncthreads();
    }
    mx1 = sa[0]; mx2 = sb[0];
    __syncthreads();
    float s1 = 0.f, sm = 0.f, s2 = 0.f;
    for (int m = tid; m < NPIX_; m += 256) {
        float x = r[m], mv = mk[m] ? 1.f : 0.f;
        float e1 = __expf(x - mx1);
        s1 += e1; sm += mv * e1;
        s2 += __expf((mv > 0.f ? -10000.f : x) - mx2);
    }
    sa[tid] = s1; sb[tid] = sm; sc[tid] = s2;
    __syncthreads();
    for (int s = 128; s > 0; s >>= 1) {
        if (tid < s) { sa[tid] += sa[tid+s]; sb[tid] += sb[tid+s]; sc[tid] += sc[tid+s]; }
        __syncthreads();
    }
    if (tid == 0) {
        stats[row*4+0] = mx1; stats[row*4+1] = 1.f / sa[0];
        stats[row*4+2] = mx2; stats[row*4+3] = 1.f / sc[0];
        conf[row] = sb[0] / sa[0];
    }
}

__global__ __launch_bounds__(256) void k_av_mma(
    const float* __restrict__ cor, const unsigned char* __restrict__ mask,
    const float* __restrict__ stats, const __nv_bfloat16* __restrict__ vhi,
    const __nv_bfloat16* __restrict__ vlo, float* __restrict__ O, int g) {
    extern __shared__ __nv_bfloat16 sm[];
    __nv_bfloat16* Ah = sm;
    __nv_bfloat16* Al = sm + 9216;
    __nv_bfloat16* Bh = sm + 18432;
    __nv_bfloat16* Bl = sm + 27648;
    int tid = threadIdx.x, lane = tid & 31, w = tid >> 5;
    int wm = w & 3, wn = w >> 2;
    int gq = lane >> 2, tg = lane & 3;
    int b = blockIdx.z, n0 = blockIdx.x << 7, c0 = blockIdx.y << 7;
    int r = tid >> 1, ml0 = (tid & 1) << 5;
    float mx = stats[((size_t)b * NPIX_ + n0 + r) * 4 + g * 2];
    float iv = stats[((size_t)b * NPIX_ + n0 + r) * 4 + g * 2 + 1];
    const float* C = cor + ((size_t)(b * NPIX_ + n0) + r) * NPIX_;
    const unsigned char* M = mask + ((size_t)(b * NPIX_ + n0) + r) * NPIX_;
    int bc = tid & 127, bhh = tid >> 7;
    const __nv_bfloat16* BHsrc = vhi + ((size_t)b * CV_ + c0 + bc) * NPIX_ + bhh * 32;
    const __nv_bfloat16* BLsrc = vlo + ((size_t)b * CV_ + c0 + bc) * NPIX_ + bhh * 32;
    float acc[2][8][4];
    #pragma unroll
    for (int i = 0; i < 2; i++)
        #pragma unroll
        for (int j = 0; j < 8; j++)
            #pragma unroll
            for (int t = 0; t < 4; t++) acc[i][j][t] = 0.f;
    for (int ch = 0; ch < 64; ch++) {
        int m0 = ch << 6;
        #pragma unroll
        for (int j = 0; j < 16; j++) {
            float2 cv = *(const float2*)&C[m0 + ml0 + 2*j];
            unsigned char q0 = M[m0 + ml0 + 2*j], q1 = M[m0 + ml0 + 2*j + 1];
            float w0, w1;
            if (g == 0) {
                w0 = q0 ? __expf(cv.x - mx) * iv : 0.f;
                w1 = q1 ? __expf(cv.y - mx) * iv : 0.f;
            } else {
                w0 = __expf((q0 ? -10000.f : cv.x) - mx) * iv;
                w1 = __expf((q1 ? -10000.f : cv.y) - mx) * iv;
            }
            float h0 = __bfloat162float(__float2bfloat16(w0));
            float h1 = __bfloat162float(__float2bfloat16(w1));
            int off = r * 72 + ml0 + 2*j;
            *(unsigned*)&Ah[off] = bfp(w0, w1);
            *(unsigned*)&Al[off] = bfp(w0 - h0, w1 - h1);
        }
        {
            const uint4* sh = (const uint4*)(BHsrc + m0);
            const uint4* sl = (const uint4*)(BLsrc + m0);
            uint4* dh = (uint4*)&Bh[bc * 72 + bhh * 32];
            uint4* dl = (uint4*)&Bl[bc * 72 + bhh * 32];
            dh[0] = sh[0]; dh[1] = sh[1]; dh[2] = sh[2]; dh[3] = sh[3];
            dl[0] = sl[0]; dl[1] = sl[1]; dl[2] = sl[2]; dl[3] = sl[3];
        }
        __syncthreads();
        #pragma unroll
        for (int ks = 0; ks < 4; ks++) {
            int k16 = ks << 4;
            unsigned ah[2][4], al[2][4];
            #pragma unroll
            for (int mt = 0; mt < 2; mt++) {
                const __nv_bfloat16* pa = &Ah[(wm*32 + mt*16 + gq) * 72 + k16 + tg*2];
                ah[mt][0] = *(const unsigned*)pa;
                ah[mt][1] = *(const unsigned*)(pa + 8*72);
                ah[mt][2] = *(const unsigned*)(pa + 8);
                ah[mt][3] = *(const unsigned*)(pa + 8*72 + 8);
                const __nv_bfloat16* pl = &Al[(wm*32 + mt*16 + gq) * 72 + k16 + tg*2];
                al[mt][0] = *(const unsigned*)pl;
                al[mt][1] = *(const unsigned*)(pl + 8*72);
                al[mt][2] = *(const unsigned*)(pl + 8);
                al[mt][3] = *(const unsigned*)(pl + 8*72 + 8);
            }
            #pragma unroll
            for (int nt = 0; nt < 8; nt++) {
                const __nv_bfloat16* pb = &Bh[(wn*64 + nt*8 + gq) * 72 + k16 + tg*2];
                unsigned b0 = *(const unsigned*)pb;
                unsigned b1 = *(const unsigned*)(pb + 8);
                const __nv_bfloat16* pbl = &Bl[(wn*64 + nt*8 + gq) * 72 + k16 + tg*2];
                unsigned l0 = *(const unsigned*)pbl;
                unsigned l1 = *(const unsigned*)(pbl + 8);
                #pragma unroll
                for (int mt = 0; mt < 2; mt++) {
                    mma16816(acc[mt][nt], ah[mt], b0, b1);
                    mma16816(acc[mt][nt], ah[mt], l0, l1);
                    mma16816(acc[mt][nt], al[mt], b0, b1);
                }
            }
        }
        __syncthreads();
    }
    #pragma unroll
    for (int mt = 0; mt < 2; mt++) {
        int row = n0 + wm*32 + mt*16 + gq;
        #pragma unroll
        for (int nt = 0; nt < 8; nt++) {
            int col = c0 + wn*64 + nt*8 + tg*2;
            float* p0 = &O[((size_t)b * CV_ + col) * NPIX_ + row];
            float* p1 = p0 + NPIX_;
            p0[0] = acc[mt][nt][0]; p1[0] = acc[mt][nt][1];
            p0[8] = acc[mt][nt][2]; p1[8] = acc[mt][nt][3];
        }
    }
}

__global__ __launch_bounds__(256) void k_conv_mma(
    const float* __restrict__ in, const unsigned* __restrict__ wp,
    const float* __restrict__ bias, float* __restrict__ out,
    int Cin, int Cout, int flags, const float* __restrict__ res) {
    extern __shared__ __nv_bfloat16 sm[];
    __nv_bfloat16* Hh = sm;
    __nv_bfloat16* Hl = sm + 1800;
    __nv_bfloat16* Wh = sm + 3600;
    __nv_bfloat16* Wl = sm + 24336;
    int tid = threadIdx.x, lane = tid & 31, w8 = tid >> 5;
    int wm = w8 & 3, wn = w8 >> 2;
    int gq = lane >> 2, tg = lane & 3;
    int b = blockIdx.z, t = blockIdx.y, oc0 = blockIdx.x << 7;
    int y0 = (t >> 3) << 3, x0 = (t & 7) << 3;
    float acc[8][4];
    #pragma unroll
    for (int j = 0; j < 8; j++)
        #pragma unroll
        for (int q = 0; q < 4; q++) acc[j][q] = 0.f;
    for (int ic0 = 0; ic0 < Cin; ic0 += 16) {
        for (int i = tid; i < 1600; i += 256) {
            int icl = i / 100, pos = i - icl * 100;
            int hy = pos / 10, hx = pos - hy * 10;
            int gy = y0 + hy - 1, gx = x0 + hx - 1;
            float v = ((unsigned)gy < 64u && (unsigned)gx < 64u)
                ? in[(((size_t)b * Cin + ic0 + icl) * 64 + gy) * 64 + gx] : 0.f;
            __nv_bfloat16 h = __float2bfloat16(v);
            Hh[pos * 18 + icl] = h;
            Hl[pos * 18 + icl] = __float2bfloat16(v - __bfloat162float(h));
        }
        for (int j = tid; j < 18432; j += 256) {
            int tap = j >> 11, rem = j & 2047;
            int oc = rem >> 4, icl = rem & 15;
            unsigned pk = wp[((size_t)tap * Cout + oc0 + oc) * Cin + ic0 + icl];
            unsigned short hb = (unsigned short)(pk & 0xFFFFu);
            unsigned short lb = (unsigned short)(pk >> 16);
            Wh[(tap * 128 + oc) * 18 + icl] = *(__nv_bfloat16*)&hb;
            Wl[(tap * 128 + oc) * 18 + icl] = *(__nv_bfloat16*)&lb;
        }
        __syncthreads();
        #pragma unroll
        for (int tap = 0; tap < 9; tap++) {
            int ky = tap / 3, kx = tap - ky * 3;
            int pA0 = ((wm * 2 + ky) * 10 + gq + kx) * 18 + tg * 2;
            int pA1 = pA0 + 180;
            unsigned ah[4], al[4];
            ah[0] = *(const unsigned*)&Hh[pA0];
            ah[1] = *(const unsigned*)&Hh[pA1];
            ah[2] = *(const unsigned*)&Hh[pA0 + 8];
            ah[3] = *(const unsigned*)&Hh[pA1 + 8];
            al[0] = *(const unsigned*)&Hl[pA0];
            al[1] = *(const unsigned*)&Hl[pA1];
            al[2] = *(const unsigned*)&Hl[pA0 + 8];
            al[3] = *(const unsigned*)&Hl[pA1 + 8];
            #pragma unroll
            for (int nt = 0; nt < 8; nt++) {
                int brow = (tap * 128 + wn * 64 + nt * 8 + gq) * 18 + tg * 2;
                unsigned b0 = *(const unsigned*)&Wh[brow];
                unsigned b1 = *(const unsigned*)&Wh[brow + 8];
                unsigned l0 = *(const unsigned*)&Wl[brow];
                unsigned l1 = *(const unsigned*)&Wl[brow + 8];
                mma16816(acc[nt], ah, b0, b1);
                mma16816(acc[nt], ah, l0, l1);
                mma16816(acc[nt], al, b0, b1);
            }
        }
        __syncthreads();
    }
    int yA = y0 + wm * 2, xA = x0 + gq;
    #pragma unroll
    for (int nt = 0; nt < 8; nt++) {
        int oc = oc0 + wn * 64 + nt * 8 + tg * 2;
        float b0 = bias[oc], b1 = bias[oc + 1];
        size_t a00 = (((size_t)b * Cout + oc) * 64 + yA) * 64 + xA;
        size_t a10 = a00 + 64;
        size_t a01 = a00 + 4096, a11 = a01 + 64;
        float v00 = acc[nt][0] + b0, v01 = acc[nt][1] + b1;
        float v10 = acc[nt][2] + b0, v11 = acc[nt][3] + b1;
        if (flags & 1) {
            v00 = fmaxf(v00, 0.f); v01 = fmaxf(v01, 0.f);
            v10 = fmaxf(v10, 0.f); v11 = fmaxf(v11, 0.f);
        }
        if (flags & 2) {
            v00 += res[a00]; v01 += res[a01];
            v10 += res[a10]; v11 += res[a11];
        }
        out[a00] = v00; out[a01] = v01;
        out[a10] = v10; out[a11] = v11;
    }
}

__global__ void k_conv3(const float* __restrict__ in, const float* __restrict__ wgt,
                        const float* __restrict__ bias, float* __restrict__ out,
                        int Cin, int Cout, int flags, const float* __restrict__ res) {
    extern __shared__ float smf[];
    float* ws  = smf;
    float* ins = smf + 18432;
    int b = blockIdx.z, t = blockIdx.y, oc0 = blockIdx.x << 7;
    int y0 = (t >> 3) << 3, x0 = (t & 7) << 3, tid = threadIdx.x;
    int tx = tid & 15, ty = tid >> 4;
    int pyb = tx >> 1, pxb = (tx & 1) << 2;
    ull acc[4][4];
    #pragma unroll
    for (int p = 0; p < 4; p++)
        #pragma unroll
        for (int j = 0; j < 4; j++) acc[p][j] = 0ull;
    for (int ic0 = 0; ic0 < Cin; ic0 += 16) {
        for (int i = tid; i < 1600; i += 256) {
            int icl = i / 100, rem = i - icl * 100, hy = rem / 10, hx = rem - hy * 10;
            int gy = y0 + hy - 1, gx = x0 + hx - 1, ic = ic0 + icl;
            float v = 0.f;
            if (ic < Cin && (unsigned)gy < 64u && (unsigned)gx < 64u)
                v = in[(((size_t)b * Cin + ic) * 64 + gy) * 64 + gx];
            ins[i] = v;
        }
        for (int i = tid; i < 18432; i += 256) {
            int oc = i & 127, kk = i >> 7, icl = kk / 9, tap = kk - icl * 9, ic = ic0 + icl;
            ws[i] = (ic < Cin) ? wgt[(((size_t)(oc0 + oc)) * Cin + ic) * 9 + tap] : 0.f;
        }
        __syncthreads();
        int icm = (Cin - ic0 < 16) ? (Cin - ic0) : 16;
        for (int icl = 0; icl < icm; icl++) {
            ull xb[3][6];
            const float* iw = &ins[icl * 100 + pyb * 10 + pxb];
            #pragma unroll
            for (int ky = 0; ky < 3; ky++)
                #pragma unroll
                for (int c = 0; c < 6; c++) {
                    float v = iw[ky * 10 + c];
                    xb[ky][c] = pk2(v, v);
                }
            #pragma unroll
            for (int ky = 0; ky < 3; ky++)
                #pragma unroll
                for (int kx = 0; kx < 3; kx++) {
                    const float* wpv = &ws[(icl * 9 + ky * 3 + kx) * 128 + (ty << 3)];
                    ull w0 = *(const ull*)wpv, w1 = *(const ull*)(wpv + 2);
                    ull w2 = *(const ull*)(wpv + 4), w3 = *(const ull*)(wpv + 6);
                    #pragma unroll
                    for (int p = 0; p < 4; p++) {
                        ull xq = xb[ky][kx + p];
                        fma2(acc[p][0], xq, w0); fma2(acc[p][1], xq, w1);
                        fma2(acc[p][2], xq, w2); fma2(acc[p][3], xq, w3);
                    }
                }
        }
        __syncthreads();
    }
    #pragma unroll
    for (int j = 0; j < 4; j++) {
        int ocA = oc0 + (ty << 3) + 2 * j;
        float bA = bias[ocA], bB = bias[ocA + 1];
        size_t rowA = (((size_t)b * Cout + ocA) * 64 + y0 + pyb) * 64 + x0 + pxb;
        size_t rowB = rowA + 4096;
        #pragma unroll
        for (int p = 0; p < 4; p++) {
            float2 vpair = up2(acc[p][j]);
            float va = vpair.x + bA, vb = vpair.y + bB;
            if (flags & 1) { va = fmaxf(va, 0.f); vb = fmaxf(vb, 0.f); }
            if (flags & 2) { va += res[rowA + p]; vb += res[rowB + p]; }
            out[rowA + p] = va;
            out[rowB + p] = vb;
        }
    }
}

__global__ void k_instnorm(const float* __restrict__ x, float* __restrict__ st) {
    int row = blockIdx.x, tid = threadIdx.x;
    const float* p = x + (size_t)row * NPIX_;
    float s = 0.f, ss = 0.f;
    for (int i = tid; i < NPIX_; i += 256) { float v = p[i]; s += v; ss += v * v; }
    __shared__ float r1[256], r2[256];
    r1[tid] = s; r2[tid] = ss;
    __syncthreads();
    for (int k = 128; k > 0; k >>= 1) {
        if (tid < k) { r1[tid] += r1[tid+k]; r2[tid] += r2[tid+k]; }
        __syncthreads();
    }
    if (tid == 0) {
        float m = r1[0] * (1.f / NPIX_);
        float v = r2[0] * (1.f / NPIX_) - m * m;
        st[row*2] = m; st[row*2+1] = rsqrtf(v + 1e-5f);
    }
}

__global__ void k_spade_pono(const float* __restrict__ q, const float* __restrict__ gam,
                             const float* __restrict__ bet, const float* __restrict__ outat,
                             const float* __restrict__ conf, const float* __restrict__ innm,
                             float* __restrict__ y) {
    int b = blockIdx.x >> 6, n0 = (blockIdx.x & 63) << 6, tid = threadIdx.x;
    int nn = tid & 63, cp = tid >> 6;
    __shared__ float ps[4][64], pss[4][64], pm[64], pr[64];
    float cf = conf[(size_t)b * NPIX_ + n0 + nn];
    float s = 0.f, ss = 0.f;
    for (int base = 0; base < CV_; base += 4) {
        int cc = base + cp;
        size_t o = ((size_t)b * CV_ + cc) * NPIX_ + n0 + nn;
        float m = innm[(b*CV_+cc)*2], rs = innm[(b*CV_+cc)*2+1];
        float qv = q[o];
        float sp = (qv - m) * rs * (1.f + gam[o]) + bet[o];
        float tv = outat[o] + (1.f - cf) * sp + qv;
        s += tv; ss += tv * tv;
    }
    ps[cp][nn] = s; pss[cp][nn] = ss;
    __syncthreads();
    if (tid < 64) {
        float S = ps[0][tid]+ps[1][tid]+ps[2][tid]+ps[3][tid];
        float SS = pss[0][tid]+pss[1][tid]+pss[2][tid]+pss[3][tid];
        float m = S * (1.f/256.f), v = SS * (1.f/256.f) - m * m;
        pm[tid] = m; pr[tid] = rsqrtf(v + 1e-5f);
    }
    __syncthreads();
    float mmu = pm[nn], rr = pr[nn];
    for (int base = 0; base < CV_; base += 4) {
        int cc = base + cp;
        size_t o = ((size_t)b * CV_ + cc) * NPIX_ + n0 + nn;
        float m = innm[(b*CV_+cc)*2], rs = innm[(b*CV_+cc)*2+1];
        float qv = q[o];
        float sp = (qv - m) * rs * (1.f + gam[o]) + bet[o];
        float tv = outat[o] + (1.f - cf) * sp + qv;
        y[o] = (tv - mmu) * rr;
    }
}

extern "C" void kernel_launch(void* const* d_in, const int* in_sizes, int n_in,
                              void* d_out, int out_size) {
    const float *q = (const float*)d_in[0], *k = (const float*)d_in[1],
                *v = (const float*)d_in[2], *pos = (const float*)d_in[3],
                *seg = (const float*)d_in[4], *v2 = (const float*)d_in[5],
                *f_w = (const float*)d_in[6], *f_b = (const float*)d_in[7],
                *g_w = (const float*)d_in[8], *g_b = (const float*)d_in[9],
                *h_w = (const float*)d_in[10], *h_b = (const float*)d_in[11],
                *fp_w = (const float*)d_in[12], *fp_b = (const float*)d_in[13],
                *gp_w = (const float*)d_in[14], *gp_b = (const float*)d_in[15],
                *sp_s_w = (const float*)d_in[16], *sp_s_b = (const float*)d_in[17],
                *sp_g_w = (const float*)d_in[18], *sp_g_b = (const float*)d_in[19],
                *sp_b_w = (const float*)d_in[20], *sp_b_b = (const float*)d_in[21],
                *r1_w = (const float*)d_in[22], *r1_b = (const float*)d_in[23],
                *r2_w = (const float*)d_in[24], *r2_b = (const float*)d_in[25];
    float* S;
    cudaGetSymbolAddress((void**)&S, g_scratch);
    float* out_res  = (float*)d_out;
    float* out_out2 = out_res + 2097152;
    float* out_cor  = out_res + 4194304;
    unsigned char* mask = (unsigned char*)(S + OFF_MASK);
    __nv_bfloat16* QNH = (__nv_bfloat16*)(S + OFF_QN);
    __nv_bfloat16* QNL = (__nv_bfloat16*)(S + OFF_QN + 1310720u);
    __nv_bfloat16* KNH = (__nv_bfloat16*)(S + OFF_KN);
    __nv_bfloat16* KNL = (__nv_bfloat16*)(S + OFF_KN + 1310720u);
    __nv_bfloat16* VHI  = (__nv_bfloat16*)(S + OFF_VHI);
    __nv_bfloat16* VLO  = (__nv_bfloat16*)(S + OFF_VLO);
    __nv_bfloat16* V2HI = (__nv_bfloat16*)(S + OFF_V2HI);
    __nv_bfloat16* V2LO = (__nv_bfloat16*)(S + OFF_V2LO);
    __nv_bfloat16* QFH  = (__nv_bfloat16*)(S + OFF_QFH);
    __nv_bfloat16* QFL  = (__nv_bfloat16*)(S + OFF_QFL);
    __nv_bfloat16* KFH  = (__nv_bfloat16*)(S + OFF_KFH);
    __nv_bfloat16* KFL  = (__nv_bfloat16*)(S + OFF_KFL);
    unsigned* WR1 = (unsigned*)(S + OFF_WR1);
    unsigned* WR2 = (unsigned*)(S + OFF_WR2);
    unsigned* WG  = (unsigned*)(S + OFF_WG);
    unsigned* WB  = (unsigned*)(S + OFF_WB);
    unsigned* WF1 = (unsigned*)(S + OFF_WF1);
    unsigned* WG1 = (unsigned*)(S + OFF_WG1);
    cudaFuncSetAttribute(k_conv3, cudaFuncAttributeMaxDynamicSharedMemorySize, 80128);
    cudaFuncSetAttribute(k_av_mma, cudaFuncAttributeMaxDynamicSharedMemorySize, 73728);
    cudaFuncSetAttribute(k_cor_mma, cudaFuncAttributeMaxDynamicSharedMemorySize, 73728);
    cudaFuncSetAttribute(k_conv_mma, cudaFuncAttributeMaxDynamicSharedMemorySize, 90144);
    cudaFuncSetAttribute(k_gemm_mma, cudaFuncAttributeMaxDynamicSharedMemorySize, 55296);

    k_wprep<<<2304, 256>>>(r1_w, WR1, 256, 256);
    k_wprep<<<2304, 256>>>(r2_w, WR2, 256, 256);
    k_wprep<<<1152, 256>>>(sp_g_w, WG, 256, 128);
    k_wprep<<<1152, 256>>>(sp_b_w, WB, 256, 128);
    k_wprep1<<<400, 256>>>(f_w, WF1, CQK_ * CQK_);
    k_wprep1<<<400, 256>>>(g_w, WG1, CQK_ * CQK_);
    k_normcat<<<128, 256>>>(q, pos, S + OFF_QUERY, QNH, QNL);
    k_normcat<<<128, 256>>>(k, pos, S + OFF_KEYT, KNH, KNL);
    k_gemm_mma<<<dim3(64,5), 256, 55296>>>(QNH, QNL, WF1, f_b, QFH, QFL, CQK_, CQK_);
    k_gemm_mma<<<dim3(64,5), 256, 55296>>>(KNH, KNL, WG1, g_b, KFH, KFL, CQK_, CQK_);
    k_gemm<<<dim3(1,128), 256>>>(S + OFF_QUERY, fp_w, fp_b, S + OFF_QP, CQK_, DP_);
    k_gemm<<<dim3(1,128), 256>>>(S + OFF_KEYT,  gp_w, gp_b, S + OFF_KP, CQK_, DP_);
    k_gemmW<<<dim3(4,64,2), 256>>>(v, h_w, h_b, S + OFF_VH);
    k_split<<<8192, 256>>>(S + OFF_VH, VHI, VLO);
    k_split<<<8192, 256>>>(v2, V2HI, V2LO);
    k_cor_mma<<<dim3(32,32,2), 256, 73728>>>(QFH, QFL, KFH, KFL, out_cor);
    k_mask<<<dim3(32,32,2), 256>>>(S + OFF_QP, S + OFF_KP, mask);
    k_rowstats<<<8192, 256>>>(out_cor, mask, S + OFF_STATS, S + OFF_CONF);
    k_av_mma<<<dim3(32,2,2), 256, 73728>>>(out_cor, mask, S + OFF_STATS, VHI, VLO, S + OFF_OUT, 0);
    k_av_mma<<<dim3(32,2,2), 256, 73728>>>(out_cor, mask, S + OFF_STATS, V2HI, V2LO, out_out2, 1);
    k_conv3<<<dim3(1,64,2), 256, 80128>>>(seg, sp_s_w, sp_s_b, S + OFF_ACTV, 3, 128, 1, nullptr);
    k_conv_mma<<<dim3(2,64,2), 256, 90144>>>(S + OFF_ACTV, WG, sp_g_b, S + OFF_GAMMA, 128, 256, 0, nullptr);
    k_conv_mma<<<dim3(2,64,2), 256, 90144>>>(S + OFF_ACTV, WB, sp_b_b, S + OFF_BETA,  128, 256, 0, nullptr);
    k_instnorm<<<512, 256>>>(q, S + OFF_INNM);
    k_spade_pono<<<128, 256>>>(q, S + OFF_GAMMA, S + OFF_BETA, S + OFF_OUT,
                               S + OFF_CONF, S + OFF_INNM, S + OFF_Y);
    k_conv_mma<<<dim3(2,64,2), 256, 90144>>>(S + OFF_Y,  WR1, r1_b, S + OFF_T1, 256, 256, 1, nullptr);
    k_conv_mma<<<dim3(2,64,2), 256, 90144>>>(S + OFF_T1, WR2, r2_b, out_res,    256, 256, 2, S + OFF_Y);
}